// round 9
// baseline (speedup 1.0000x reference)
#include <cuda_runtime.h>
#include <cuda_fp16.h>
#include <cstdint>

#define EMBED 1024
#define HEADS 16
#define HDIM  64
#define BATCH 2
#define SEQ   2048
#define ROWSM (BATCH*SEQ)   // 4096
#define EE    (EMBED*EMBED)
#define RME   (ROWSM*EMBED)

// ---------------- scratch (__device__ globals; no allocation allowed) ----------------
__device__ float  g_Mcat[2*EE];    // [Wk^T Wk, Wq^T Wq]
__device__ float  g_q   [RME];     // q projected (fp32)
__device__ float  g_at  [RME];     // attention output
__device__ __half g_Wo2h[2*EE], g_Wo2l[2*EE];  // [Wqo, Wko] planes
__device__ __half g_Wvh [EE],   g_Wvl [EE];    // Wv planes
__device__ __half g_Woh [EE],   g_Wol [EE];    // Wo planes
__device__ __half g_kh  [RME],  g_kl  [RME];   // k planes  [b*S+s][E]
__device__ __half g_vh  [RME];                 // v hi plane [b*S+s][E]

// ---------------- helpers ----------------
__device__ __forceinline__ void split_f16(float f, __half& hi, __half& lo) {
    hi = __float2half_rn(f);
    lo = __float2half_rn(f - __half2float(hi));
}
__device__ __forceinline__ void split2(float a, float b, uint32_t& hi, uint32_t& lo) {
    __half2 h = __floats2half2_rn(a, b);
    float2 hf = __half22float2(h);
    __half2 l = __floats2half2_rn(a - hf.x, b - hf.y);
    hi = *reinterpret_cast<uint32_t*>(&h);
    lo = *reinterpret_cast<uint32_t*>(&l);
}
__device__ __forceinline__ uint32_t pack_h2(float a, float b) {
    __half2 h = __floats2half2_rn(a, b);
    return *reinterpret_cast<uint32_t*>(&h);
}
__device__ __forceinline__ void mma_f16(float (&d)[4], const uint32_t (&a)[4],
                                        const uint32_t (&b)[2], const float (&c)[4]) {
    asm volatile(
        "mma.sync.aligned.m16n8k16.row.col.f32.f16.f16.f32 "
        "{%0,%1,%2,%3},{%4,%5,%6,%7},{%8,%9},{%10,%11,%12,%13};\n"
        : "=f"(d[0]), "=f"(d[1]), "=f"(d[2]), "=f"(d[3])
        : "r"(a[0]), "r"(a[1]), "r"(a[2]), "r"(a[3]),
          "r"(b[0]), "r"(b[1]),
          "f"(c[0]), "f"(c[1]), "f"(c[2]), "f"(c[3]));
}
__device__ __forceinline__ uint32_t sptr(const void* p) {
    return (uint32_t)__cvta_generic_to_shared(p);
}
__device__ __forceinline__ void ldmx4(uint32_t* r, const __half* p) {
    asm volatile("ldmatrix.sync.aligned.m8n8.x4.shared.b16 {%0,%1,%2,%3}, [%4];"
        : "=r"(r[0]), "=r"(r[1]), "=r"(r[2]), "=r"(r[3]) : "r"(sptr(p)));
}
__device__ __forceinline__ void ldmx4t(uint32_t* r, const __half* p) {
    asm volatile("ldmatrix.sync.aligned.m8n8.x4.trans.shared.b16 {%0,%1,%2,%3}, [%4];"
        : "=r"(r[0]), "=r"(r[1]), "=r"(r[2]), "=r"(r[3]) : "r"(sptr(p)));
}
__device__ __forceinline__ void cp16(void* s, const void* g) {
    asm volatile("cp.async.cg.shared.global [%0], [%1], 16;" :: "r"(sptr(s)), "l"(g));
}
__device__ __forceinline__ void cp_commit() { asm volatile("cp.async.commit_group;"); }
template<int N> __device__ __forceinline__ void cp_wait() {
    asm volatile("cp.async.wait_group %0;" :: "n"(N));
}

// ---------------- weight pre-split kernel ----------------
__global__ void __launch_bounds__(256) split_planes(const float* __restrict__ w,
                                                    __half* __restrict__ hi,
                                                    __half* __restrict__ lo) {
    int i = blockIdx.x * 256 + threadIdx.x;
    __half h, l; split_f16(w[i], h, l);
    hi[i] = h; lo[i] = l;
}

// ---------------- generic batched split-fp16 GEMM, convert-overlapped pipeline ----------------
// z selects pointer set. C = alpha*opA(A)*opB(B) [+ beta*Cin]
// BPRE: B pre-split fp16 planes [n][k], cp'd direct (1-ahead, double-buffered).
//       Else B fp32 staged (2-ahead) + converted (1-ahead into double-buffered planes).
// A always fp32 staged (2-ahead) + converted (1-ahead).
// Per tile: cp_wait + ONE barrier; convert(j+1) overlaps MMA(j) across warps.
// EPI: 0 = fp32 C; 1 = planes Hh/Hl (+z*sH); 2 = qkv (z0: fp32 C0; z1: planes; z2: hi->Ht)
template<int BM,int BN,int BK,int WM,int WN,bool TA,bool TB,bool HASC,bool SPLITA,bool BPRE,int EPI>
__global__ void __launch_bounds__((BM/WM)*(BN/WN)*32)
gemm_f16s(const float* A0, const float* A1, const float* A2,
          const void* Bv0, const void* Bv1, const void* Bv2,
          const __half* Bl0, const __half* Bl1, const __half* Bl2,
          const float* Ci0, const float* Ci1, const float* Ci2,
          float* C0, float* C1, float* C2,
          __half* Hh, __half* Hl, __half* Ht, long long sH,
          int M, int N, int K, int lda, int ldb, int ldc,
          float alpha, float beta)
{
    constexpr int WARPS_N = BN / WN;
    constexpr int WARPS_M = BM / WM;
    constexpr int NTH = WARPS_M * WARPS_N * 32;
    constexpr int MFRAG = WM / 16, NFRAG = WN / 8, KSTEPS = BK / 16;
    constexpr int LDK = BK + 8;
    constexpr int CA = BM * BK / 4 / NTH;      // fp32 16B chunks (A stage)
    constexpr int CB = BN * BK / 4 / NTH;      // fp32 16B chunks (B stage, !BPRE)
    constexpr int CBH = (BN * (BK / 8)) / NTH; // half 16B chunks per plane (BPRE)
    constexpr int APL = SPLITA ? 2 : 1;
    constexpr int ASZ = APL * BM * LDK;        // halves per A plane-buffer
    constexpr int BSZ = 2 * BN * LDK;          // halves per B plane-buffer

    extern __shared__ char smraw[];
    float*  Ast = (float*)smraw;                         // [2][BM*BK]
    float*  Bst = nullptr;
    __half* As;
    __half* Bs;
    if constexpr (BPRE) {
        As = (__half*)(Ast + 2 * BM * BK);
        Bs = As + 2 * ASZ;                               // [2][2][BN*LDK]
    } else {
        Bst = Ast + 2 * BM * BK;                         // [2][BN*BK]
        As = (__half*)(Bst + 2 * BN * BK);
        Bs = As + 2 * ASZ;
    }

    const int z = blockIdx.z;
    const float* A = (z == 0) ? A0 : ((z == 1) ? A1 : A2);
    const void*  Bv = (z == 0) ? Bv0 : ((z == 1) ? Bv1 : Bv2);
    const __half* Bl = (z == 0) ? Bl0 : ((z == 1) ? Bl1 : Bl2);
    const float* Cin = (z == 0) ? Ci0 : ((z == 1) ? Ci1 : Ci2);
    float*       C = (z == 0) ? C0 : ((z == 1) ? C1 : C2);

    const int mbase = blockIdx.y * BM;
    const int nbase = blockIdx.x * BN;
    const int tid  = threadIdx.x;
    const int warp = tid >> 5, lane = tid & 31;
    const int wm = warp / WARPS_N, wn = warp % WARPS_N;
    const int gq = lane >> 2, tq = lane & 3;

    float acc[MFRAG][NFRAG][4];
#pragma unroll
    for (int i = 0; i < MFRAG; i++)
#pragma unroll
        for (int j = 0; j < NFRAG; j++)
#pragma unroll
            for (int r = 0; r < 4; r++) acc[i][j][r] = 0.f;

    const int NTILE = K / BK;

    auto cpA = [&](int t) {
        float* dst = Ast + (t & 1) * BM * BK;
        const int kb = t * BK;
#pragma unroll
        for (int i = 0; i < CA; i++) {
            int e = i * NTH + tid;
            if (TA) { int k = e / (BM/4), mc = e % (BM/4);
                cp16(dst + k * BM + 4 * mc, A + (size_t)(kb + k) * lda + mbase + 4 * mc); }
            else    { int m = e / (BK/4), kc = e % (BK/4);
                cp16(dst + m * BK + 4 * kc, A + (size_t)(mbase + m) * lda + kb + 4 * kc); }
        }
    };
    auto cpBst = [&](int t) {   // !BPRE: fp32 stage
        float* dst = Bst + (t & 1) * BN * BK;
        const float* Bf = (const float*)Bv;
        const int kb = t * BK;
#pragma unroll
        for (int i = 0; i < CB; i++) {
            int e = i * NTH + tid;
            if (TB) { int n = e / (BK/4), kc = e % (BK/4);
                cp16(dst + n * BK + 4 * kc, Bf + (size_t)(nbase + n) * ldb + kb + 4 * kc); }
            else    { int k = e / (BN/4), nc = e % (BN/4);
                cp16(dst + k * BN + 4 * nc, Bf + (size_t)(kb + k) * ldb + nbase + 4 * nc); }
        }
    };
    auto cpBdir = [&](int t) {  // BPRE: direct into plane buffer (t&1)
        __half* dh = Bs + (t & 1) * BSZ;
        __half* dl = dh + BN * LDK;
        const __half* Bh = (const __half*)Bv;
        const int kb = t * BK;
#pragma unroll
        for (int i = 0; i < CBH; i++) {
            int e = i * NTH + tid;
            int n = e / (BK/8), k8 = e % (BK/8);
            cp16(dh + n * LDK + k8 * 8, Bh + (size_t)(nbase + n) * ldb + kb + k8 * 8);
            cp16(dl + n * LDK + k8 * 8, Bl + (size_t)(nbase + n) * ldb + kb + k8 * 8);
        }
    };
    // convert tile t from stage (t&1) into plane buffer (t&1).
    // Chunk mapping matches cp exactly -> same-thread data (per-thread cp_wait suffices).
    auto convert = [&](int t) {
        const int buf = t & 1;
        const float4* src = (const float4*)(Ast + buf * BM * BK);
        __half* ah = As + buf * ASZ;
        __half* al = ah + BM * LDK;
#pragma unroll
        for (int i = 0; i < CA; i++) {
            int e = i * NTH + tid;
            float4 v = src[e];
            if (TA) {
                int k = e / (BM/4), mc = e % (BM/4);
                __half h, l;
                split_f16(v.x, h, l); ah[(4*mc+0)*LDK + k] = h; if (SPLITA) al[(4*mc+0)*LDK + k] = l;
                split_f16(v.y, h, l); ah[(4*mc+1)*LDK + k] = h; if (SPLITA) al[(4*mc+1)*LDK + k] = l;
                split_f16(v.z, h, l); ah[(4*mc+2)*LDK + k] = h; if (SPLITA) al[(4*mc+2)*LDK + k] = l;
                split_f16(v.w, h, l); ah[(4*mc+3)*LDK + k] = h; if (SPLITA) al[(4*mc+3)*LDK + k] = l;
            } else {
                int m = e / (BK/4), kc = e % (BK/4);
                uint32_t h01, l01, h23, l23;
                split2(v.x, v.y, h01, l01);
                split2(v.z, v.w, h23, l23);
                *(uint32_t*)&ah[m*LDK + 4*kc]     = h01;
                *(uint32_t*)&ah[m*LDK + 4*kc + 2] = h23;
                if (SPLITA) {
                    *(uint32_t*)&al[m*LDK + 4*kc]     = l01;
                    *(uint32_t*)&al[m*LDK + 4*kc + 2] = l23;
                }
            }
        }
        if constexpr (!BPRE) {
            const float4* bsrc = (const float4*)(Bst + buf * BN * BK);
            __half* bh = Bs + buf * BSZ;
            __half* blp = bh + BN * LDK;
#pragma unroll
            for (int i = 0; i < CB; i++) {
                int e = i * NTH + tid;
                float4 v = bsrc[e];
                if (TB) {
                    int n = e / (BK/4), kc = e % (BK/4);
                    uint32_t h01, l01, h23, l23;
                    split2(v.x, v.y, h01, l01);
                    split2(v.z, v.w, h23, l23);
                    *(uint32_t*)&bh[n*LDK + 4*kc]      = h01;
                    *(uint32_t*)&bh[n*LDK + 4*kc + 2]  = h23;
                    *(uint32_t*)&blp[n*LDK + 4*kc]     = l01;
                    *(uint32_t*)&blp[n*LDK + 4*kc + 2] = l23;
                } else {
                    int k = e / (BN/4), nc = e % (BN/4);
                    __half h, l;
                    split_f16(v.x, h, l); bh[(4*nc+0)*LDK + k] = h; blp[(4*nc+0)*LDK + k] = l;
                    split_f16(v.y, h, l); bh[(4*nc+1)*LDK + k] = h; blp[(4*nc+1)*LDK + k] = l;
                    split_f16(v.z, h, l); bh[(4*nc+2)*LDK + k] = h; blp[(4*nc+2)*LDK + k] = l;
                    split_f16(v.w, h, l); bh[(4*nc+3)*LDK + k] = h; blp[(4*nc+3)*LDK + k] = l;
                }
            }
        }
    };

    // ---- prologue: gP0 = {stage0 [, B0]} ; gP1 = {stage1 [, B1 if !BPRE]} ----
    cpA(0); if (BPRE) cpBdir(0); else cpBst(0);
    cp_commit();
    if (NTILE > 1) { cpA(1); if (!BPRE) cpBst(1); }
    cp_commit();
    cp_wait<1>();          // gP0 arrived (self-data for convert)
    convert(0);

    const int a_row = (lane & 15);
    const int a_kof = (lane >> 4) << 3;
    const int b_row = (lane & 7) + (((lane >> 4) & 1) << 3);
    const int b_kof = ((lane >> 3) & 1) << 3;

    for (int j = 0; j < NTILE; j++) {
        cp_wait<0>();
        __syncthreads();   // visibility: cp'd B/stage data + converted planes; buffer reuse fence

        // issue next group: stages 2-ahead, BPRE B 1-ahead (into buffer (j+1)&1)
        if (j + 2 < NTILE) { cpA(j + 2); if (!BPRE) cpBst(j + 2); }
        if (BPRE && j + 1 < NTILE) cpBdir(j + 1);
        cp_commit();

        if (j + 1 < NTILE) convert(j + 1);    // overlaps MMA(j) across warps

        const int jb = j & 1;
        const __half* Ash = As + jb * ASZ;
        const __half* Asl = Ash + BM * LDK;
        const __half* Bsh = Bs + jb * BSZ;
        const __half* Bsl = Bsh + BN * LDK;
#pragma unroll
        for (int ks = 0; ks < KSTEPS; ks++) {
            const int k0 = ks * 16;
            uint32_t ah[MFRAG][4], al[MFRAG][4];
            uint32_t bh[NFRAG][2], bl[NFRAG][2];
#pragma unroll
            for (int fm = 0; fm < MFRAG; fm++) {
                const int mr = wm * WM + fm * 16 + a_row;
                ldmx4(ah[fm], &Ash[mr * LDK + k0 + a_kof]);
                if (SPLITA)
                    ldmx4(al[fm], &Asl[mr * LDK + k0 + a_kof]);
            }
#pragma unroll
            for (int fp = 0; fp < NFRAG / 2; fp++) {
                const int nr = wn * WN + fp * 16 + b_row;
                uint32_t t[4];
                ldmx4(t, &Bsh[nr * LDK + k0 + b_kof]);
                bh[2*fp][0] = t[0]; bh[2*fp][1] = t[1];
                bh[2*fp+1][0] = t[2]; bh[2*fp+1][1] = t[3];
                ldmx4(t, &Bsl[nr * LDK + k0 + b_kof]);
                bl[2*fp][0] = t[0]; bl[2*fp][1] = t[1];
                bl[2*fp+1][0] = t[2]; bl[2*fp+1][1] = t[3];
            }
#pragma unroll
            for (int fm = 0; fm < MFRAG; fm++)
#pragma unroll
                for (int fn = 0; fn < NFRAG; fn++) {
                    if (SPLITA) mma_f16(acc[fm][fn], al[fm], bh[fn], acc[fm][fn]);
                    mma_f16(acc[fm][fn], ah[fm], bl[fn], acc[fm][fn]);
                    mma_f16(acc[fm][fn], ah[fm], bh[fn], acc[fm][fn]);
                }
        }
    }

    // ---- epilogue ----
#pragma unroll
    for (int fm = 0; fm < MFRAG; fm++) {
        const int m0 = mbase + wm * WM + fm * 16 + gq;
#pragma unroll
        for (int fn = 0; fn < NFRAG; fn++) {
            const int n0 = nbase + wn * WN + fn * 8 + tq * 2;
            float v0 = alpha * acc[fm][fn][0], v1 = alpha * acc[fm][fn][1];
            float v2 = alpha * acc[fm][fn][2], v3 = alpha * acc[fm][fn][3];
            if (HASC) {
                const float* ci0 = Cin + (size_t)m0 * ldc + n0;
                const float* ci1 = Cin + (size_t)(m0 + 8) * ldc + n0;
                v0 += beta * ci0[0]; v1 += beta * ci0[1];
                v2 += beta * ci1[0]; v3 += beta * ci1[1];
            }
            const bool planes = (EPI == 1) || (EPI == 2 && z == 1);
            if (planes) {
                __half* hh = Hh + (EPI == 1 ? z * sH : 0);
                __half* hl = Hl + (EPI == 1 ? z * sH : 0);
                uint32_t h01, l01, h23, l23;
                split2(v0, v1, h01, l01);
                split2(v2, v3, h23, l23);
                *(uint32_t*)&hh[(size_t)m0 * ldc + n0] = h01;
                *(uint32_t*)&hl[(size_t)m0 * ldc + n0] = l01;
                *(uint32_t*)&hh[(size_t)(m0 + 8) * ldc + n0] = h23;
                *(uint32_t*)&hl[(size_t)(m0 + 8) * ldc + n0] = l23;
            } else if (EPI == 2 && z == 2) {
                *(uint32_t*)&Ht[(size_t)m0 * ldc + n0] = pack_h2(v0, v1);
                *(uint32_t*)&Ht[(size_t)(m0 + 8) * ldc + n0] = pack_h2(v2, v3);
            } else {
                float* c0 = C + (size_t)m0 * ldc + n0;
                float* c1 = C + (size_t)(m0 + 8) * ldc + n0;
                c0[0] = v0; c0[1] = v1;
                c1[0] = v2; c1[1] = v3;
            }
        }
    }
}

// ---------------- fused flash attention: triple-buffered, trans-V (unchanged R8) ----------------
#define FA_LD  72
#define FA_PL  (128*FA_LD)
#define FA_NT  (SEQ/128)
#define FA_SMEM (9*FA_PL*2)

__global__ void __launch_bounds__(256)
flash_attn(const float* __restrict__ qf,
           const __half* __restrict__ khi, const __half* __restrict__ klo,
           const __half* __restrict__ vhi, float* __restrict__ outb)
{
    extern __shared__ __half sm[];

    const int hh = blockIdx.x;
    const int b = hh >> 4, h = hh & 15;
    const int qt = blockIdx.y;

    const int tid = threadIdx.x;
    const int w = tid >> 5, lane = tid & 31;
    const int gq = lane >> 2, tq = lane & 3;
    const int b_row = (lane & 7) + (((lane >> 4) & 1) << 3);
    const int b_kof = ((lane >> 3) & 1) << 3;
    const int vt_row = ((lane >> 3) & 1) * 8 + (lane & 7);
    const int vt_col = ((lane >> 4) & 1) * 8;

    const __half* Kh = khi + ((size_t)b * SEQ) * EMBED + h * HDIM;
    const __half* Kl = klo + ((size_t)b * SEQ) * EMBED + h * HDIM;
    const __half* Vh = vhi + ((size_t)b * SEQ) * EMBED + h * HDIM;

    auto cpKV = [&](int j) {
        __half* dst = sm + (j % 3) * 3 * FA_PL;
        const __half* sh = Kh + (size_t)(j * 128) * EMBED;
        const __half* sl = Kl + (size_t)(j * 128) * EMBED;
        const __half* sv = Vh + (size_t)(j * 128) * EMBED;
#pragma unroll
        for (int i = 0; i < 4; i++) {
            int c = i * 256 + tid;
            int row = c >> 3, c8 = c & 7;
            cp16(dst +            row * FA_LD + c8 * 8, sh + (size_t)row * EMBED + c8 * 8);
            cp16(dst +   FA_PL +  row * FA_LD + c8 * 8, sl + (size_t)row * EMBED + c8 * 8);
            cp16(dst + 2*FA_PL +  row * FA_LD + c8 * 8, sv + (size_t)row * EMBED + c8 * 8);
        }
        cp_commit();
    };

    uint32_t qh[4][4], ql[4][4];
    {
        const float* Qb = qf + ((size_t)b * SEQ) * EMBED + h * HDIM;
        const int r0 = qt * 128 + w * 16 + gq;
        const float* Qr0 = Qb + (size_t)r0 * EMBED;
        const float* Qr1 = Qr0 + 8 * (size_t)EMBED;
#pragma unroll
        for (int ks = 0; ks < 4; ks++) {
            const int c = 16 * ks + 2 * tq;
            float2 x0 = *(const float2*)(Qr0 + c);
            float2 x1 = *(const float2*)(Qr1 + c);
            float2 x2 = *(const float2*)(Qr0 + c + 8);
            float2 x3 = *(const float2*)(Qr1 + c + 8);
            split2(x0.x * 0.125f, x0.y * 0.125f, qh[ks][0], ql[ks][0]);
            split2(x1.x * 0.125f, x1.y * 0.125f, qh[ks][1], ql[ks][1]);
            split2(x2.x * 0.125f, x2.y * 0.125f, qh[ks][2], ql[ks][2]);
            split2(x3.x * 0.125f, x3.y * 0.125f, qh[ks][3], ql[ks][3]);
        }
    }

    float o[8][4];
#pragma unroll
    for (int i = 0; i < 8; i++)
#pragma unroll
        for (int r = 0; r < 4; r++) o[i][r] = 0.f;
    float m0r = -1e30f, m1r = -1e30f, l0 = 0.f, l1 = 0.f;

    cpKV(0);
    cpKV(1);

    for (int j = 0; j < FA_NT; j++) {
        if (j + 1 < FA_NT) cp_wait<1>(); else cp_wait<0>();
        __syncthreads();
        if (j + 2 < FA_NT) cpKV(j + 2);

        const __half* Kbh = sm + (j % 3) * 3 * FA_PL;
        const __half* Kbl = Kbh + FA_PL;
        const __half* Vb  = Kbh + 2 * FA_PL;

        float s[16][4];
#pragma unroll
        for (int f = 0; f < 16; f++)
#pragma unroll
            for (int r = 0; r < 4; r++) s[f][r] = 0.f;
#pragma unroll
        for (int ks = 0; ks < 4; ks++) {
            const int k0 = 16 * ks;
#pragma unroll
            for (int fp = 0; fp < 8; fp++) {
                const int nr = fp * 16 + b_row;
                uint32_t th[4], tl[4];
                ldmx4(th, &Kbh[nr * FA_LD + k0 + b_kof]);
                ldmx4(tl, &Kbl[nr * FA_LD + k0 + b_kof]);
                uint32_t bh0[2] = {th[0], th[1]}, bh1[2] = {th[2], th[3]};
                uint32_t bl0[2] = {tl[0], tl[1]}, bl1[2] = {tl[2], tl[3]};
                mma_f16(s[2*fp],   ql[ks], bh0, s[2*fp]);
                mma_f16(s[2*fp],   qh[ks], bl0, s[2*fp]);
                mma_f16(s[2*fp],   qh[ks], bh0, s[2*fp]);
                mma_f16(s[2*fp+1], ql[ks], bh1, s[2*fp+1]);
                mma_f16(s[2*fp+1], qh[ks], bl1, s[2*fp+1]);
                mma_f16(s[2*fp+1], qh[ks], bh1, s[2*fp+1]);
            }
        }

        float mx0 = -1e30f, mx1 = -1e30f;
#pragma unroll
        for (int f = 0; f < 16; f++) {
            mx0 = fmaxf(mx0, fmaxf(s[f][0], s[f][1]));
            mx1 = fmaxf(mx1, fmaxf(s[f][2], s[f][3]));
        }
        mx0 = fmaxf(mx0, __shfl_xor_sync(0xffffffffu, mx0, 1));
        mx0 = fmaxf(mx0, __shfl_xor_sync(0xffffffffu, mx0, 2));
        mx1 = fmaxf(mx1, __shfl_xor_sync(0xffffffffu, mx1, 1));
        mx1 = fmaxf(mx1, __shfl_xor_sync(0xffffffffu, mx1, 2));
        const float mn0 = fmaxf(m0r, mx0), mn1 = fmaxf(m1r, mx1);
        const float cr0 = __expf(m0r - mn0), cr1 = __expf(m1r - mn1);
        m0r = mn0; m1r = mn1;

        float rs0 = 0.f, rs1 = 0.f;
#pragma unroll
        for (int f = 0; f < 16; f++) {
            s[f][0] = __expf(s[f][0] - mn0);
            s[f][1] = __expf(s[f][1] - mn0);
            s[f][2] = __expf(s[f][2] - mn1);
            s[f][3] = __expf(s[f][3] - mn1);
            rs0 += s[f][0] + s[f][1];
            rs1 += s[f][2] + s[f][3];
        }
        rs0 += __shfl_xor_sync(0xffffffffu, rs0, 1);
        rs0 += __shfl_xor_sync(0xffffffffu, rs0, 2);
        rs1 += __shfl_xor_sync(0xffffffffu, rs1, 1);
        rs1 += __shfl_xor_sync(0xffffffffu, rs1, 2);
        l0 = l0 * cr0 + rs0;
        l1 = l1 * cr1 + rs1;
#pragma unroll
        for (int fn = 0; fn < 8; fn++) {
            o[fn][0] *= cr0; o[fn][1] *= cr0;
            o[fn][2] *= cr1; o[fn][3] *= cr1;
        }

#pragma unroll
        for (int ks = 0; ks < 8; ks++) {
            uint32_t pa[4];
            pa[0] = pack_h2(s[2*ks][0],   s[2*ks][1]);
            pa[1] = pack_h2(s[2*ks][2],   s[2*ks][3]);
            pa[2] = pack_h2(s[2*ks+1][0], s[2*ks+1][1]);
            pa[3] = pack_h2(s[2*ks+1][2], s[2*ks+1][3]);
            const int k0 = 16 * ks;
#pragma unroll
            for (int fp = 0; fp < 4; fp++) {
                uint32_t t[4];
                ldmx4t(t, &Vb[(k0 + vt_row) * FA_LD + fp * 16 + vt_col]);
                uint32_t b0[2] = {t[0], t[1]}, b1[2] = {t[2], t[3]};
                mma_f16(o[2*fp],   pa, b0, o[2*fp]);
                mma_f16(o[2*fp+1], pa, b1, o[2*fp+1]);
            }
        }
    }

    const float inv0 = 1.f / l0, inv1 = 1.f / l1;
    const int r0 = qt * 128 + w * 16 + gq;
    float* Ob0 = outb + ((size_t)(b * SEQ + r0)) * EMBED + h * HDIM;
    float* Ob1 = Ob0 + 8 * (size_t)EMBED;
#pragma unroll
    for (int fn = 0; fn < 8; fn++) {
        const int c = fn * 8 + 2 * tq;
        float2 t0; t0.x = o[fn][0] * inv0; t0.y = o[fn][1] * inv0;
        float2 t1; t1.x = o[fn][2] * inv1; t1.y = o[fn][3] * inv1;
        *(float2*)(Ob0 + c) = t0;
        *(float2*)(Ob1 + c) = t1;
    }
}

// ---------------- host launch ----------------
extern "C" void kernel_launch(void* const* d_in, const int* in_sizes, int n_in,
                              void* d_out, int out_size)
{
    (void)in_sizes; (void)n_in; (void)out_size;
    const float* query = (const float*)d_in[0];
    const float* key   = (const float*)d_in[1];
    const float* value = (const float*)d_in[2];
    const float* Wq    = (const float*)d_in[3];
    const float* Wk    = (const float*)d_in[4];
    const float* Wv    = (const float*)d_in[5];
    const float* Wo    = (const float*)d_in[6];
    float* out = (float*)d_out;

    float *Mcat, *q, *at;
    __half *Wo2h, *Wo2l, *Wvh, *Wvl, *Woh, *Wol, *kh, *kl, *vh;
    cudaGetSymbolAddress((void**)&Mcat, g_Mcat);
    cudaGetSymbolAddress((void**)&q,    g_q);
    cudaGetSymbolAddress((void**)&at,   g_at);
    cudaGetSymbolAddress((void**)&Wo2h, g_Wo2h);
    cudaGetSymbolAddress((void**)&Wo2l, g_Wo2l);
    cudaGetSymbolAddress((void**)&Wvh,  g_Wvh);
    cudaGetSymbolAddress((void**)&Wvl,  g_Wvl);
    cudaGetSymbolAddress((void**)&Woh,  g_Woh);
    cudaGetSymbolAddress((void**)&Wol,  g_Wol);
    cudaGetSymbolAddress((void**)&kh,   g_kh);
    cudaGetSymbolAddress((void**)&kl,   g_kl);
    cudaGetSymbolAddress((void**)&vh,   g_vh);

    split_planes<<<EE/256, 256>>>(Wv, Wvh, Wvl);
    split_planes<<<EE/256, 256>>>(Wo, Woh, Wol);

    // 1: Mcat[0]=Wk^T Wk ; Mcat[1]=Wq^T Wq   (BK=32, pipeline-converted)
    {
        auto kfn = gemm_f16s<128,128,32,64,32,true,false,false,true,false,0>;
        int sm = 2*(128*32*4) + 2*(128*32*4) + 2*(2*128*40*2) + 2*(2*128*40*2); // 147456
        cudaFuncSetAttribute(kfn, cudaFuncAttributeMaxDynamicSharedMemorySize, sm);
        dim3 grid(8, 8, 2);
        kfn<<<grid, 256, sm>>>(
            Wk, Wq, nullptr,  Wk, Wq, nullptr,  nullptr, nullptr, nullptr,
            nullptr, nullptr, nullptr,
            Mcat, Mcat + EE, nullptr,
            nullptr, nullptr, nullptr, 0,
            EMBED, EMBED, EMBED, EMBED, EMBED, EMBED, 1.f, 0.f);
    }
    // 2: Wo2[z] = W[z] - W[z]@Mcat[z]  -> fp16 planes
    {
        auto kfn = gemm_f16s<128,128,32,64,32,false,false,true,true,false,1>;
        int sm = 2*(128*32*4) + 2*(128*32*4) + 2*(2*128*40*2) + 2*(2*128*40*2);
        cudaFuncSetAttribute(kfn, cudaFuncAttributeMaxDynamicSharedMemorySize, sm);
        dim3 grid(8, 8, 2);
        kfn<<<grid, 256, sm>>>(
            Wq, Wk, nullptr,  Mcat, Mcat + EE, nullptr,  nullptr, nullptr, nullptr,
            Wq, Wk, nullptr,
            nullptr, nullptr, nullptr,
            Wo2h, Wo2l, nullptr, (long long)EE,
            EMBED, EMBED, EMBED, EMBED, EMBED, EMBED, -1.f, 1.f);
    }
    // 3: projections: z0 q fp32, z1 k planes, z2 v hi plane   (BK=64, B pre-split)
    {
        auto kfn = gemm_f16s<128,128,64,64,32,false,true,false,false,true,2>;
        int sm = 2*(128*64*4) + 2*(1*128*72*2) + 2*(2*128*72*2);   // 176128
        cudaFuncSetAttribute(kfn, cudaFuncAttributeMaxDynamicSharedMemorySize, sm);
        dim3 grid(8, 32, 3);
        kfn<<<grid, 256, sm>>>(
            query, key, value,
            Wo2h, Wo2h + EE, Wvh,  Wo2l, Wo2l + EE, Wvl,
            nullptr, nullptr, nullptr,
            q, nullptr, nullptr,
            kh, kl, vh, 0,
            ROWSM, EMBED, EMBED, EMBED, EMBED, EMBED, 1.f, 0.f);
    }
    // 4: flash attention
    {
        cudaFuncSetAttribute(flash_attn, cudaFuncAttributeMaxDynamicSharedMemorySize, FA_SMEM);
        dim3 grid(BATCH * HEADS, SEQ / 128);
        flash_attn<<<grid, 256, FA_SMEM>>>(q, kh, kl, vh, at);
    }
    // 5: out = at @ Wo^T  (A full split, B pre-split)
    {
        auto kfn = gemm_f16s<128,128,64,64,32,false,true,false,true,true,0>;
        int sm = 2*(128*64*4) + 2*(2*128*72*2) + 2*(2*128*72*2);   // 212992
        cudaFuncSetAttribute(kfn, cudaFuncAttributeMaxDynamicSharedMemorySize, sm);
        dim3 grid(8, 32, 1);
        kfn<<<grid, 256, sm>>>(
            at, nullptr, nullptr,
            Woh, nullptr, nullptr,  Wol, nullptr, nullptr,
            nullptr, nullptr, nullptr,
            out, nullptr, nullptr,
            nullptr, nullptr, nullptr, 0,
            ROWSM, EMBED, EMBED, EMBED, EMBED, EMBED, 1.f, 0.f);
    }
}

// round 10
// speedup vs baseline: 1.1493x; 1.1493x over previous
#include <cuda_runtime.h>
#include <cuda_fp16.h>
#include <cstdint>

#define EMBED 1024
#define HEADS 16
#define HDIM  64
#define BATCH 2
#define SEQ   2048
#define ROWSM (BATCH*SEQ)   // 4096
#define EE    (EMBED*EMBED)
#define RME   (ROWSM*EMBED)

// ---------------- scratch (__device__ globals; no allocation allowed) ----------------
__device__ float  g_Mcat[2*EE];    // [Wk^T Wk, Wq^T Wq]
__device__ float  g_q   [RME];     // q projected (fp32)
__device__ float  g_at  [RME];     // attention output
__device__ __half g_Wo2h[2*EE], g_Wo2l[2*EE];  // [Wqo, Wko] planes
__device__ __half g_Wvh [EE],   g_Wvl [EE];    // Wv planes
__device__ __half g_Woh [EE],   g_Wol [EE];    // Wo planes
__device__ __half g_kh  [RME],  g_kl  [RME];   // k planes  [b*S+s][E]
__device__ __half g_vh  [RME];                 // v hi plane [b*S+s][E]

// ---------------- helpers ----------------
__device__ __forceinline__ void split_f16(float f, __half& hi, __half& lo) {
    hi = __float2half_rn(f);
    lo = __float2half_rn(f - __half2float(hi));
}
__device__ __forceinline__ void split2(float a, float b, uint32_t& hi, uint32_t& lo) {
    __half2 h = __floats2half2_rn(a, b);
    float2 hf = __half22float2(h);
    __half2 l = __floats2half2_rn(a - hf.x, b - hf.y);
    hi = *reinterpret_cast<uint32_t*>(&h);
    lo = *reinterpret_cast<uint32_t*>(&l);
}
__device__ __forceinline__ uint32_t pack_h2(float a, float b) {
    __half2 h = __floats2half2_rn(a, b);
    return *reinterpret_cast<uint32_t*>(&h);
}
__device__ __forceinline__ void mma_f16(float (&d)[4], const uint32_t (&a)[4],
                                        const uint32_t (&b)[2], const float (&c)[4]) {
    asm volatile(
        "mma.sync.aligned.m16n8k16.row.col.f32.f16.f16.f32 "
        "{%0,%1,%2,%3},{%4,%5,%6,%7},{%8,%9},{%10,%11,%12,%13};\n"
        : "=f"(d[0]), "=f"(d[1]), "=f"(d[2]), "=f"(d[3])
        : "r"(a[0]), "r"(a[1]), "r"(a[2]), "r"(a[3]),
          "r"(b[0]), "r"(b[1]),
          "f"(c[0]), "f"(c[1]), "f"(c[2]), "f"(c[3]));
}
__device__ __forceinline__ uint32_t sptr(const void* p) {
    return (uint32_t)__cvta_generic_to_shared(p);
}
__device__ __forceinline__ void ldmx4(uint32_t* r, const __half* p) {
    asm volatile("ldmatrix.sync.aligned.m8n8.x4.shared.b16 {%0,%1,%2,%3}, [%4];"
        : "=r"(r[0]), "=r"(r[1]), "=r"(r[2]), "=r"(r[3]) : "r"(sptr(p)));
}
__device__ __forceinline__ void ldmx4t(uint32_t* r, const __half* p) {
    asm volatile("ldmatrix.sync.aligned.m8n8.x4.trans.shared.b16 {%0,%1,%2,%3}, [%4];"
        : "=r"(r[0]), "=r"(r[1]), "=r"(r[2]), "=r"(r[3]) : "r"(sptr(p)));
}
__device__ __forceinline__ void cp16(void* s, const void* g) {
    asm volatile("cp.async.cg.shared.global [%0], [%1], 16;" :: "r"(sptr(s)), "l"(g));
}
__device__ __forceinline__ void cp_commit() { asm volatile("cp.async.commit_group;"); }
template<int N> __device__ __forceinline__ void cp_wait() {
    asm volatile("cp.async.wait_group %0;" :: "n"(N));
}

// ---------------- weight pre-split kernel ----------------
__global__ void __launch_bounds__(256) split_planes(const float* __restrict__ w,
                                                    __half* __restrict__ hi,
                                                    __half* __restrict__ lo) {
    int i = blockIdx.x * 256 + threadIdx.x;
    __half h, l; split_f16(w[i], h, l);
    hi[i] = h; lo[i] = l;
}

// ---------------- generic batched split-fp16 GEMM (R8 pipeline, phase-ordered MMAs) ----------------
// z selects pointer set. C = alpha*opA(A)*opB(B) [+ beta*Cin]
// BPRE: B pre-split planes [n][k], cp'd direct, double-buffered. Else fp32 staged.
// EPI: 0 = fp32 C; 1 = planes Hh/Hl (+z*sH); 2 = qkv (z0: fp32 C0; z1: planes; z2: hi->Ht)
template<int BM,int BN,int BK,int WM,int WN,bool TA,bool TB,bool HASC,bool SPLITA,bool BPRE,int EPI>
__global__ void __launch_bounds__((BM/WM)*(BN/WN)*32)
gemm_f16s(const float* A0, const float* A1, const float* A2,
          const void* Bv0, const void* Bv1, const void* Bv2,
          const __half* Bl0, const __half* Bl1, const __half* Bl2,
          const float* Ci0, const float* Ci1, const float* Ci2,
          float* C0, float* C1, float* C2,
          __half* Hh, __half* Hl, __half* Ht, long long sH,
          int M, int N, int K, int lda, int ldb, int ldc,
          float alpha, float beta)
{
    constexpr int WARPS_N = BN / WN;
    constexpr int WARPS_M = BM / WM;
    constexpr int NTH = WARPS_M * WARPS_N * 32;
    constexpr int MFRAG = WM / 16, NFRAG = WN / 8, KSTEPS = BK / 16;
    constexpr int LDK = BK + 8;
    constexpr int EA = BM * BK / NTH, EB = BN * BK / NTH;
    constexpr int CA = BM * BK / 4 / NTH, CB = BN * BK / 4 / NTH;
    constexpr int CBH = (BN * (BK / 8)) / NTH;
    constexpr int APL = SPLITA ? 2 : 1;

    extern __shared__ char smraw[];
    float*  Ast = (float*)smraw;
    float*  Bst = nullptr;
    __half* As;
    __half* Bs;
    if constexpr (BPRE) {
        As = (__half*)(Ast + BM * BK);
        Bs = As + APL * BM * LDK;          // [2 buf][2 plane][BN*LDK]
    } else {
        Bst = Ast + BM * BK;
        As = (__half*)(Bst + BN * BK);
        Bs = As + APL * BM * LDK;          // [2 plane][BN*LDK]
    }

    const int z = blockIdx.z;
    const float* A = (z == 0) ? A0 : ((z == 1) ? A1 : A2);
    const void*  Bv = (z == 0) ? Bv0 : ((z == 1) ? Bv1 : Bv2);
    const __half* Bl = (z == 0) ? Bl0 : ((z == 1) ? Bl1 : Bl2);
    const float* Cin = (z == 0) ? Ci0 : ((z == 1) ? Ci1 : Ci2);
    float*       C = (z == 0) ? C0 : ((z == 1) ? C1 : C2);

    const int mbase = blockIdx.y * BM;
    const int nbase = blockIdx.x * BN;
    const int tid  = threadIdx.x;
    const int warp = tid >> 5, lane = tid & 31;
    const int wm = warp / WARPS_N, wn = warp % WARPS_N;
    const int gq = lane >> 2, tq = lane & 3;

    float acc[MFRAG][NFRAG][4];
#pragma unroll
    for (int i = 0; i < MFRAG; i++)
#pragma unroll
        for (int j = 0; j < NFRAG; j++)
#pragma unroll
            for (int r = 0; r < 4; r++) acc[i][j][r] = 0.f;

    auto cpA = [&](int kb) {
#pragma unroll
        for (int i = 0; i < CA; i++) {
            int e = i * NTH + tid;
            if (TA) { int k = e / (BM/4), mc = e % (BM/4);
                cp16(Ast + k * BM + 4 * mc, A + (size_t)(kb + k) * lda + mbase + 4 * mc); }
            else    { int m = e / (BK/4), kc = e % (BK/4);
                cp16(Ast + m * BK + 4 * kc, A + (size_t)(mbase + m) * lda + kb + 4 * kc); }
        }
    };
    auto cpB = [&](int kb, int buf) {
        if constexpr (BPRE) {
            const __half* Bh = (const __half*)Bv;
#pragma unroll
            for (int i = 0; i < CBH; i++) {
                int e = i * NTH + tid;
                int n = e / (BK/8), k8 = e % (BK/8);
                cp16(Bs + (buf*2 + 0) * BN * LDK + n * LDK + k8 * 8,
                     Bh + (size_t)(nbase + n) * ldb + kb + k8 * 8);
                cp16(Bs + (buf*2 + 1) * BN * LDK + n * LDK + k8 * 8,
                     Bl + (size_t)(nbase + n) * ldb + kb + k8 * 8);
            }
        } else {
            const float* Bf = (const float*)Bv;
#pragma unroll
            for (int i = 0; i < CB; i++) {
                int e = i * NTH + tid;
                if (TB) { int n = e / (BK/4), kc = e % (BK/4);
                    cp16(Bst + n * BK + 4 * kc, Bf + (size_t)(nbase + n) * ldb + kb + 4 * kc); }
                else    { int k = e / (BN/4), nc = e % (BN/4);
                    cp16(Bst + k * BN + 4 * nc, Bf + (size_t)(kb + k) * ldb + nbase + 4 * nc); }
            }
        }
    };
    auto convert = [&]() {
#pragma unroll
        for (int i = 0; i < EA; i++) {
            int e = i * NTH + tid; int m, k;
            if (TA) { k = e / BM; m = e % BM; } else { m = e / BK; k = e % BK; }
            float f = Ast[e];
            if (SPLITA) {
                __half h, l; split_f16(f, h, l);
                As[m * LDK + k] = h;
                As[BM * LDK + m * LDK + k] = l;
            } else {
                As[m * LDK + k] = __float2half_rn(f);
            }
        }
        if constexpr (!BPRE) {
#pragma unroll
            for (int i = 0; i < EB; i++) {
                int e = i * NTH + tid; int n, k;
                if (TB) { n = e / BK; k = e % BK; } else { k = e / BN; n = e % BN; }
                float f = Bst[e];
                __half h, l; split_f16(f, h, l);
                Bs[n * LDK + k] = h;
                Bs[BN * LDK + n * LDK + k] = l;
            }
        }
    };

    // ---- pipeline prologue ----
    cpA(0); cpB(0, 0); cp_commit();
    cp_wait<0>(); __syncthreads();
    convert(); __syncthreads();
    if (BK < K) { cpA(BK); cpB(BK, 1); cp_commit(); }

    const int a_row = (lane & 15);
    const int a_kof = (lane >> 4) << 3;
    const int b_row = (lane & 7) + (((lane >> 4) & 1) << 3);
    const int b_kof = ((lane >> 3) & 1) << 3;

    for (int kb = 0; kb < K; kb += BK) {
        const int ibuf = BPRE ? ((kb / BK) & 1) : 0;
        const __half* Bsh = Bs + (BPRE ? (ibuf*2 + 0) * BN * LDK : 0);
        const __half* Bsl = Bs + (BPRE ? (ibuf*2 + 1) * BN * LDK : BN * LDK);
#pragma unroll
        for (int ks = 0; ks < KSTEPS; ks++) {
            const int k0 = ks * 16;
            uint32_t ah[MFRAG][4], al[MFRAG][4];
            uint32_t bh[NFRAG][2], bl[NFRAG][2];
#pragma unroll
            for (int fm = 0; fm < MFRAG; fm++) {
                const int mr = wm * WM + fm * 16 + a_row;
                ldmx4(ah[fm], &As[mr * LDK + k0 + a_kof]);
                if (SPLITA)
                    ldmx4(al[fm], &As[BM * LDK + mr * LDK + k0 + a_kof]);
            }
#pragma unroll
            for (int fp = 0; fp < NFRAG / 2; fp++) {
                const int nr = wn * WN + fp * 16 + b_row;
                uint32_t t[4];
                ldmx4(t, &Bsh[nr * LDK + k0 + b_kof]);
                bh[2*fp][0] = t[0]; bh[2*fp][1] = t[1];
                bh[2*fp+1][0] = t[2]; bh[2*fp+1][1] = t[3];
                ldmx4(t, &Bsl[nr * LDK + k0 + b_kof]);
                bl[2*fp][0] = t[0]; bl[2*fp][1] = t[1];
                bl[2*fp+1][0] = t[2]; bl[2*fp+1][1] = t[3];
            }
            // phase-separated issue: each acc touched once per sweep of 16
            // independent MMAs -> dependency distance MFRAG*NFRAG.
            if (SPLITA) {
#pragma unroll
                for (int fm = 0; fm < MFRAG; fm++)
#pragma unroll
                    for (int fn = 0; fn < NFRAG; fn++)
                        mma_f16(acc[fm][fn], al[fm], bh[fn], acc[fm][fn]);
            }
#pragma unroll
            for (int fm = 0; fm < MFRAG; fm++)
#pragma unroll
                for (int fn = 0; fn < NFRAG; fn++)
                    mma_f16(acc[fm][fn], ah[fm], bl[fn], acc[fm][fn]);
#pragma unroll
            for (int fm = 0; fm < MFRAG; fm++)
#pragma unroll
                for (int fn = 0; fn < NFRAG; fn++)
                    mma_f16(acc[fm][fn], ah[fm], bh[fn], acc[fm][fn]);
        }
        if (kb + BK < K) {
            cp_wait<0>(); __syncthreads();
            convert(); __syncthreads();
            if (kb + 2 * BK < K) { cpA(kb + 2*BK); cpB(kb + 2*BK, ibuf); cp_commit(); }
        }
    }

    // ---- epilogue ----
#pragma unroll
    for (int fm = 0; fm < MFRAG; fm++) {
        const int m0 = mbase + wm * WM + fm * 16 + gq;
#pragma unroll
        for (int fn = 0; fn < NFRAG; fn++) {
            const int n0 = nbase + wn * WN + fn * 8 + tq * 2;
            float v0 = alpha * acc[fm][fn][0], v1 = alpha * acc[fm][fn][1];
            float v2 = alpha * acc[fm][fn][2], v3 = alpha * acc[fm][fn][3];
            if (HASC) {
                const float* ci0 = Cin + (size_t)m0 * ldc + n0;
                const float* ci1 = Cin + (size_t)(m0 + 8) * ldc + n0;
                v0 += beta * ci0[0]; v1 += beta * ci0[1];
                v2 += beta * ci1[0]; v3 += beta * ci1[1];
            }
            const bool planes = (EPI == 1) || (EPI == 2 && z == 1);
            if (planes) {
                __half* hh = Hh + (EPI == 1 ? z * sH : 0);
                __half* hl = Hl + (EPI == 1 ? z * sH : 0);
                uint32_t h01, l01, h23, l23;
                split2(v0, v1, h01, l01);
                split2(v2, v3, h23, l23);
                *(uint32_t*)&hh[(size_t)m0 * ldc + n0] = h01;
                *(uint32_t*)&hl[(size_t)m0 * ldc + n0] = l01;
                *(uint32_t*)&hh[(size_t)(m0 + 8) * ldc + n0] = h23;
                *(uint32_t*)&hl[(size_t)(m0 + 8) * ldc + n0] = l23;
            } else if (EPI == 2 && z == 2) {
                *(uint32_t*)&Ht[(size_t)m0 * ldc + n0] = pack_h2(v0, v1);
                *(uint32_t*)&Ht[(size_t)(m0 + 8) * ldc + n0] = pack_h2(v2, v3);
            } else {
                float* c0 = C + (size_t)m0 * ldc + n0;
                float* c1 = C + (size_t)(m0 + 8) * ldc + n0;
                c0[0] = v0; c0[1] = v1;
                c1[0] = v2; c1[1] = v3;
            }
        }
    }
}

// ---------------- fused flash attention: triple-buffered, trans-V, paired QK^T ----------------
#define FA_LD  72
#define FA_PL  (128*FA_LD)
#define FA_NT  (SEQ/128)
#define FA_SMEM (9*FA_PL*2)

__global__ void __launch_bounds__(256)
flash_attn(const float* __restrict__ qf,
           const __half* __restrict__ khi, const __half* __restrict__ klo,
           const __half* __restrict__ vhi, float* __restrict__ outb)
{
    extern __shared__ __half sm[];

    const int hh = blockIdx.x;
    const int b = hh >> 4, h = hh & 15;
    const int qt = blockIdx.y;

    const int tid = threadIdx.x;
    const int w = tid >> 5, lane = tid & 31;
    const int gq = lane >> 2, tq = lane & 3;
    const int b_row = (lane & 7) + (((lane >> 4) & 1) << 3);
    const int b_kof = ((lane >> 3) & 1) << 3;
    const int vt_row = ((lane >> 3) & 1) * 8 + (lane & 7);
    const int vt_col = ((lane >> 4) & 1) * 8;

    const __half* Kh = khi + ((size_t)b * SEQ) * EMBED + h * HDIM;
    const __half* Kl = klo + ((size_t)b * SEQ) * EMBED + h * HDIM;
    const __half* Vh = vhi + ((size_t)b * SEQ) * EMBED + h * HDIM;

    auto cpKV = [&](int j) {
        __half* dst = sm + (j % 3) * 3 * FA_PL;
        const __half* sh = Kh + (size_t)(j * 128) * EMBED;
        const __half* sl = Kl + (size_t)(j * 128) * EMBED;
        const __half* sv = Vh + (size_t)(j * 128) * EMBED;
#pragma unroll
        for (int i = 0; i < 4; i++) {
            int c = i * 256 + tid;
            int row = c >> 3, c8 = c & 7;
            cp16(dst +            row * FA_LD + c8 * 8, sh + (size_t)row * EMBED + c8 * 8);
            cp16(dst +   FA_PL +  row * FA_LD + c8 * 8, sl + (size_t)row * EMBED + c8 * 8);
            cp16(dst + 2*FA_PL +  row * FA_LD + c8 * 8, sv + (size_t)row * EMBED + c8 * 8);
        }
        cp_commit();
    };

    uint32_t qh[4][4], ql[4][4];
    {
        const float* Qb = qf + ((size_t)b * SEQ) * EMBED + h * HDIM;
        const int r0 = qt * 128 + w * 16 + gq;
        const float* Qr0 = Qb + (size_t)r0 * EMBED;
        const float* Qr1 = Qr0 + 8 * (size_t)EMBED;
#pragma unroll
        for (int ks = 0; ks < 4; ks++) {
            const int c = 16 * ks + 2 * tq;
            float2 x0 = *(const float2*)(Qr0 + c);
            float2 x1 = *(const float2*)(Qr1 + c);
            float2 x2 = *(const float2*)(Qr0 + c + 8);
            float2 x3 = *(const float2*)(Qr1 + c + 8);
            split2(x0.x * 0.125f, x0.y * 0.125f, qh[ks][0], ql[ks][0]);
            split2(x1.x * 0.125f, x1.y * 0.125f, qh[ks][1], ql[ks][1]);
            split2(x2.x * 0.125f, x2.y * 0.125f, qh[ks][2], ql[ks][2]);
            split2(x3.x * 0.125f, x3.y * 0.125f, qh[ks][3], ql[ks][3]);
        }
    }

    float o[8][4];
#pragma unroll
    for (int i = 0; i < 8; i++)
#pragma unroll
        for (int r = 0; r < 4; r++) o[i][r] = 0.f;
    float m0r = -1e30f, m1r = -1e30f, l0 = 0.f, l1 = 0.f;

    cpKV(0);
    cpKV(1);

    for (int j = 0; j < FA_NT; j++) {
        if (j + 1 < FA_NT) cp_wait<1>(); else cp_wait<0>();
        __syncthreads();
        if (j + 2 < FA_NT) cpKV(j + 2);

        const __half* Kbh = sm + (j % 3) * 3 * FA_PL;
        const __half* Kbl = Kbh + FA_PL;
        const __half* Vb  = Kbh + 2 * FA_PL;

        // ---- S = Q K^T: K-frag pairs, 3 phases of 4 independent MMAs ----
        float s[16][4];
#pragma unroll
        for (int f = 0; f < 16; f++)
#pragma unroll
            for (int r = 0; r < 4; r++) s[f][r] = 0.f;
#pragma unroll
        for (int ks = 0; ks < 4; ks++) {
            const int k0 = 16 * ks;
#pragma unroll
            for (int fp = 0; fp < 4; fp++) {
                const int nr0 = (2*fp)     * 16 + b_row;
                const int nr1 = (2*fp + 1) * 16 + b_row;
                uint32_t th0[4], tl0[4], th1[4], tl1[4];
                ldmx4(th0, &Kbh[nr0 * FA_LD + k0 + b_kof]);
                ldmx4(tl0, &Kbl[nr0 * FA_LD + k0 + b_kof]);
                ldmx4(th1, &Kbh[nr1 * FA_LD + k0 + b_kof]);
                ldmx4(tl1, &Kbl[nr1 * FA_LD + k0 + b_kof]);
                uint32_t bh00[2] = {th0[0], th0[1]}, bh01[2] = {th0[2], th0[3]};
                uint32_t bl00[2] = {tl0[0], tl0[1]}, bl01[2] = {tl0[2], tl0[3]};
                uint32_t bh10[2] = {th1[0], th1[1]}, bh11[2] = {th1[2], th1[3]};
                uint32_t bl10[2] = {tl1[0], tl1[1]}, bl11[2] = {tl1[2], tl1[3]};
                // phase 1: ql . K_hi (4 independent accs)
                mma_f16(s[4*fp],   ql[ks], bh00, s[4*fp]);
                mma_f16(s[4*fp+1], ql[ks], bh01, s[4*fp+1]);
                mma_f16(s[4*fp+2], ql[ks], bh10, s[4*fp+2]);
                mma_f16(s[4*fp+3], ql[ks], bh11, s[4*fp+3]);
                // phase 2: qh . K_lo
                mma_f16(s[4*fp],   qh[ks], bl00, s[4*fp]);
                mma_f16(s[4*fp+1], qh[ks], bl01, s[4*fp+1]);
                mma_f16(s[4*fp+2], qh[ks], bl10, s[4*fp+2]);
                mma_f16(s[4*fp+3], qh[ks], bl11, s[4*fp+3]);
                // phase 3: qh . K_hi
                mma_f16(s[4*fp],   qh[ks], bh00, s[4*fp]);
                mma_f16(s[4*fp+1], qh[ks], bh01, s[4*fp+1]);
                mma_f16(s[4*fp+2], qh[ks], bh10, s[4*fp+2]);
                mma_f16(s[4*fp+3], qh[ks], bh11, s[4*fp+3]);
            }
        }

        float mx0 = -1e30f, mx1 = -1e30f;
#pragma unroll
        for (int f = 0; f < 16; f++) {
            mx0 = fmaxf(mx0, fmaxf(s[f][0], s[f][1]));
            mx1 = fmaxf(mx1, fmaxf(s[f][2], s[f][3]));
        }
        mx0 = fmaxf(mx0, __shfl_xor_sync(0xffffffffu, mx0, 1));
        mx0 = fmaxf(mx0, __shfl_xor_sync(0xffffffffu, mx0, 2));
        mx1 = fmaxf(mx1, __shfl_xor_sync(0xffffffffu, mx1, 1));
        mx1 = fmaxf(mx1, __shfl_xor_sync(0xffffffffu, mx1, 2));
        const float mn0 = fmaxf(m0r, mx0), mn1 = fmaxf(m1r, mx1);
        const float cr0 = __expf(m0r - mn0), cr1 = __expf(m1r - mn1);
        m0r = mn0; m1r = mn1;

        float rs0 = 0.f, rs1 = 0.f;
#pragma unroll
        for (int f = 0; f < 16; f++) {
            s[f][0] = __expf(s[f][0] - mn0);
            s[f][1] = __expf(s[f][1] - mn0);
            s[f][2] = __expf(s[f][2] - mn1);
            s[f][3] = __expf(s[f][3] - mn1);
            rs0 += s[f][0] + s[f][1];
            rs1 += s[f][2] + s[f][3];
        }
        rs0 += __shfl_xor_sync(0xffffffffu, rs0, 1);
        rs0 += __shfl_xor_sync(0xffffffffu, rs0, 2);
        rs1 += __shfl_xor_sync(0xffffffffu, rs1, 1);
        rs1 += __shfl_xor_sync(0xffffffffu, rs1, 2);
        l0 = l0 * cr0 + rs0;
        l1 = l1 * cr1 + rs1;
#pragma unroll
        for (int fn = 0; fn < 8; fn++) {
            o[fn][0] *= cr0; o[fn][1] *= cr0;
            o[fn][2] *= cr1; o[fn][3] *= cr1;
        }

#pragma unroll
        for (int ks = 0; ks < 8; ks++) {
            uint32_t pa[4];
            pa[0] = pack_h2(s[2*ks][0],   s[2*ks][1]);
            pa[1] = pack_h2(s[2*ks][2],   s[2*ks][3]);
            pa[2] = pack_h2(s[2*ks+1][0], s[2*ks+1][1]);
            pa[3] = pack_h2(s[2*ks+1][2], s[2*ks+1][3]);
            const int k0 = 16 * ks;
#pragma unroll
            for (int fp = 0; fp < 4; fp++) {
                uint32_t t[4];
                ldmx4t(t, &Vb[(k0 + vt_row) * FA_LD + fp * 16 + vt_col]);
                uint32_t b0[2] = {t[0], t[1]}, b1[2] = {t[2], t[3]};
                mma_f16(o[2*fp],   pa, b0, o[2*fp]);
                mma_f16(o[2*fp+1], pa, b1, o[2*fp+1]);
            }
        }
    }

    const float inv0 = 1.f / l0, inv1 = 1.f / l1;
    const int r0 = qt * 128 + w * 16 + gq;
    float* Ob0 = outb + ((size_t)(b * SEQ + r0)) * EMBED + h * HDIM;
    float* Ob1 = Ob0 + 8 * (size_t)EMBED;
#pragma unroll
    for (int fn = 0; fn < 8; fn++) {
        const int c = fn * 8 + 2 * tq;
        float2 t0; t0.x = o[fn][0] * inv0; t0.y = o[fn][1] * inv0;
        float2 t1; t1.x = o[fn][2] * inv1; t1.y = o[fn][3] * inv1;
        *(float2*)(Ob0 + c) = t0;
        *(float2*)(Ob1 + c) = t1;
    }
}

// ---------------- host launch ----------------
extern "C" void kernel_launch(void* const* d_in, const int* in_sizes, int n_in,
                              void* d_out, int out_size)
{
    (void)in_sizes; (void)n_in; (void)out_size;
    const float* query = (const float*)d_in[0];
    const float* key   = (const float*)d_in[1];
    const float* value = (const float*)d_in[2];
    const float* Wq    = (const float*)d_in[3];
    const float* Wk    = (const float*)d_in[4];
    const float* Wv    = (const float*)d_in[5];
    const float* Wo    = (const float*)d_in[6];
    float* out = (float*)d_out;

    float *Mcat, *q, *at;
    __half *Wo2h, *Wo2l, *Wvh, *Wvl, *Woh, *Wol, *kh, *kl, *vh;
    cudaGetSymbolAddress((void**)&Mcat, g_Mcat);
    cudaGetSymbolAddress((void**)&q,    g_q);
    cudaGetSymbolAddress((void**)&at,   g_at);
    cudaGetSymbolAddress((void**)&Wo2h, g_Wo2h);
    cudaGetSymbolAddress((void**)&Wo2l, g_Wo2l);
    cudaGetSymbolAddress((void**)&Wvh,  g_Wvh);
    cudaGetSymbolAddress((void**)&Wvl,  g_Wvl);
    cudaGetSymbolAddress((void**)&Woh,  g_Woh);
    cudaGetSymbolAddress((void**)&Wol,  g_Wol);
    cudaGetSymbolAddress((void**)&kh,   g_kh);
    cudaGetSymbolAddress((void**)&kl,   g_kl);
    cudaGetSymbolAddress((void**)&vh,   g_vh);

    split_planes<<<EE/256, 256>>>(Wv, Wvh, Wvl);
    split_planes<<<EE/256, 256>>>(Wo, Woh, Wol);

    // 1: Mcat[0]=Wk^T Wk ; Mcat[1]=Wq^T Wq   (R8 config: BK=64)
    {
        auto kfn = gemm_f16s<128,128,64,64,32,true,false,false,true,false,0>;
        int sm = (128*64 + 128*64)*4 + (2*128 + 2*128)*72*2;   // 139264
        cudaFuncSetAttribute(kfn, cudaFuncAttributeMaxDynamicSharedMemorySize, sm);
        dim3 grid(8, 8, 2);
        kfn<<<grid, 256, sm>>>(
            Wk, Wq, nullptr,  Wk, Wq, nullptr,  nullptr, nullptr, nullptr,
            nullptr, nullptr, nullptr,
            Mcat, Mcat + EE, nullptr,
            nullptr, nullptr, nullptr, 0,
            EMBED, EMBED, EMBED, EMBED, EMBED, EMBED, 1.f, 0.f);
    }
    // 2: Wo2[z] = W[z] - W[z]@Mcat[z]  -> fp16 planes
    {
        auto kfn = gemm_f16s<128,128,64,64,32,false,false,true,true,false,1>;
        int sm = (128*64 + 128*64)*4 + (2*128 + 2*128)*72*2;
        cudaFuncSetAttribute(kfn, cudaFuncAttributeMaxDynamicSharedMemorySize, sm);
        dim3 grid(8, 8, 2);
        kfn<<<grid, 256, sm>>>(
            Wq, Wk, nullptr,  Mcat, Mcat + EE, nullptr,  nullptr, nullptr, nullptr,
            Wq, Wk, nullptr,
            nullptr, nullptr, nullptr,
            Wo2h, Wo2l, nullptr, (long long)EE,
            EMBED, EMBED, EMBED, EMBED, EMBED, EMBED, -1.f, 1.f);
    }
    // 3: projections: z0 q fp32, z1 k planes, z2 v hi plane
    {
        auto kfn = gemm_f16s<128,128,64,64,32,false,true,false,false,true,2>;
        int sm = 128*64*4 + 1*128*72*2 + 4*128*72*2;           // 124928
        cudaFuncSetAttribute(kfn, cudaFuncAttributeMaxDynamicSharedMemorySize, sm);
        dim3 grid(8, 32, 3);
        kfn<<<grid, 256, sm>>>(
            query, key, value,
            Wo2h, Wo2h + EE, Wvh,  Wo2l, Wo2l + EE, Wvl,
            nullptr, nullptr, nullptr,
            q, nullptr, nullptr,
            kh, kl, vh, 0,
            ROWSM, EMBED, EMBED, EMBED, EMBED, EMBED, 1.f, 0.f);
    }
    // 4: flash attention
    {
        cudaFuncSetAttribute(flash_attn, cudaFuncAttributeMaxDynamicSharedMemorySize, FA_SMEM);
        dim3 grid(BATCH * HEADS, SEQ / 128);
        flash_attn<<<grid, 256, FA_SMEM>>>(q, kh, kl, vh, at);
    }
    // 5: out = at @ Wo^T  (A full split, B pre-split)
    {
        auto kfn = gemm_f16s<128,128,64,64,32,false,true,false,true,true,0>;
        int sm = 128*64*4 + 2*128*72*2 + 4*128*72*2;           // 143360
        cudaFuncSetAttribute(kfn, cudaFuncAttributeMaxDynamicSharedMemorySize, sm);
        dim3 grid(8, 32, 1);
        kfn<<<grid, 256, sm>>>(
            at, nullptr, nullptr,
            Woh, nullptr, nullptr,  Wol, nullptr, nullptr,
            nullptr, nullptr, nullptr,
            out, nullptr, nullptr,
            nullptr, nullptr, nullptr, 0,
            ROWSM, EMBED, EMBED, EMBED, EMBED, EMBED, 1.f, 0.f);
    }
}

// round 11
// speedup vs baseline: 1.2756x; 1.1098x over previous
#include <cuda_runtime.h>
#include <cuda_fp16.h>
#include <cstdint>

#define EMBED 1024
#define HEADS 16
#define HDIM  64
#define BATCH 2
#define SEQ   2048
#define ROWSM (BATCH*SEQ)   // 4096
#define EE    (EMBED*EMBED)
#define RME   (ROWSM*EMBED)

// ---------------- scratch (__device__ globals; no allocation allowed) ----------------
__device__ float  g_Mcat[2*EE];    // [Wk^T Wk, Wq^T Wq]
__device__ float  g_q   [RME];     // q projected (fp32)
__device__ float  g_at  [RME];     // attention output
__device__ __half g_Wo2h[2*EE], g_Wo2l[2*EE];  // [Wqo, Wko] planes
__device__ __half g_Wvh [EE],   g_Wvl [EE];    // Wv planes
__device__ __half g_Woh [EE],   g_Wol [EE];    // Wo planes
__device__ __half g_kh  [RME],  g_kl  [RME];   // k planes  [b*S+s][E]
__device__ __half g_vh  [RME];                 // v hi plane [b*S+s][E]

// ---------------- helpers ----------------
__device__ __forceinline__ void split_f16(float f, __half& hi, __half& lo) {
    hi = __float2half_rn(f);
    lo = __float2half_rn(f - __half2float(hi));
}
__device__ __forceinline__ void split2(float a, float b, uint32_t& hi, uint32_t& lo) {
    __half2 h = __floats2half2_rn(a, b);
    float2 hf = __half22float2(h);
    __half2 l = __floats2half2_rn(a - hf.x, b - hf.y);
    hi = *reinterpret_cast<uint32_t*>(&h);
    lo = *reinterpret_cast<uint32_t*>(&l);
}
__device__ __forceinline__ uint32_t pack_h2(float a, float b) {
    __half2 h = __floats2half2_rn(a, b);
    return *reinterpret_cast<uint32_t*>(&h);
}
__device__ __forceinline__ void mma_f16(float (&d)[4], const uint32_t (&a)[4],
                                        const uint32_t (&b)[2], const float (&c)[4]) {
    asm volatile(
        "mma.sync.aligned.m16n8k16.row.col.f32.f16.f16.f32 "
        "{%0,%1,%2,%3},{%4,%5,%6,%7},{%8,%9},{%10,%11,%12,%13};\n"
        : "=f"(d[0]), "=f"(d[1]), "=f"(d[2]), "=f"(d[3])
        : "r"(a[0]), "r"(a[1]), "r"(a[2]), "r"(a[3]),
          "r"(b[0]), "r"(b[1]),
          "f"(c[0]), "f"(c[1]), "f"(c[2]), "f"(c[3]));
}
__device__ __forceinline__ uint32_t sptr(const void* p) {
    return (uint32_t)__cvta_generic_to_shared(p);
}
__device__ __forceinline__ void ldmx4(uint32_t* r, const __half* p) {
    asm volatile("ldmatrix.sync.aligned.m8n8.x4.shared.b16 {%0,%1,%2,%3}, [%4];"
        : "=r"(r[0]), "=r"(r[1]), "=r"(r[2]), "=r"(r[3]) : "r"(sptr(p)));
}
__device__ __forceinline__ void ldmx4t(uint32_t* r, const __half* p) {
    asm volatile("ldmatrix.sync.aligned.m8n8.x4.trans.shared.b16 {%0,%1,%2,%3}, [%4];"
        : "=r"(r[0]), "=r"(r[1]), "=r"(r[2]), "=r"(r[3]) : "r"(sptr(p)));
}
__device__ __forceinline__ void cp16(void* s, const void* g) {
    asm volatile("cp.async.cg.shared.global [%0], [%1], 16;" :: "r"(sptr(s)), "l"(g));
}
__device__ __forceinline__ void cp_commit() { asm volatile("cp.async.commit_group;"); }
template<int N> __device__ __forceinline__ void cp_wait() {
    asm volatile("cp.async.wait_group %0;" :: "n"(N));
}

// ---------------- weight pre-split kernel ----------------
__global__ void __launch_bounds__(256) split_planes(const float* __restrict__ w,
                                                    __half* __restrict__ hi,
                                                    __half* __restrict__ lo) {
    int i = blockIdx.x * 256 + threadIdx.x;
    __half h, l; split_f16(w[i], h, l);
    hi[i] = h; lo[i] = l;
}

// ---------------- generic batched split-fp16 GEMM (R8 pipeline, high-occupancy warping) ----------------
// z selects pointer set. C = alpha*opA(A)*opB(B) [+ beta*Cin]
// BPRE: B pre-split planes [n][k], cp'd direct, double-buffered. Else fp32 staged.
// EPI: 0 = fp32 C; 1 = planes Hh/Hl (+z*sH); 2 = qkv (z0: fp32 C0; z1: planes; z2: hi->Ht)
template<int BM,int BN,int BK,int WM,int WN,bool TA,bool TB,bool HASC,bool SPLITA,bool BPRE,int EPI>
__global__ void __launch_bounds__((BM/WM)*(BN/WN)*32)
gemm_f16s(const float* A0, const float* A1, const float* A2,
          const void* Bv0, const void* Bv1, const void* Bv2,
          const __half* Bl0, const __half* Bl1, const __half* Bl2,
          const float* Ci0, const float* Ci1, const float* Ci2,
          float* C0, float* C1, float* C2,
          __half* Hh, __half* Hl, __half* Ht, long long sH,
          int M, int N, int K, int lda, int ldb, int ldc,
          float alpha, float beta)
{
    constexpr int WARPS_N = BN / WN;
    constexpr int WARPS_M = BM / WM;
    constexpr int NTH = WARPS_M * WARPS_N * 32;
    constexpr int MFRAG = WM / 16, NFRAG = WN / 8, KSTEPS = BK / 16;
    constexpr int LDK = BK + 8;
    constexpr int EA = BM * BK / NTH, EB = BN * BK / NTH;
    constexpr int CA = BM * BK / 4 / NTH, CB = BN * BK / 4 / NTH;
    constexpr int CBH = (BN * (BK / 8)) / NTH;
    constexpr int APL = SPLITA ? 2 : 1;

    extern __shared__ char smraw[];
    float*  Ast = (float*)smraw;
    float*  Bst = nullptr;
    __half* As;
    __half* Bs;
    if constexpr (BPRE) {
        As = (__half*)(Ast + BM * BK);
        Bs = As + APL * BM * LDK;          // [2 buf][2 plane][BN*LDK]
    } else {
        Bst = Ast + BM * BK;
        As = (__half*)(Bst + BN * BK);
        Bs = As + APL * BM * LDK;          // [2 plane][BN*LDK]
    }

    const int z = blockIdx.z;
    const float* A = (z == 0) ? A0 : ((z == 1) ? A1 : A2);
    const void*  Bv = (z == 0) ? Bv0 : ((z == 1) ? Bv1 : Bv2);
    const __half* Bl = (z == 0) ? Bl0 : ((z == 1) ? Bl1 : Bl2);
    const float* Cin = (z == 0) ? Ci0 : ((z == 1) ? Ci1 : Ci2);
    float*       C = (z == 0) ? C0 : ((z == 1) ? C1 : C2);

    const int mbase = blockIdx.y * BM;
    const int nbase = blockIdx.x * BN;
    const int tid  = threadIdx.x;
    const int warp = tid >> 5, lane = tid & 31;
    const int wm = warp / WARPS_N, wn = warp % WARPS_N;
    const int gq = lane >> 2, tq = lane & 3;

    float acc[MFRAG][NFRAG][4];
#pragma unroll
    for (int i = 0; i < MFRAG; i++)
#pragma unroll
        for (int j = 0; j < NFRAG; j++)
#pragma unroll
            for (int r = 0; r < 4; r++) acc[i][j][r] = 0.f;

    auto cpA = [&](int kb) {
#pragma unroll
        for (int i = 0; i < CA; i++) {
            int e = i * NTH + tid;
            if (TA) { int k = e / (BM/4), mc = e % (BM/4);
                cp16(Ast + k * BM + 4 * mc, A + (size_t)(kb + k) * lda + mbase + 4 * mc); }
            else    { int m = e / (BK/4), kc = e % (BK/4);
                cp16(Ast + m * BK + 4 * kc, A + (size_t)(mbase + m) * lda + kb + 4 * kc); }
        }
    };
    auto cpB = [&](int kb, int buf) {
        if constexpr (BPRE) {
            const __half* Bh = (const __half*)Bv;
#pragma unroll
            for (int i = 0; i < CBH; i++) {
                int e = i * NTH + tid;
                int n = e / (BK/8), k8 = e % (BK/8);
                cp16(Bs + (buf*2 + 0) * BN * LDK + n * LDK + k8 * 8,
                     Bh + (size_t)(nbase + n) * ldb + kb + k8 * 8);
                cp16(Bs + (buf*2 + 1) * BN * LDK + n * LDK + k8 * 8,
                     Bl + (size_t)(nbase + n) * ldb + kb + k8 * 8);
            }
        } else {
            const float* Bf = (const float*)Bv;
#pragma unroll
            for (int i = 0; i < CB; i++) {
                int e = i * NTH + tid;
                if (TB) { int n = e / (BK/4), kc = e % (BK/4);
                    cp16(Bst + n * BK + 4 * kc, Bf + (size_t)(nbase + n) * ldb + kb + 4 * kc); }
                else    { int k = e / (BN/4), nc = e % (BN/4);
                    cp16(Bst + k * BN + 4 * nc, Bf + (size_t)(kb + k) * ldb + nbase + 4 * nc); }
            }
        }
    };
    auto convert = [&]() {
#pragma unroll
        for (int i = 0; i < EA; i++) {
            int e = i * NTH + tid; int m, k;
            if (TA) { k = e / BM; m = e % BM; } else { m = e / BK; k = e % BK; }
            float f = Ast[e];
            if (SPLITA) {
                __half h, l; split_f16(f, h, l);
                As[m * LDK + k] = h;
                As[BM * LDK + m * LDK + k] = l;
            } else {
                As[m * LDK + k] = __float2half_rn(f);
            }
        }
        if constexpr (!BPRE) {
#pragma unroll
            for (int i = 0; i < EB; i++) {
                int e = i * NTH + tid; int n, k;
                if (TB) { n = e / BK; k = e % BK; } else { k = e / BN; n = e % BN; }
                float f = Bst[e];
                __half h, l; split_f16(f, h, l);
                Bs[n * LDK + k] = h;
                Bs[BN * LDK + n * LDK + k] = l;
            }
        }
    };

    // ---- pipeline prologue ----
    cpA(0); cpB(0, 0); cp_commit();
    cp_wait<0>(); __syncthreads();
    convert(); __syncthreads();
    if (BK < K) { cpA(BK); cpB(BK, 1); cp_commit(); }

    const int a_row = (lane & 15);
    const int a_kof = (lane >> 4) << 3;
    const int b_row = (lane & 7) + (((lane >> 4) & 1) << 3);
    const int b_kof = ((lane >> 3) & 1) << 3;

    for (int kb = 0; kb < K; kb += BK) {
        const int ibuf = BPRE ? ((kb / BK) & 1) : 0;
        const __half* Bsh = Bs + (BPRE ? (ibuf*2 + 0) * BN * LDK : 0);
        const __half* Bsl = Bs + (BPRE ? (ibuf*2 + 1) * BN * LDK : BN * LDK);
#pragma unroll
        for (int ks = 0; ks < KSTEPS; ks++) {
            const int k0 = ks * 16;
            uint32_t ah[MFRAG][4], al[MFRAG][4];
            uint32_t bh[NFRAG][2], bl[NFRAG][2];
#pragma unroll
            for (int fm = 0; fm < MFRAG; fm++) {
                const int mr = wm * WM + fm * 16 + a_row;
                ldmx4(ah[fm], &As[mr * LDK + k0 + a_kof]);
                if (SPLITA)
                    ldmx4(al[fm], &As[BM * LDK + mr * LDK + k0 + a_kof]);
            }
#pragma unroll
            for (int fp = 0; fp < NFRAG / 2; fp++) {
                const int nr = wn * WN + fp * 16 + b_row;
                uint32_t t[4];
                ldmx4(t, &Bsh[nr * LDK + k0 + b_kof]);
                bh[2*fp][0] = t[0]; bh[2*fp][1] = t[1];
                bh[2*fp+1][0] = t[2]; bh[2*fp+1][1] = t[3];
                ldmx4(t, &Bsl[nr * LDK + k0 + b_kof]);
                bl[2*fp][0] = t[0]; bl[2*fp][1] = t[1];
                bl[2*fp+1][0] = t[2]; bl[2*fp+1][1] = t[3];
            }
            // phase-separated issue across independent accumulators
            if (SPLITA) {
#pragma unroll
                for (int fm = 0; fm < MFRAG; fm++)
#pragma unroll
                    for (int fn = 0; fn < NFRAG; fn++)
                        mma_f16(acc[fm][fn], al[fm], bh[fn], acc[fm][fn]);
            }
#pragma unroll
            for (int fm = 0; fm < MFRAG; fm++)
#pragma unroll
                for (int fn = 0; fn < NFRAG; fn++)
                    mma_f16(acc[fm][fn], ah[fm], bl[fn], acc[fm][fn]);
#pragma unroll
            for (int fm = 0; fm < MFRAG; fm++)
#pragma unroll
                for (int fn = 0; fn < NFRAG; fn++)
                    mma_f16(acc[fm][fn], ah[fm], bh[fn], acc[fm][fn]);
        }
        if (kb + BK < K) {
            cp_wait<0>(); __syncthreads();
            convert(); __syncthreads();
            if (kb + 2 * BK < K) { cpA(kb + 2*BK); cpB(kb + 2*BK, ibuf); cp_commit(); }
        }
    }

    // ---- epilogue ----
#pragma unroll
    for (int fm = 0; fm < MFRAG; fm++) {
        const int m0 = mbase + wm * WM + fm * 16 + gq;
#pragma unroll
        for (int fn = 0; fn < NFRAG; fn++) {
            const int n0 = nbase + wn * WN + fn * 8 + tq * 2;
            float v0 = alpha * acc[fm][fn][0], v1 = alpha * acc[fm][fn][1];
            float v2 = alpha * acc[fm][fn][2], v3 = alpha * acc[fm][fn][3];
            if (HASC) {
                const float* ci0 = Cin + (size_t)m0 * ldc + n0;
                const float* ci1 = Cin + (size_t)(m0 + 8) * ldc + n0;
                v0 += beta * ci0[0]; v1 += beta * ci0[1];
                v2 += beta * ci1[0]; v3 += beta * ci1[1];
            }
            const bool planes = (EPI == 1) || (EPI == 2 && z == 1);
            if (planes) {
                __half* hh = Hh + (EPI == 1 ? z * sH : 0);
                __half* hl = Hl + (EPI == 1 ? z * sH : 0);
                uint32_t h01, l01, h23, l23;
                split2(v0, v1, h01, l01);
                split2(v2, v3, h23, l23);
                *(uint32_t*)&hh[(size_t)m0 * ldc + n0] = h01;
                *(uint32_t*)&hl[(size_t)m0 * ldc + n0] = l01;
                *(uint32_t*)&hh[(size_t)(m0 + 8) * ldc + n0] = h23;
                *(uint32_t*)&hl[(size_t)(m0 + 8) * ldc + n0] = l23;
            } else if (EPI == 2 && z == 2) {
                *(uint32_t*)&Ht[(size_t)m0 * ldc + n0] = pack_h2(v0, v1);
                *(uint32_t*)&Ht[(size_t)(m0 + 8) * ldc + n0] = pack_h2(v2, v3);
            } else {
                float* c0 = C + (size_t)m0 * ldc + n0;
                float* c1 = C + (size_t)(m0 + 8) * ldc + n0;
                c0[0] = v0; c0[1] = v1;
                c1[0] = v2; c1[1] = v3;
            }
        }
    }
}

// ---------------- fused flash attention: triple-buffered, trans-V, paired QK^T ----------------
#define FA_LD  72
#define FA_PL  (128*FA_LD)
#define FA_NT  (SEQ/128)
#define FA_SMEM (9*FA_PL*2)

__global__ void __launch_bounds__(256)
flash_attn(const float* __restrict__ qf,
           const __half* __restrict__ khi, const __half* __restrict__ klo,
           const __half* __restrict__ vhi, float* __restrict__ outb)
{
    extern __shared__ __half sm[];

    const int hh = blockIdx.x;
    const int b = hh >> 4, h = hh & 15;
    const int qt = blockIdx.y;

    const int tid = threadIdx.x;
    const int w = tid >> 5, lane = tid & 31;
    const int gq = lane >> 2, tq = lane & 3;
    const int b_row = (lane & 7) + (((lane >> 4) & 1) << 3);
    const int b_kof = ((lane >> 3) & 1) << 3;
    const int vt_row = ((lane >> 3) & 1) * 8 + (lane & 7);
    const int vt_col = ((lane >> 4) & 1) * 8;

    const __half* Kh = khi + ((size_t)b * SEQ) * EMBED + h * HDIM;
    const __half* Kl = klo + ((size_t)b * SEQ) * EMBED + h * HDIM;
    const __half* Vh = vhi + ((size_t)b * SEQ) * EMBED + h * HDIM;

    auto cpKV = [&](int j) {
        __half* dst = sm + (j % 3) * 3 * FA_PL;
        const __half* sh = Kh + (size_t)(j * 128) * EMBED;
        const __half* sl = Kl + (size_t)(j * 128) * EMBED;
        const __half* sv = Vh + (size_t)(j * 128) * EMBED;
#pragma unroll
        for (int i = 0; i < 4; i++) {
            int c = i * 256 + tid;
            int row = c >> 3, c8 = c & 7;
            cp16(dst +            row * FA_LD + c8 * 8, sh + (size_t)row * EMBED + c8 * 8);
            cp16(dst +   FA_PL +  row * FA_LD + c8 * 8, sl + (size_t)row * EMBED + c8 * 8);
            cp16(dst + 2*FA_PL +  row * FA_LD + c8 * 8, sv + (size_t)row * EMBED + c8 * 8);
        }
        cp_commit();
    };

    uint32_t qh[4][4], ql[4][4];
    {
        const float* Qb = qf + ((size_t)b * SEQ) * EMBED + h * HDIM;
        const int r0 = qt * 128 + w * 16 + gq;
        const float* Qr0 = Qb + (size_t)r0 * EMBED;
        const float* Qr1 = Qr0 + 8 * (size_t)EMBED;
#pragma unroll
        for (int ks = 0; ks < 4; ks++) {
            const int c = 16 * ks + 2 * tq;
            float2 x0 = *(const float2*)(Qr0 + c);
            float2 x1 = *(const float2*)(Qr1 + c);
            float2 x2 = *(const float2*)(Qr0 + c + 8);
            float2 x3 = *(const float2*)(Qr1 + c + 8);
            split2(x0.x * 0.125f, x0.y * 0.125f, qh[ks][0], ql[ks][0]);
            split2(x1.x * 0.125f, x1.y * 0.125f, qh[ks][1], ql[ks][1]);
            split2(x2.x * 0.125f, x2.y * 0.125f, qh[ks][2], ql[ks][2]);
            split2(x3.x * 0.125f, x3.y * 0.125f, qh[ks][3], ql[ks][3]);
        }
    }

    float o[8][4];
#pragma unroll
    for (int i = 0; i < 8; i++)
#pragma unroll
        for (int r = 0; r < 4; r++) o[i][r] = 0.f;
    float m0r = -1e30f, m1r = -1e30f, l0 = 0.f, l1 = 0.f;

    cpKV(0);
    cpKV(1);

    for (int j = 0; j < FA_NT; j++) {
        if (j + 1 < FA_NT) cp_wait<1>(); else cp_wait<0>();
        __syncthreads();
        if (j + 2 < FA_NT) cpKV(j + 2);

        const __half* Kbh = sm + (j % 3) * 3 * FA_PL;
        const __half* Kbl = Kbh + FA_PL;
        const __half* Vb  = Kbh + 2 * FA_PL;

        float s[16][4];
#pragma unroll
        for (int f = 0; f < 16; f++)
#pragma unroll
            for (int r = 0; r < 4; r++) s[f][r] = 0.f;
#pragma unroll
        for (int ks = 0; ks < 4; ks++) {
            const int k0 = 16 * ks;
#pragma unroll
            for (int fp = 0; fp < 4; fp++) {
                const int nr0 = (2*fp)     * 16 + b_row;
                const int nr1 = (2*fp + 1) * 16 + b_row;
                uint32_t th0[4], tl0[4], th1[4], tl1[4];
                ldmx4(th0, &Kbh[nr0 * FA_LD + k0 + b_kof]);
                ldmx4(tl0, &Kbl[nr0 * FA_LD + k0 + b_kof]);
                ldmx4(th1, &Kbh[nr1 * FA_LD + k0 + b_kof]);
                ldmx4(tl1, &Kbl[nr1 * FA_LD + k0 + b_kof]);
                uint32_t bh00[2] = {th0[0], th0[1]}, bh01[2] = {th0[2], th0[3]};
                uint32_t bl00[2] = {tl0[0], tl0[1]}, bl01[2] = {tl0[2], tl0[3]};
                uint32_t bh10[2] = {th1[0], th1[1]}, bh11[2] = {th1[2], th1[3]};
                uint32_t bl10[2] = {tl1[0], tl1[1]}, bl11[2] = {tl1[2], tl1[3]};
                mma_f16(s[4*fp],   ql[ks], bh00, s[4*fp]);
                mma_f16(s[4*fp+1], ql[ks], bh01, s[4*fp+1]);
                mma_f16(s[4*fp+2], ql[ks], bh10, s[4*fp+2]);
                mma_f16(s[4*fp+3], ql[ks], bh11, s[4*fp+3]);
                mma_f16(s[4*fp],   qh[ks], bl00, s[4*fp]);
                mma_f16(s[4*fp+1], qh[ks], bl01, s[4*fp+1]);
                mma_f16(s[4*fp+2], qh[ks], bl10, s[4*fp+2]);
                mma_f16(s[4*fp+3], qh[ks], bl11, s[4*fp+3]);
                mma_f16(s[4*fp],   qh[ks], bh00, s[4*fp]);
                mma_f16(s[4*fp+1], qh[ks], bh01, s[4*fp+1]);
                mma_f16(s[4*fp+2], qh[ks], bh10, s[4*fp+2]);
                mma_f16(s[4*fp+3], qh[ks], bh11, s[4*fp+3]);
            }
        }

        float mx0 = -1e30f, mx1 = -1e30f;
#pragma unroll
        for (int f = 0; f < 16; f++) {
            mx0 = fmaxf(mx0, fmaxf(s[f][0], s[f][1]));
            mx1 = fmaxf(mx1, fmaxf(s[f][2], s[f][3]));
        }
        mx0 = fmaxf(mx0, __shfl_xor_sync(0xffffffffu, mx0, 1));
        mx0 = fmaxf(mx0, __shfl_xor_sync(0xffffffffu, mx0, 2));
        mx1 = fmaxf(mx1, __shfl_xor_sync(0xffffffffu, mx1, 1));
        mx1 = fmaxf(mx1, __shfl_xor_sync(0xffffffffu, mx1, 2));
        const float mn0 = fmaxf(m0r, mx0), mn1 = fmaxf(m1r, mx1);
        const float cr0 = __expf(m0r - mn0), cr1 = __expf(m1r - mn1);
        m0r = mn0; m1r = mn1;

        float rs0 = 0.f, rs1 = 0.f;
#pragma unroll
        for (int f = 0; f < 16; f++) {
            s[f][0] = __expf(s[f][0] - mn0);
            s[f][1] = __expf(s[f][1] - mn0);
            s[f][2] = __expf(s[f][2] - mn1);
            s[f][3] = __expf(s[f][3] - mn1);
            rs0 += s[f][0] + s[f][1];
            rs1 += s[f][2] + s[f][3];
        }
        rs0 += __shfl_xor_sync(0xffffffffu, rs0, 1);
        rs0 += __shfl_xor_sync(0xffffffffu, rs0, 2);
        rs1 += __shfl_xor_sync(0xffffffffu, rs1, 1);
        rs1 += __shfl_xor_sync(0xffffffffu, rs1, 2);
        l0 = l0 * cr0 + rs0;
        l1 = l1 * cr1 + rs1;
#pragma unroll
        for (int fn = 0; fn < 8; fn++) {
            o[fn][0] *= cr0; o[fn][1] *= cr0;
            o[fn][2] *= cr1; o[fn][3] *= cr1;
        }

#pragma unroll
        for (int ks = 0; ks < 8; ks++) {
            uint32_t pa[4];
            pa[0] = pack_h2(s[2*ks][0],   s[2*ks][1]);
            pa[1] = pack_h2(s[2*ks][2],   s[2*ks][3]);
            pa[2] = pack_h2(s[2*ks+1][0], s[2*ks+1][1]);
            pa[3] = pack_h2(s[2*ks+1][2], s[2*ks+1][3]);
            const int k0 = 16 * ks;
#pragma unroll
            for (int fp = 0; fp < 4; fp++) {
                uint32_t t[4];
                ldmx4t(t, &Vb[(k0 + vt_row) * FA_LD + fp * 16 + vt_col]);
                uint32_t b0[2] = {t[0], t[1]}, b1[2] = {t[2], t[3]};
                mma_f16(o[2*fp],   pa, b0, o[2*fp]);
                mma_f16(o[2*fp+1], pa, b1, o[2*fp+1]);
            }
        }
    }

    const float inv0 = 1.f / l0, inv1 = 1.f / l1;
    const int r0 = qt * 128 + w * 16 + gq;
    float* Ob0 = outb + ((size_t)(b * SEQ + r0)) * EMBED + h * HDIM;
    float* Ob1 = Ob0 + 8 * (size_t)EMBED;
#pragma unroll
    for (int fn = 0; fn < 8; fn++) {
        const int c = fn * 8 + 2 * tq;
        float2 t0; t0.x = o[fn][0] * inv0; t0.y = o[fn][1] * inv0;
        float2 t1; t1.x = o[fn][2] * inv1; t1.y = o[fn][3] * inv1;
        *(float2*)(Ob0 + c) = t0;
        *(float2*)(Ob1 + c) = t1;
    }
}

// ---------------- host launch ----------------
extern "C" void kernel_launch(void* const* d_in, const int* in_sizes, int n_in,
                              void* d_out, int out_size)
{
    (void)in_sizes; (void)n_in; (void)out_size;
    const float* query = (const float*)d_in[0];
    const float* key   = (const float*)d_in[1];
    const float* value = (const float*)d_in[2];
    const float* Wq    = (const float*)d_in[3];
    const float* Wk    = (const float*)d_in[4];
    const float* Wv    = (const float*)d_in[5];
    const float* Wo    = (const float*)d_in[6];
    float* out = (float*)d_out;

    float *Mcat, *q, *at;
    __half *Wo2h, *Wo2l, *Wvh, *Wvl, *Woh, *Wol, *kh, *kl, *vh;
    cudaGetSymbolAddress((void**)&Mcat, g_Mcat);
    cudaGetSymbolAddress((void**)&q,    g_q);
    cudaGetSymbolAddress((void**)&at,   g_at);
    cudaGetSymbolAddress((void**)&Wo2h, g_Wo2h);
    cudaGetSymbolAddress((void**)&Wo2l, g_Wo2l);
    cudaGetSymbolAddress((void**)&Wvh,  g_Wvh);
    cudaGetSymbolAddress((void**)&Wvl,  g_Wvl);
    cudaGetSymbolAddress((void**)&Woh,  g_Woh);
    cudaGetSymbolAddress((void**)&Wol,  g_Wol);
    cudaGetSymbolAddress((void**)&kh,   g_kh);
    cudaGetSymbolAddress((void**)&kl,   g_kl);
    cudaGetSymbolAddress((void**)&vh,   g_vh);

    split_planes<<<EE/256, 256>>>(Wv, Wvh, Wvl);
    split_planes<<<EE/256, 256>>>(Wo, Woh, Wol);

    // 1: Mcat[0]=Wk^T Wk ; Mcat[1]=Wq^T Wq   (512 threads, WM=WN=32)
    {
        auto kfn = gemm_f16s<128,128,64,32,32,true,false,false,true,false,0>;
        int sm = (128*64 + 128*64)*4 + (2*128 + 2*128)*72*2;   // 139264
        cudaFuncSetAttribute(kfn, cudaFuncAttributeMaxDynamicSharedMemorySize, sm);
        dim3 grid(8, 8, 2);
        kfn<<<grid, 512, sm>>>(
            Wk, Wq, nullptr,  Wk, Wq, nullptr,  nullptr, nullptr, nullptr,
            nullptr, nullptr, nullptr,
            Mcat, Mcat + EE, nullptr,
            nullptr, nullptr, nullptr, 0,
            EMBED, EMBED, EMBED, EMBED, EMBED, EMBED, 1.f, 0.f);
    }
    // 2: Wo2[z] = W[z] - W[z]@Mcat[z]  -> fp16 planes
    {
        auto kfn = gemm_f16s<128,128,64,32,32,false,false,true,true,false,1>;
        int sm = (128*64 + 128*64)*4 + (2*128 + 2*128)*72*2;
        cudaFuncSetAttribute(kfn, cudaFuncAttributeMaxDynamicSharedMemorySize, sm);
        dim3 grid(8, 8, 2);
        kfn<<<grid, 512, sm>>>(
            Wq, Wk, nullptr,  Mcat, Mcat + EE, nullptr,  nullptr, nullptr, nullptr,
            Wq, Wk, nullptr,
            nullptr, nullptr, nullptr,
            Wo2h, Wo2l, nullptr, (long long)EE,
            EMBED, EMBED, EMBED, EMBED, EMBED, EMBED, -1.f, 1.f);
    }
    // 3: projections: z0 q fp32, z1 k planes, z2 v hi plane
    {
        auto kfn = gemm_f16s<128,128,64,32,32,false,true,false,false,true,2>;
        int sm = 128*64*4 + 1*128*72*2 + 4*128*72*2;           // 124928
        cudaFuncSetAttribute(kfn, cudaFuncAttributeMaxDynamicSharedMemorySize, sm);
        dim3 grid(8, 32, 3);
        kfn<<<grid, 512, sm>>>(
            query, key, value,
            Wo2h, Wo2h + EE, Wvh,  Wo2l, Wo2l + EE, Wvl,
            nullptr, nullptr, nullptr,
            q, nullptr, nullptr,
            kh, kl, vh, 0,
            ROWSM, EMBED, EMBED, EMBED, EMBED, EMBED, 1.f, 0.f);
    }
    // 4: flash attention
    {
        cudaFuncSetAttribute(flash_attn, cudaFuncAttributeMaxDynamicSharedMemorySize, FA_SMEM);
        dim3 grid(BATCH * HEADS, SEQ / 128);
        flash_attn<<<grid, 256, FA_SMEM>>>(q, kh, kl, vh, at);
    }
    // 5: out = at @ Wo^T  (A hi-only now, B pre-split)
    {
        auto kfn = gemm_f16s<128,128,64,32,32,false,true,false,false,true,0>;
        int sm = 128*64*4 + 1*128*72*2 + 4*128*72*2;           // 124928
        cudaFuncSetAttribute(kfn, cudaFuncAttributeMaxDynamicSharedMemorySize, sm);
        dim3 grid(8, 32, 1);
        kfn<<<grid, 512, sm>>>(
            at, nullptr, nullptr,
            Woh, nullptr, nullptr,  Wol, nullptr, nullptr,
            nullptr, nullptr, nullptr,
            out, nullptr, nullptr,
            nullptr, nullptr, nullptr, 0,
            ROWSM, EMBED, EMBED, EMBED, EMBED, EMBED, 1.f, 0.f);
    }
}

// round 12
// speedup vs baseline: 1.3745x; 1.0775x over previous
#include <cuda_runtime.h>
#include <cuda_fp16.h>
#include <cstdint>

#define EMBED 1024
#define HEADS 16
#define HDIM  64
#define BATCH 2
#define SEQ   2048
#define ROWSM (BATCH*SEQ)   // 4096
#define EE    (EMBED*EMBED)
#define RME   (ROWSM*EMBED)

// ---------------- scratch (__device__ globals; no allocation allowed) ----------------
__device__ float  g_Mcat[2*EE];    // [Wk^T Wk, Wq^T Wq]
__device__ float  g_q   [RME];     // q projected (fp32)
__device__ float  g_at  [RME];     // attention output
__device__ __half g_Wo2h[2*EE], g_Wo2l[2*EE];  // [Wqo, Wko] planes
__device__ __half g_Wvh [EE],   g_Wvl [EE];    // Wv planes
__device__ __half g_Woh [EE],   g_Wol [EE];    // Wo planes
__device__ __half g_kh  [RME],  g_kl  [RME];   // k planes  [b*S+s][E]
__device__ __half g_vh  [RME];                 // v hi plane [b*S+s][E]

// ---------------- helpers ----------------
__device__ __forceinline__ void split_f16(float f, __half& hi, __half& lo) {
    hi = __float2half_rn(f);
    lo = __float2half_rn(f - __half2float(hi));
}
__device__ __forceinline__ void split2(float a, float b, uint32_t& hi, uint32_t& lo) {
    __half2 h = __floats2half2_rn(a, b);
    float2 hf = __half22float2(h);
    __half2 l = __floats2half2_rn(a - hf.x, b - hf.y);
    hi = *reinterpret_cast<uint32_t*>(&h);
    lo = *reinterpret_cast<uint32_t*>(&l);
}
__device__ __forceinline__ uint32_t pack_h2(float a, float b) {
    __half2 h = __floats2half2_rn(a, b);
    return *reinterpret_cast<uint32_t*>(&h);
}
__device__ __forceinline__ void mma_f16(float (&d)[4], const uint32_t (&a)[4],
                                        const uint32_t (&b)[2], const float (&c)[4]) {
    asm volatile(
        "mma.sync.aligned.m16n8k16.row.col.f32.f16.f16.f32 "
        "{%0,%1,%2,%3},{%4,%5,%6,%7},{%8,%9},{%10,%11,%12,%13};\n"
        : "=f"(d[0]), "=f"(d[1]), "=f"(d[2]), "=f"(d[3])
        : "r"(a[0]), "r"(a[1]), "r"(a[2]), "r"(a[3]),
          "r"(b[0]), "r"(b[1]),
          "f"(c[0]), "f"(c[1]), "f"(c[2]), "f"(c[3]));
}
__device__ __forceinline__ uint32_t sptr(const void* p) {
    return (uint32_t)__cvta_generic_to_shared(p);
}
__device__ __forceinline__ void ldmx4(uint32_t* r, const __half* p) {
    asm volatile("ldmatrix.sync.aligned.m8n8.x4.shared.b16 {%0,%1,%2,%3}, [%4];"
        : "=r"(r[0]), "=r"(r[1]), "=r"(r[2]), "=r"(r[3]) : "r"(sptr(p)));
}
__device__ __forceinline__ void ldmx4t(uint32_t* r, const __half* p) {
    asm volatile("ldmatrix.sync.aligned.m8n8.x4.trans.shared.b16 {%0,%1,%2,%3}, [%4];"
        : "=r"(r[0]), "=r"(r[1]), "=r"(r[2]), "=r"(r[3]) : "r"(sptr(p)));
}
__device__ __forceinline__ void cp16(void* s, const void* g) {
    asm volatile("cp.async.cg.shared.global [%0], [%1], 16;" :: "r"(sptr(s)), "l"(g));
}
__device__ __forceinline__ void cp_commit() { asm volatile("cp.async.commit_group;"); }
template<int N> __device__ __forceinline__ void cp_wait() {
    asm volatile("cp.async.wait_group %0;" :: "n"(N));
}

// ---------------- weight pre-split kernel ----------------
__global__ void __launch_bounds__(256) split_planes(const float* __restrict__ w,
                                                    __half* __restrict__ hi,
                                                    __half* __restrict__ lo) {
    int i = blockIdx.x * 256 + threadIdx.x;
    __half h, l; split_f16(w[i], h, l);
    hi[i] = h; lo[i] = l;
}

// ---------------- generic batched split-fp16 GEMM (R11 high-occupancy config) ----------------
// z selects pointer set. C = alpha*opA(A)*opB(B) [+ beta*Cin]
// BPRE: B pre-split planes [n][k], cp'd direct, double-buffered. Else fp32 staged.
// EPI: 0 = fp32 C; 1 = planes Hh/Hl (+z*sH); 2 = qkv (z0: fp32 C0; z1: planes; z2: hi->Ht)
template<int BM,int BN,int BK,int WM,int WN,bool TA,bool TB,bool HASC,bool SPLITA,bool BPRE,int EPI>
__global__ void __launch_bounds__((BM/WM)*(BN/WN)*32)
gemm_f16s(const float* A0, const float* A1, const float* A2,
          const void* Bv0, const void* Bv1, const void* Bv2,
          const __half* Bl0, const __half* Bl1, const __half* Bl2,
          const float* Ci0, const float* Ci1, const float* Ci2,
          float* C0, float* C1, float* C2,
          __half* Hh, __half* Hl, __half* Ht, long long sH,
          int M, int N, int K, int lda, int ldb, int ldc,
          float alpha, float beta)
{
    constexpr int WARPS_N = BN / WN;
    constexpr int WARPS_M = BM / WM;
    constexpr int NTH = WARPS_M * WARPS_N * 32;
    constexpr int MFRAG = WM / 16, NFRAG = WN / 8, KSTEPS = BK / 16;
    constexpr int LDK = BK + 8;
    constexpr int EA = BM * BK / NTH, EB = BN * BK / NTH;
    constexpr int CA = BM * BK / 4 / NTH, CB = BN * BK / 4 / NTH;
    constexpr int CBH = (BN * (BK / 8)) / NTH;
    constexpr int APL = SPLITA ? 2 : 1;

    extern __shared__ char smraw[];
    float*  Ast = (float*)smraw;
    float*  Bst = nullptr;
    __half* As;
    __half* Bs;
    if constexpr (BPRE) {
        As = (__half*)(Ast + BM * BK);
        Bs = As + APL * BM * LDK;          // [2 buf][2 plane][BN*LDK]
    } else {
        Bst = Ast + BM * BK;
        As = (__half*)(Bst + BN * BK);
        Bs = As + APL * BM * LDK;          // [2 plane][BN*LDK]
    }

    const int z = blockIdx.z;
    const float* A = (z == 0) ? A0 : ((z == 1) ? A1 : A2);
    const void*  Bv = (z == 0) ? Bv0 : ((z == 1) ? Bv1 : Bv2);
    const __half* Bl = (z == 0) ? Bl0 : ((z == 1) ? Bl1 : Bl2);
    const float* Cin = (z == 0) ? Ci0 : ((z == 1) ? Ci1 : Ci2);
    float*       C = (z == 0) ? C0 : ((z == 1) ? C1 : C2);

    const int mbase = blockIdx.y * BM;
    const int nbase = blockIdx.x * BN;
    const int tid  = threadIdx.x;
    const int warp = tid >> 5, lane = tid & 31;
    const int wm = warp / WARPS_N, wn = warp % WARPS_N;
    const int gq = lane >> 2, tq = lane & 3;

    float acc[MFRAG][NFRAG][4];
#pragma unroll
    for (int i = 0; i < MFRAG; i++)
#pragma unroll
        for (int j = 0; j < NFRAG; j++)
#pragma unroll
            for (int r = 0; r < 4; r++) acc[i][j][r] = 0.f;

    auto cpA = [&](int kb) {
#pragma unroll
        for (int i = 0; i < CA; i++) {
            int e = i * NTH + tid;
            if (TA) { int k = e / (BM/4), mc = e % (BM/4);
                cp16(Ast + k * BM + 4 * mc, A + (size_t)(kb + k) * lda + mbase + 4 * mc); }
            else    { int m = e / (BK/4), kc = e % (BK/4);
                cp16(Ast + m * BK + 4 * kc, A + (size_t)(mbase + m) * lda + kb + 4 * kc); }
        }
    };
    auto cpB = [&](int kb, int buf) {
        if constexpr (BPRE) {
            const __half* Bh = (const __half*)Bv;
#pragma unroll
            for (int i = 0; i < CBH; i++) {
                int e = i * NTH + tid;
                int n = e / (BK/8), k8 = e % (BK/8);
                cp16(Bs + (buf*2 + 0) * BN * LDK + n * LDK + k8 * 8,
                     Bh + (size_t)(nbase + n) * ldb + kb + k8 * 8);
                cp16(Bs + (buf*2 + 1) * BN * LDK + n * LDK + k8 * 8,
                     Bl + (size_t)(nbase + n) * ldb + kb + k8 * 8);
            }
        } else {
            const float* Bf = (const float*)Bv;
#pragma unroll
            for (int i = 0; i < CB; i++) {
                int e = i * NTH + tid;
                if (TB) { int n = e / (BK/4), kc = e % (BK/4);
                    cp16(Bst + n * BK + 4 * kc, Bf + (size_t)(nbase + n) * ldb + kb + 4 * kc); }
                else    { int k = e / (BN/4), nc = e % (BN/4);
                    cp16(Bst + k * BN + 4 * nc, Bf + (size_t)(kb + k) * ldb + nbase + 4 * nc); }
            }
        }
    };
    auto convert = [&]() {
#pragma unroll
        for (int i = 0; i < EA; i++) {
            int e = i * NTH + tid; int m, k;
            if (TA) { k = e / BM; m = e % BM; } else { m = e / BK; k = e % BK; }
            float f = Ast[e];
            if (SPLITA) {
                __half h, l; split_f16(f, h, l);
                As[m * LDK + k] = h;
                As[BM * LDK + m * LDK + k] = l;
            } else {
                As[m * LDK + k] = __float2half_rn(f);
            }
        }
        if constexpr (!BPRE) {
#pragma unroll
            for (int i = 0; i < EB; i++) {
                int e = i * NTH + tid; int n, k;
                if (TB) { n = e / BK; k = e % BK; } else { k = e / BN; n = e % BN; }
                float f = Bst[e];
                __half h, l; split_f16(f, h, l);
                Bs[n * LDK + k] = h;
                Bs[BN * LDK + n * LDK + k] = l;
            }
        }
    };

    // ---- pipeline prologue ----
    cpA(0); cpB(0, 0); cp_commit();
    cp_wait<0>(); __syncthreads();
    convert(); __syncthreads();
    if (BK < K) { cpA(BK); cpB(BK, 1); cp_commit(); }

    const int a_row = (lane & 15);
    const int a_kof = (lane >> 4) << 3;
    const int b_row = (lane & 7) + (((lane >> 4) & 1) << 3);
    const int b_kof = ((lane >> 3) & 1) << 3;

    for (int kb = 0; kb < K; kb += BK) {
        const int ibuf = BPRE ? ((kb / BK) & 1) : 0;
        const __half* Bsh = Bs + (BPRE ? (ibuf*2 + 0) * BN * LDK : 0);
        const __half* Bsl = Bs + (BPRE ? (ibuf*2 + 1) * BN * LDK : BN * LDK);
#pragma unroll
        for (int ks = 0; ks < KSTEPS; ks++) {
            const int k0 = ks * 16;
            uint32_t ah[MFRAG][4], al[MFRAG][4];
            uint32_t bh[NFRAG][2], bl[NFRAG][2];
#pragma unroll
            for (int fm = 0; fm < MFRAG; fm++) {
                const int mr = wm * WM + fm * 16 + a_row;
                ldmx4(ah[fm], &As[mr * LDK + k0 + a_kof]);
                if (SPLITA)
                    ldmx4(al[fm], &As[BM * LDK + mr * LDK + k0 + a_kof]);
            }
#pragma unroll
            for (int fp = 0; fp < NFRAG / 2; fp++) {
                const int nr = wn * WN + fp * 16 + b_row;
                uint32_t t[4];
                ldmx4(t, &Bsh[nr * LDK + k0 + b_kof]);
                bh[2*fp][0] = t[0]; bh[2*fp][1] = t[1];
                bh[2*fp+1][0] = t[2]; bh[2*fp+1][1] = t[3];
                ldmx4(t, &Bsl[nr * LDK + k0 + b_kof]);
                bl[2*fp][0] = t[0]; bl[2*fp][1] = t[1];
                bl[2*fp+1][0] = t[2]; bl[2*fp+1][1] = t[3];
            }
            // phase-separated issue across independent accumulators
            if (SPLITA) {
#pragma unroll
                for (int fm = 0; fm < MFRAG; fm++)
#pragma unroll
                    for (int fn = 0; fn < NFRAG; fn++)
                        mma_f16(acc[fm][fn], al[fm], bh[fn], acc[fm][fn]);
            }
#pragma unroll
            for (int fm = 0; fm < MFRAG; fm++)
#pragma unroll
                for (int fn = 0; fn < NFRAG; fn++)
                    mma_f16(acc[fm][fn], ah[fm], bl[fn], acc[fm][fn]);
#pragma unroll
            for (int fm = 0; fm < MFRAG; fm++)
#pragma unroll
                for (int fn = 0; fn < NFRAG; fn++)
                    mma_f16(acc[fm][fn], ah[fm], bh[fn], acc[fm][fn]);
        }
        if (kb + BK < K) {
            cp_wait<0>(); __syncthreads();
            convert(); __syncthreads();
            if (kb + 2 * BK < K) { cpA(kb + 2*BK); cpB(kb + 2*BK, ibuf); cp_commit(); }
        }
    }

    // ---- epilogue ----
#pragma unroll
    for (int fm = 0; fm < MFRAG; fm++) {
        const int m0 = mbase + wm * WM + fm * 16 + gq;
#pragma unroll
        for (int fn = 0; fn < NFRAG; fn++) {
            const int n0 = nbase + wn * WN + fn * 8 + tq * 2;
            float v0 = alpha * acc[fm][fn][0], v1 = alpha * acc[fm][fn][1];
            float v2 = alpha * acc[fm][fn][2], v3 = alpha * acc[fm][fn][3];
            if (HASC) {
                const float* ci0 = Cin + (size_t)m0 * ldc + n0;
                const float* ci1 = Cin + (size_t)(m0 + 8) * ldc + n0;
                v0 += beta * ci0[0]; v1 += beta * ci0[1];
                v2 += beta * ci1[0]; v3 += beta * ci1[1];
            }
            const bool planes = (EPI == 1) || (EPI == 2 && z == 1);
            if (planes) {
                __half* hh = Hh + (EPI == 1 ? z * sH : 0);
                __half* hl = Hl + (EPI == 1 ? z * sH : 0);
                uint32_t h01, l01, h23, l23;
                split2(v0, v1, h01, l01);
                split2(v2, v3, h23, l23);
                *(uint32_t*)&hh[(size_t)m0 * ldc + n0] = h01;
                *(uint32_t*)&hl[(size_t)m0 * ldc + n0] = l01;
                *(uint32_t*)&hh[(size_t)(m0 + 8) * ldc + n0] = h23;
                *(uint32_t*)&hl[(size_t)(m0 + 8) * ldc + n0] = l23;
            } else if (EPI == 2 && z == 2) {
                *(uint32_t*)&Ht[(size_t)m0 * ldc + n0] = pack_h2(v0, v1);
                *(uint32_t*)&Ht[(size_t)(m0 + 8) * ldc + n0] = pack_h2(v2, v3);
            } else {
                float* c0 = C + (size_t)m0 * ldc + n0;
                float* c1 = C + (size_t)(m0 + 8) * ldc + n0;
                c0[0] = v0; c0[1] = v1;
                c1[0] = v2; c1[1] = v3;
            }
        }
    }
}

// ---------------- fused flash attention: triple-buffered, trans-V, q hi-only ----------------
#define FA_LD  72
#define FA_PL  (128*FA_LD)
#define FA_NT  (SEQ/128)
#define FA_SMEM (9*FA_PL*2)

__global__ void __launch_bounds__(256)
flash_attn(const float* __restrict__ qf,
           const __half* __restrict__ khi, const __half* __restrict__ klo,
           const __half* __restrict__ vhi, float* __restrict__ outb)
{
    extern __shared__ __half sm[];

    const int hh = blockIdx.x;
    const int b = hh >> 4, h = hh & 15;
    const int qt = blockIdx.y;

    const int tid = threadIdx.x;
    const int w = tid >> 5, lane = tid & 31;
    const int gq = lane >> 2, tq = lane & 3;
    const int b_row = (lane & 7) + (((lane >> 4) & 1) << 3);
    const int b_kof = ((lane >> 3) & 1) << 3;
    const int vt_row = ((lane >> 3) & 1) * 8 + (lane & 7);
    const int vt_col = ((lane >> 4) & 1) * 8;

    const __half* Kh = khi + ((size_t)b * SEQ) * EMBED + h * HDIM;
    const __half* Kl = klo + ((size_t)b * SEQ) * EMBED + h * HDIM;
    const __half* Vh = vhi + ((size_t)b * SEQ) * EMBED + h * HDIM;

    auto cpKV = [&](int j) {
        __half* dst = sm + (j % 3) * 3 * FA_PL;
        const __half* sh = Kh + (size_t)(j * 128) * EMBED;
        const __half* sl = Kl + (size_t)(j * 128) * EMBED;
        const __half* sv = Vh + (size_t)(j * 128) * EMBED;
#pragma unroll
        for (int i = 0; i < 4; i++) {
            int c = i * 256 + tid;
            int row = c >> 3, c8 = c & 7;
            cp16(dst +            row * FA_LD + c8 * 8, sh + (size_t)row * EMBED + c8 * 8);
            cp16(dst +   FA_PL +  row * FA_LD + c8 * 8, sl + (size_t)row * EMBED + c8 * 8);
            cp16(dst + 2*FA_PL +  row * FA_LD + c8 * 8, sv + (size_t)row * EMBED + c8 * 8);
        }
        cp_commit();
    };

    // ---- Q fragments: hi-only (pre-scaled) ----
    uint32_t qh[4][4];
    {
        const float* Qb = qf + ((size_t)b * SEQ) * EMBED + h * HDIM;
        const int r0 = qt * 128 + w * 16 + gq;
        const float* Qr0 = Qb + (size_t)r0 * EMBED;
        const float* Qr1 = Qr0 + 8 * (size_t)EMBED;
#pragma unroll
        for (int ks = 0; ks < 4; ks++) {
            const int c = 16 * ks + 2 * tq;
            float2 x0 = *(const float2*)(Qr0 + c);
            float2 x1 = *(const float2*)(Qr1 + c);
            float2 x2 = *(const float2*)(Qr0 + c + 8);
            float2 x3 = *(const float2*)(Qr1 + c + 8);
            qh[ks][0] = pack_h2(x0.x * 0.125f, x0.y * 0.125f);
            qh[ks][1] = pack_h2(x1.x * 0.125f, x1.y * 0.125f);
            qh[ks][2] = pack_h2(x2.x * 0.125f, x2.y * 0.125f);
            qh[ks][3] = pack_h2(x3.x * 0.125f, x3.y * 0.125f);
        }
    }

    float o[8][4];
#pragma unroll
    for (int i = 0; i < 8; i++)
#pragma unroll
        for (int r = 0; r < 4; r++) o[i][r] = 0.f;
    float m0r = -1e30f, m1r = -1e30f, l0 = 0.f, l1 = 0.f;

    cpKV(0);
    cpKV(1);

    for (int j = 0; j < FA_NT; j++) {
        if (j + 1 < FA_NT) cp_wait<1>(); else cp_wait<0>();
        __syncthreads();
        if (j + 2 < FA_NT) cpKV(j + 2);

        const __half* Kbh = sm + (j % 3) * 3 * FA_PL;
        const __half* Kbl = Kbh + FA_PL;
        const __half* Vb  = Kbh + 2 * FA_PL;

        // ---- S = Q_hi (K_hi + K_lo): 2 phases of 4 independent MMAs ----
        float s[16][4];
#pragma unroll
        for (int f = 0; f < 16; f++)
#pragma unroll
            for (int r = 0; r < 4; r++) s[f][r] = 0.f;
#pragma unroll
        for (int ks = 0; ks < 4; ks++) {
            const int k0 = 16 * ks;
#pragma unroll
            for (int fp = 0; fp < 4; fp++) {
                const int nr0 = (2*fp)     * 16 + b_row;
                const int nr1 = (2*fp + 1) * 16 + b_row;
                uint32_t th0[4], tl0[4], th1[4], tl1[4];
                ldmx4(th0, &Kbh[nr0 * FA_LD + k0 + b_kof]);
                ldmx4(tl0, &Kbl[nr0 * FA_LD + k0 + b_kof]);
                ldmx4(th1, &Kbh[nr1 * FA_LD + k0 + b_kof]);
                ldmx4(tl1, &Kbl[nr1 * FA_LD + k0 + b_kof]);
                uint32_t bh00[2] = {th0[0], th0[1]}, bh01[2] = {th0[2], th0[3]};
                uint32_t bl00[2] = {tl0[0], tl0[1]}, bl01[2] = {tl0[2], tl0[3]};
                uint32_t bh10[2] = {th1[0], th1[1]}, bh11[2] = {th1[2], th1[3]};
                uint32_t bl10[2] = {tl1[0], tl1[1]}, bl11[2] = {tl1[2], tl1[3]};
                // phase 1: qh . K_lo (small term first)
                mma_f16(s[4*fp],   qh[ks], bl00, s[4*fp]);
                mma_f16(s[4*fp+1], qh[ks], bl01, s[4*fp+1]);
                mma_f16(s[4*fp+2], qh[ks], bl10, s[4*fp+2]);
                mma_f16(s[4*fp+3], qh[ks], bl11, s[4*fp+3]);
                // phase 2: qh . K_hi
                mma_f16(s[4*fp],   qh[ks], bh00, s[4*fp]);
                mma_f16(s[4*fp+1], qh[ks], bh01, s[4*fp+1]);
                mma_f16(s[4*fp+2], qh[ks], bh10, s[4*fp+2]);
                mma_f16(s[4*fp+3], qh[ks], bh11, s[4*fp+3]);
            }
        }

        float mx0 = -1e30f, mx1 = -1e30f;
#pragma unroll
        for (int f = 0; f < 16; f++) {
            mx0 = fmaxf(mx0, fmaxf(s[f][0], s[f][1]));
            mx1 = fmaxf(mx1, fmaxf(s[f][2], s[f][3]));
        }
        mx0 = fmaxf(mx0, __shfl_xor_sync(0xffffffffu, mx0, 1));
        mx0 = fmaxf(mx0, __shfl_xor_sync(0xffffffffu, mx0, 2));
        mx1 = fmaxf(mx1, __shfl_xor_sync(0xffffffffu, mx1, 1));
        mx1 = fmaxf(mx1, __shfl_xor_sync(0xffffffffu, mx1, 2));
        const float mn0 = fmaxf(m0r, mx0), mn1 = fmaxf(m1r, mx1);
        const float cr0 = __expf(m0r - mn0), cr1 = __expf(m1r - mn1);
        m0r = mn0; m1r = mn1;

        float rs0 = 0.f, rs1 = 0.f;
#pragma unroll
        for (int f = 0; f < 16; f++) {
            s[f][0] = __expf(s[f][0] - mn0);
            s[f][1] = __expf(s[f][1] - mn0);
            s[f][2] = __expf(s[f][2] - mn1);
            s[f][3] = __expf(s[f][3] - mn1);
            rs0 += s[f][0] + s[f][1];
            rs1 += s[f][2] + s[f][3];
        }
        rs0 += __shfl_xor_sync(0xffffffffu, rs0, 1);
        rs0 += __shfl_xor_sync(0xffffffffu, rs0, 2);
        rs1 += __shfl_xor_sync(0xffffffffu, rs1, 1);
        rs1 += __shfl_xor_sync(0xffffffffu, rs1, 2);
        l0 = l0 * cr0 + rs0;
        l1 = l1 * cr1 + rs1;
#pragma unroll
        for (int fn = 0; fn < 8; fn++) {
            o[fn][0] *= cr0; o[fn][1] *= cr0;
            o[fn][2] *= cr1; o[fn][3] *= cr1;
        }

#pragma unroll
        for (int ks = 0; ks < 8; ks++) {
            uint32_t pa[4];
            pa[0] = pack_h2(s[2*ks][0],   s[2*ks][1]);
            pa[1] = pack_h2(s[2*ks][2],   s[2*ks][3]);
            pa[2] = pack_h2(s[2*ks+1][0], s[2*ks+1][1]);
            pa[3] = pack_h2(s[2*ks+1][2], s[2*ks+1][3]);
            const int k0 = 16 * ks;
#pragma unroll
            for (int fp = 0; fp < 4; fp++) {
                uint32_t t[4];
                ldmx4t(t, &Vb[(k0 + vt_row) * FA_LD + fp * 16 + vt_col]);
                uint32_t b0[2] = {t[0], t[1]}, b1[2] = {t[2], t[3]};
                mma_f16(o[2*fp],   pa, b0, o[2*fp]);
                mma_f16(o[2*fp+1], pa, b1, o[2*fp+1]);
            }
        }
    }

    const float inv0 = 1.f / l0, inv1 = 1.f / l1;
    const int r0 = qt * 128 + w * 16 + gq;
    float* Ob0 = outb + ((size_t)(b * SEQ + r0)) * EMBED + h * HDIM;
    float* Ob1 = Ob0 + 8 * (size_t)EMBED;
#pragma unroll
    for (int fn = 0; fn < 8; fn++) {
        const int c = fn * 8 + 2 * tq;
        float2 t0; t0.x = o[fn][0] * inv0; t0.y = o[fn][1] * inv0;
        float2 t1; t1.x = o[fn][2] * inv1; t1.y = o[fn][3] * inv1;
        *(float2*)(Ob0 + c) = t0;
        *(float2*)(Ob1 + c) = t1;
    }
}

// ---------------- host launch ----------------
extern "C" void kernel_launch(void* const* d_in, const int* in_sizes, int n_in,
                              void* d_out, int out_size)
{
    (void)in_sizes; (void)n_in; (void)out_size;
    const float* query = (const float*)d_in[0];
    const float* key   = (const float*)d_in[1];
    const float* value = (const float*)d_in[2];
    const float* Wq    = (const float*)d_in[3];
    const float* Wk    = (const float*)d_in[4];
    const float* Wv    = (const float*)d_in[5];
    const float* Wo    = (const float*)d_in[6];
    float* out = (float*)d_out;

    float *Mcat, *q, *at;
    __half *Wo2h, *Wo2l, *Wvh, *Wvl, *Woh, *Wol, *kh, *kl, *vh;
    cudaGetSymbolAddress((void**)&Mcat, g_Mcat);
    cudaGetSymbolAddress((void**)&q,    g_q);
    cudaGetSymbolAddress((void**)&at,   g_at);
    cudaGetSymbolAddress((void**)&Wo2h, g_Wo2h);
    cudaGetSymbolAddress((void**)&Wo2l, g_Wo2l);
    cudaGetSymbolAddress((void**)&Wvh,  g_Wvh);
    cudaGetSymbolAddress((void**)&Wvl,  g_Wvl);
    cudaGetSymbolAddress((void**)&Woh,  g_Woh);
    cudaGetSymbolAddress((void**)&Wol,  g_Wol);
    cudaGetSymbolAddress((void**)&kh,   g_kh);
    cudaGetSymbolAddress((void**)&kl,   g_kl);
    cudaGetSymbolAddress((void**)&vh,   g_vh);

    split_planes<<<EE/256, 256>>>(Wv, Wvh, Wvl);
    split_planes<<<EE/256, 256>>>(Wo, Woh, Wol);

    // 1: Mcat[0]=Wk^T Wk ; Mcat[1]=Wq^T Wq   (A hi-only, B split: 2 MMAs)
    {
        auto kfn = gemm_f16s<128,128,64,32,32,true,false,false,false,false,0>;
        int sm = (128*64 + 128*64)*4 + (1*128 + 2*128)*72*2;   // 120832
        cudaFuncSetAttribute(kfn, cudaFuncAttributeMaxDynamicSharedMemorySize, sm);
        dim3 grid(8, 8, 2);
        kfn<<<grid, 512, sm>>>(
            Wk, Wq, nullptr,  Wk, Wq, nullptr,  nullptr, nullptr, nullptr,
            nullptr, nullptr, nullptr,
            Mcat, Mcat + EE, nullptr,
            nullptr, nullptr, nullptr, 0,
            EMBED, EMBED, EMBED, EMBED, EMBED, EMBED, 1.f, 0.f);
    }
    // 2: Wo2[z] = W[z] - W[z]@Mcat[z]  -> fp16 planes  (full split)
    {
        auto kfn = gemm_f16s<128,128,64,32,32,false,false,true,true,false,1>;
        int sm = (128*64 + 128*64)*4 + (2*128 + 2*128)*72*2;   // 139264
        cudaFuncSetAttribute(kfn, cudaFuncAttributeMaxDynamicSharedMemorySize, sm);
        dim3 grid(8, 8, 2);
        kfn<<<grid, 512, sm>>>(
            Wq, Wk, nullptr,  Mcat, Mcat + EE, nullptr,  nullptr, nullptr, nullptr,
            Wq, Wk, nullptr,
            nullptr, nullptr, nullptr,
            Wo2h, Wo2l, nullptr, (long long)EE,
            EMBED, EMBED, EMBED, EMBED, EMBED, EMBED, -1.f, 1.f);
    }
    // 3: projections: z0 q fp32, z1 k planes, z2 v hi plane
    {
        auto kfn = gemm_f16s<128,128,64,32,32,false,true,false,false,true,2>;
        int sm = 128*64*4 + 1*128*72*2 + 4*128*72*2;           // 124928
        cudaFuncSetAttribute(kfn, cudaFuncAttributeMaxDynamicSharedMemorySize, sm);
        dim3 grid(8, 32, 3);
        kfn<<<grid, 512, sm>>>(
            query, key, value,
            Wo2h, Wo2h + EE, Wvh,  Wo2l, Wo2l + EE, Wvl,
            nullptr, nullptr, nullptr,
            q, nullptr, nullptr,
            kh, kl, vh, 0,
            ROWSM, EMBED, EMBED, EMBED, EMBED, EMBED, 1.f, 0.f);
    }
    // 4: flash attention (q hi-only)
    {
        cudaFuncSetAttribute(flash_attn, cudaFuncAttributeMaxDynamicSharedMemorySize, FA_SMEM);
        dim3 grid(BATCH * HEADS, SEQ / 128);
        flash_attn<<<grid, 256, FA_SMEM>>>(q, kh, kl, vh, at);
    }
    // 5: out = at @ Wo^T  (A hi-only, B pre-split)
    {
        auto kfn = gemm_f16s<128,128,64,32,32,false,true,false,false,true,0>;
        int sm = 128*64*4 + 1*128*72*2 + 4*128*72*2;           // 124928
        cudaFuncSetAttribute(kfn, cudaFuncAttributeMaxDynamicSharedMemorySize, sm);
        dim3 grid(8, 32, 1);
        kfn<<<grid, 512, sm>>>(
            at, nullptr, nullptr,
            Woh, nullptr, nullptr,  Wol, nullptr, nullptr,
            nullptr, nullptr, nullptr,
            out, nullptr, nullptr,
            nullptr, nullptr, nullptr, 0,
            ROWSM, EMBED, EMBED, EMBED, EMBED, EMBED, 1.f, 0.f);
    }
}

// round 14
// speedup vs baseline: 1.3987x; 1.0176x over previous
#include <cuda_runtime.h>
#include <cuda_fp16.h>
#include <cstdint>

#define EMBED 1024
#define HEADS 16
#define HDIM  64
#define BATCH 2
#define SEQ   2048
#define ROWSM (BATCH*SEQ)   // 4096
#define EE    (EMBED*EMBED)
#define RME   (ROWSM*EMBED)

// ---------------- scratch (__device__ globals; no allocation allowed) ----------------
__device__ float  g_Mcat[2*EE];    // [Wk^T Wk, Wq^T Wq]
__device__ float  g_q   [RME];     // q projected (fp32)
__device__ float  g_at  [RME];     // attention output
__device__ __half g_Wo2h[2*EE], g_Wo2l[2*EE];  // [Wqo, Wko] planes
__device__ __half g_Wvh [EE],   g_Wvl [EE];    // Wv planes
__device__ __half g_Woh [EE],   g_Wol [EE];    // Wo planes
__device__ __half g_kh  [RME],  g_kl  [RME];   // k planes  [b*S+s][E]
__device__ __half g_vh  [RME];                 // v hi plane [b*S+s][E]

// ---------------- helpers ----------------
__device__ __forceinline__ void split_f16(float f, __half& hi, __half& lo) {
    hi = __float2half_rn(f);
    lo = __float2half_rn(f - __half2float(hi));
}
__device__ __forceinline__ void split2(float a, float b, uint32_t& hi, uint32_t& lo) {
    __half2 h = __floats2half2_rn(a, b);
    float2 hf = __half22float2(h);
    __half2 l = __floats2half2_rn(a - hf.x, b - hf.y);
    hi = *reinterpret_cast<uint32_t*>(&h);
    lo = *reinterpret_cast<uint32_t*>(&l);
}
__device__ __forceinline__ uint32_t pack_h2(float a, float b) {
    __half2 h = __floats2half2_rn(a, b);
    return *reinterpret_cast<uint32_t*>(&h);
}
__device__ __forceinline__ void mma_f16(float (&d)[4], const uint32_t (&a)[4],
                                        const uint32_t (&b)[2], const float (&c)[4]) {
    asm volatile(
        "mma.sync.aligned.m16n8k16.row.col.f32.f16.f16.f32 "
        "{%0,%1,%2,%3},{%4,%5,%6,%7},{%8,%9},{%10,%11,%12,%13};\n"
        : "=f"(d[0]), "=f"(d[1]), "=f"(d[2]), "=f"(d[3])
        : "r"(a[0]), "r"(a[1]), "r"(a[2]), "r"(a[3]),
          "r"(b[0]), "r"(b[1]),
          "f"(c[0]), "f"(c[1]), "f"(c[2]), "f"(c[3]));
}
__device__ __forceinline__ uint32_t sptr(const void* p) {
    return (uint32_t)__cvta_generic_to_shared(p);
}
__device__ __forceinline__ void ldmx4(uint32_t* r, const __half* p) {
    asm volatile("ldmatrix.sync.aligned.m8n8.x4.shared.b16 {%0,%1,%2,%3}, [%4];"
        : "=r"(r[0]), "=r"(r[1]), "=r"(r[2]), "=r"(r[3]) : "r"(sptr(p)));
}
__device__ __forceinline__ void ldmx4t(uint32_t* r, const __half* p) {
    asm volatile("ldmatrix.sync.aligned.m8n8.x4.trans.shared.b16 {%0,%1,%2,%3}, [%4];"
        : "=r"(r[0]), "=r"(r[1]), "=r"(r[2]), "=r"(r[3]) : "r"(sptr(p)));
}
__device__ __forceinline__ void cp16(void* s, const void* g) {
    asm volatile("cp.async.cg.shared.global [%0], [%1], 16;" :: "r"(sptr(s)), "l"(g));
}
__device__ __forceinline__ void cp_commit() { asm volatile("cp.async.commit_group;"); }
template<int N> __device__ __forceinline__ void cp_wait() {
    asm volatile("cp.async.wait_group %0;" :: "n"(N));
}

// ---------------- weight pre-split kernel ----------------
__global__ void __launch_bounds__(256) split_planes(const float* __restrict__ w,
                                                    __half* __restrict__ hi,
                                                    __half* __restrict__ lo) {
    int i = blockIdx.x * 256 + threadIdx.x;
    __half h, l; split_f16(w[i], h, l);
    hi[i] = h; lo[i] = l;
}

// ---------------- generic batched split-fp16 GEMM (R12 winning config) ----------------
// z selects pointer set. C = alpha*opA(A)*opB(B) [+ beta*Cin]
// BPRE: B pre-split planes [n][k], cp'd direct, double-buffered. Else fp32 staged.
// EPI: 0 = fp32 C; 1 = planes Hh/Hl (+z*sH); 2 = qkv (z0: fp32 C0; z1: planes; z2: hi->Ht)
template<int BM,int BN,int BK,int WM,int WN,bool TA,bool TB,bool HASC,bool SPLITA,bool BPRE,int EPI>
__global__ void __launch_bounds__((BM/WM)*(BN/WN)*32)
gemm_f16s(const float* A0, const float* A1, const float* A2,
          const void* Bv0, const void* Bv1, const void* Bv2,
          const __half* Bl0, const __half* Bl1, const __half* Bl2,
          const float* Ci0, const float* Ci1, const float* Ci2,
          float* C0, float* C1, float* C2,
          __half* Hh, __half* Hl, __half* Ht, long long sH,
          int M, int N, int K, int lda, int ldb, int ldc,
          float alpha, float beta)
{
    constexpr int WARPS_N = BN / WN;
    constexpr int WARPS_M = BM / WM;
    constexpr int NTH = WARPS_M * WARPS_N * 32;
    constexpr int MFRAG = WM / 16, NFRAG = WN / 8, KSTEPS = BK / 16;
    constexpr int LDK = BK + 8;
    constexpr int EA = BM * BK / NTH, EB = BN * BK / NTH;
    constexpr int CA = BM * BK / 4 / NTH, CB = BN * BK / 4 / NTH;
    constexpr int CBH = (BN * (BK / 8)) / NTH;
    constexpr int APL = SPLITA ? 2 : 1;

    extern __shared__ char smraw[];
    float*  Ast = (float*)smraw;
    float*  Bst = nullptr;
    __half* As;
    __half* Bs;
    if constexpr (BPRE) {
        As = (__half*)(Ast + BM * BK);
        Bs = As + APL * BM * LDK;          // [2 buf][2 plane][BN*LDK]
    } else {
        Bst = Ast + BM * BK;
        As = (__half*)(Bst + BN * BK);
        Bs = As + APL * BM * LDK;          // [2 plane][BN*LDK]
    }

    const int z = blockIdx.z;
    const float* A = (z == 0) ? A0 : ((z == 1) ? A1 : A2);
    const void*  Bv = (z == 0) ? Bv0 : ((z == 1) ? Bv1 : Bv2);
    const __half* Bl = (z == 0) ? Bl0 : ((z == 1) ? Bl1 : Bl2);
    const float* Cin = (z == 0) ? Ci0 : ((z == 1) ? Ci1 : Ci2);
    float*       C = (z == 0) ? C0 : ((z == 1) ? C1 : C2);

    const int mbase = blockIdx.y * BM;
    const int nbase = blockIdx.x * BN;
    const int tid  = threadIdx.x;
    const int warp = tid >> 5, lane = tid & 31;
    const int wm = warp / WARPS_N, wn = warp % WARPS_N;
    const int gq = lane >> 2, tq = lane & 3;

    float acc[MFRAG][NFRAG][4];
#pragma unroll
    for (int i = 0; i < MFRAG; i++)
#pragma unroll
        for (int j = 0; j < NFRAG; j++)
#pragma unroll
            for (int r = 0; r < 4; r++) acc[i][j][r] = 0.f;

    auto cpA = [&](int kb) {
#pragma unroll
        for (int i = 0; i < CA; i++) {
            int e = i * NTH + tid;
            if (TA) { int k = e / (BM/4), mc = e % (BM/4);
                cp16(Ast + k * BM + 4 * mc, A + (size_t)(kb + k) * lda + mbase + 4 * mc); }
            else    { int m = e / (BK/4), kc = e % (BK/4);
                cp16(Ast + m * BK + 4 * kc, A + (size_t)(mbase + m) * lda + kb + 4 * kc); }
        }
    };
    auto cpB = [&](int kb, int buf) {
        if constexpr (BPRE) {
            const __half* Bh = (const __half*)Bv;
#pragma unroll
            for (int i = 0; i < CBH; i++) {
                int e = i * NTH + tid;
                int n = e / (BK/8), k8 = e % (BK/8);
                cp16(Bs + (buf*2 + 0) * BN * LDK + n * LDK + k8 * 8,
                     Bh + (size_t)(nbase + n) * ldb + kb + k8 * 8);
                cp16(Bs + (buf*2 + 1) * BN * LDK + n * LDK + k8 * 8,
                     Bl + (size_t)(nbase + n) * ldb + kb + k8 * 8);
            }
        } else {
            const float* Bf = (const float*)Bv;
#pragma unroll
            for (int i = 0; i < CB; i++) {
                int e = i * NTH + tid;
                if (TB) { int n = e / (BK/4), kc = e % (BK/4);
                    cp16(Bst + n * BK + 4 * kc, Bf + (size_t)(nbase + n) * ldb + kb + 4 * kc); }
                else    { int k = e / (BN/4), nc = e % (BN/4);
                    cp16(Bst + k * BN + 4 * nc, Bf + (size_t)(kb + k) * ldb + nbase + 4 * nc); }
            }
        }
    };
    auto convert = [&]() {
#pragma unroll
        for (int i = 0; i < EA; i++) {
            int e = i * NTH + tid; int m, k;
            if (TA) { k = e / BM; m = e % BM; } else { m = e / BK; k = e % BK; }
            float f = Ast[e];
            if (SPLITA) {
                __half h, l; split_f16(f, h, l);
                As[m * LDK + k] = h;
                As[BM * LDK + m * LDK + k] = l;
            } else {
                As[m * LDK + k] = __float2half_rn(f);
            }
        }
        if constexpr (!BPRE) {
#pragma unroll
            for (int i = 0; i < EB; i++) {
                int e = i * NTH + tid; int n, k;
                if (TB) { n = e / BK; k = e % BK; } else { k = e / BN; n = e % BN; }
                float f = Bst[e];
                __half h, l; split_f16(f, h, l);
                Bs[n * LDK + k] = h;
                Bs[BN * LDK + n * LDK + k] = l;
            }
        }
    };

    cpA(0); cpB(0, 0); cp_commit();
    cp_wait<0>(); __syncthreads();
    convert(); __syncthreads();
    if (BK < K) { cpA(BK); cpB(BK, 1); cp_commit(); }

    const int a_row = (lane & 15);
    const int a_kof = (lane >> 4) << 3;
    const int b_row = (lane & 7) + (((lane >> 4) & 1) << 3);
    const int b_kof = ((lane >> 3) & 1) << 3;

    for (int kb = 0; kb < K; kb += BK) {
        const int ibuf = BPRE ? ((kb / BK) & 1) : 0;
        const __half* Bsh = Bs + (BPRE ? (ibuf*2 + 0) * BN * LDK : 0);
        const __half* Bsl = Bs + (BPRE ? (ibuf*2 + 1) * BN * LDK : BN * LDK);
#pragma unroll
        for (int ks = 0; ks < KSTEPS; ks++) {
            const int k0 = ks * 16;
            uint32_t ah[MFRAG][4], al[MFRAG][4];
            uint32_t bh[NFRAG][2], bl[NFRAG][2];
#pragma unroll
            for (int fm = 0; fm < MFRAG; fm++) {
                const int mr = wm * WM + fm * 16 + a_row;
                ldmx4(ah[fm], &As[mr * LDK + k0 + a_kof]);
                if (SPLITA)
                    ldmx4(al[fm], &As[BM * LDK + mr * LDK + k0 + a_kof]);
            }
#pragma unroll
            for (int fp = 0; fp < NFRAG / 2; fp++) {
                const int nr = wn * WN + fp * 16 + b_row;
                uint32_t t[4];
                ldmx4(t, &Bsh[nr * LDK + k0 + b_kof]);
                bh[2*fp][0] = t[0]; bh[2*fp][1] = t[1];
                bh[2*fp+1][0] = t[2]; bh[2*fp+1][1] = t[3];
                ldmx4(t, &Bsl[nr * LDK + k0 + b_kof]);
                bl[2*fp][0] = t[0]; bl[2*fp][1] = t[1];
                bl[2*fp+1][0] = t[2]; bl[2*fp+1][1] = t[3];
            }
            if (SPLITA) {
#pragma unroll
                for (int fm = 0; fm < MFRAG; fm++)
#pragma unroll
                    for (int fn = 0; fn < NFRAG; fn++)
                        mma_f16(acc[fm][fn], al[fm], bh[fn], acc[fm][fn]);
            }
#pragma unroll
            for (int fm = 0; fm < MFRAG; fm++)
#pragma unroll
                for (int fn = 0; fn < NFRAG; fn++)
                    mma_f16(acc[fm][fn], ah[fm], bl[fn], acc[fm][fn]);
#pragma unroll
            for (int fm = 0; fm < MFRAG; fm++)
#pragma unroll
                for (int fn = 0; fn < NFRAG; fn++)
                    mma_f16(acc[fm][fn], ah[fm], bh[fn], acc[fm][fn]);
        }
        if (kb + BK < K) {
            cp_wait<0>(); __syncthreads();
            convert(); __syncthreads();
            if (kb + 2 * BK < K) { cpA(kb + 2*BK); cpB(kb + 2*BK, ibuf); cp_commit(); }
        }
    }

#pragma unroll
    for (int fm = 0; fm < MFRAG; fm++) {
        const int m0 = mbase + wm * WM + fm * 16 + gq;
#pragma unroll
        for (int fn = 0; fn < NFRAG; fn++) {
            const int n0 = nbase + wn * WN + fn * 8 + tq * 2;
            float v0 = alpha * acc[fm][fn][0], v1 = alpha * acc[fm][fn][1];
            float v2 = alpha * acc[fm][fn][2], v3 = alpha * acc[fm][fn][3];
            if (HASC) {
                const float* ci0 = Cin + (size_t)m0 * ldc + n0;
                const float* ci1 = Cin + (size_t)(m0 + 8) * ldc + n0;
                v0 += beta * ci0[0]; v1 += beta * ci0[1];
                v2 += beta * ci1[0]; v3 += beta * ci1[1];
            }
            const bool planes = (EPI == 1) || (EPI == 2 && z == 1);
            if (planes) {
                __half* hh = Hh + (EPI == 1 ? z * sH : 0);
                __half* hl = Hl + (EPI == 1 ? z * sH : 0);
                uint32_t h01, l01, h23, l23;
                split2(v0, v1, h01, l01);
                split2(v2, v3, h23, l23);
                *(uint32_t*)&hh[(size_t)m0 * ldc + n0] = h01;
                *(uint32_t*)&hl[(size_t)m0 * ldc + n0] = l01;
                *(uint32_t*)&hh[(size_t)(m0 + 8) * ldc + n0] = h23;
                *(uint32_t*)&hl[(size_t)(m0 + 8) * ldc + n0] = l23;
            } else if (EPI == 2 && z == 2) {
                *(uint32_t*)&Ht[(size_t)m0 * ldc + n0] = pack_h2(v0, v1);
                *(uint32_t*)&Ht[(size_t)(m0 + 8) * ldc + n0] = pack_h2(v2, v3);
            } else {
                float* c0 = C + (size_t)m0 * ldc + n0;
                float* c1 = C + (size_t)(m0 + 8) * ldc + n0;
                c0[0] = v0; c0[1] = v1;
                c1[0] = v2; c1[1] = v3;
            }
        }
    }
}

// ---------------- fused flash attention: 512 threads, BQ=256, shared KV ----------------
#define FA_LD  72
#define FA_PL  (128*FA_LD)
#define FA_NT  (SEQ/128)
#define FA_SMEM (9*FA_PL*2)

__global__ void __launch_bounds__(512)
flash_attn(const float* __restrict__ qf,
           const __half* __restrict__ khi, const __half* __restrict__ klo,
           const __half* __restrict__ vhi, float* __restrict__ outb)
{
    extern __shared__ __half sm[];

    const int hh = blockIdx.x;
    const int b = hh >> 4, h = hh & 15;
    const int qt = blockIdx.y;            // 0..7 (256 q rows per block)

    const int tid = threadIdx.x;
    const int w = tid >> 5, lane = tid & 31;   // 16 warps
    const int gq = lane >> 2, tq = lane & 3;
    const int b_row = (lane & 7) + (((lane >> 4) & 1) << 3);
    const int b_kof = ((lane >> 3) & 1) << 3;
    const int vt_row = ((lane >> 3) & 1) * 8 + (lane & 7);
    const int vt_col = ((lane >> 4) & 1) * 8;

    const __half* Kh = khi + ((size_t)b * SEQ) * EMBED + h * HDIM;
    const __half* Kl = klo + ((size_t)b * SEQ) * EMBED + h * HDIM;
    const __half* Vh = vhi + ((size_t)b * SEQ) * EMBED + h * HDIM;

    auto cpKV = [&](int j) {
        __half* dst = sm + (j % 3) * 3 * FA_PL;
        const __half* sh = Kh + (size_t)(j * 128) * EMBED;
        const __half* sl = Kl + (size_t)(j * 128) * EMBED;
        const __half* sv = Vh + (size_t)(j * 128) * EMBED;
#pragma unroll
        for (int i = 0; i < 2; i++) {
            int c = i * 512 + tid;
            int row = c >> 3, c8 = c & 7;
            cp16(dst +            row * FA_LD + c8 * 8, sh + (size_t)row * EMBED + c8 * 8);
            cp16(dst +   FA_PL +  row * FA_LD + c8 * 8, sl + (size_t)row * EMBED + c8 * 8);
            cp16(dst + 2*FA_PL +  row * FA_LD + c8 * 8, sv + (size_t)row * EMBED + c8 * 8);
        }
        cp_commit();
    };

    // ---- Q fragments: hi-only (pre-scaled) ----
    uint32_t qh[4][4];
    {
        const float* Qb = qf + ((size_t)b * SEQ) * EMBED + h * HDIM;
        const int r0 = qt * 256 + w * 16 + gq;
        const float* Qr0 = Qb + (size_t)r0 * EMBED;
        const float* Qr1 = Qr0 + 8 * (size_t)EMBED;
#pragma unroll
        for (int ks = 0; ks < 4; ks++) {
            const int c = 16 * ks + 2 * tq;
            float2 x0 = *(const float2*)(Qr0 + c);
            float2 x1 = *(const float2*)(Qr1 + c);
            float2 x2 = *(const float2*)(Qr0 + c + 8);
            float2 x3 = *(const float2*)(Qr1 + c + 8);
            qh[ks][0] = pack_h2(x0.x * 0.125f, x0.y * 0.125f);
            qh[ks][1] = pack_h2(x1.x * 0.125f, x1.y * 0.125f);
            qh[ks][2] = pack_h2(x2.x * 0.125f, x2.y * 0.125f);
            qh[ks][3] = pack_h2(x3.x * 0.125f, x3.y * 0.125f);
        }
    }

    float o[8][4];
#pragma unroll
    for (int i = 0; i < 8; i++)
#pragma unroll
        for (int r = 0; r < 4; r++) o[i][r] = 0.f;
    float m0r = -1e30f, m1r = -1e30f, l0 = 0.f, l1 = 0.f;

    cpKV(0);
    cpKV(1);

    for (int j = 0; j < FA_NT; j++) {
        if (j + 1 < FA_NT) cp_wait<1>(); else cp_wait<0>();
        __syncthreads();
        if (j + 2 < FA_NT) cpKV(j + 2);

        const __half* Kbh = sm + (j % 3) * 3 * FA_PL;
        const __half* Kbl = Kbh + FA_PL;
        const __half* Vb  = Kbh + 2 * FA_PL;

        // ---- S = Q_hi (K_hi + K_lo): 2 phases of 4 independent MMAs ----
        float s[16][4];
#pragma unroll
        for (int f = 0; f < 16; f++)
#pragma unroll
            for (int r = 0; r < 4; r++) s[f][r] = 0.f;
#pragma unroll
        for (int ks = 0; ks < 4; ks++) {
            const int k0 = 16 * ks;
#pragma unroll
            for (int fp = 0; fp < 4; fp++) {
                const int nr0 = (2*fp)     * 16 + b_row;
                const int nr1 = (2*fp + 1) * 16 + b_row;
                uint32_t th0[4], tl0[4], th1[4], tl1[4];
                ldmx4(th0, &Kbh[nr0 * FA_LD + k0 + b_kof]);
                ldmx4(tl0, &Kbl[nr0 * FA_LD + k0 + b_kof]);
                ldmx4(th1, &Kbh[nr1 * FA_LD + k0 + b_kof]);
                ldmx4(tl1, &Kbl[nr1 * FA_LD + k0 + b_kof]);
                uint32_t bh00[2] = {th0[0], th0[1]}, bh01[2] = {th0[2], th0[3]};
                uint32_t bl00[2] = {tl0[0], tl0[1]}, bl01[2] = {tl0[2], tl0[3]};
                uint32_t bh10[2] = {th1[0], th1[1]}, bh11[2] = {th1[2], th1[3]};
                uint32_t bl10[2] = {tl1[0], tl1[1]}, bl11[2] = {tl1[2], tl1[3]};
                mma_f16(s[4*fp],   qh[ks], bl00, s[4*fp]);
                mma_f16(s[4*fp+1], qh[ks], bl01, s[4*fp+1]);
                mma_f16(s[4*fp+2], qh[ks], bl10, s[4*fp+2]);
                mma_f16(s[4*fp+3], qh[ks], bl11, s[4*fp+3]);
                mma_f16(s[4*fp],   qh[ks], bh00, s[4*fp]);
                mma_f16(s[4*fp+1], qh[ks], bh01, s[4*fp+1]);
                mma_f16(s[4*fp+2], qh[ks], bh10, s[4*fp+2]);
                mma_f16(s[4*fp+3], qh[ks], bh11, s[4*fp+3]);
            }
        }

        float mx0 = -1e30f, mx1 = -1e30f;
#pragma unroll
        for (int f = 0; f < 16; f++) {
            mx0 = fmaxf(mx0, fmaxf(s[f][0], s[f][1]));
            mx1 = fmaxf(mx1, fmaxf(s[f][2], s[f][3]));
        }
        mx0 = fmaxf(mx0, __shfl_xor_sync(0xffffffffu, mx0, 1));
        mx0 = fmaxf(mx0, __shfl_xor_sync(0xffffffffu, mx0, 2));
        mx1 = fmaxf(mx1, __shfl_xor_sync(0xffffffffu, mx1, 1));
        mx1 = fmaxf(mx1, __shfl_xor_sync(0xffffffffu, mx1, 2));
        const float mn0 = fmaxf(m0r, mx0), mn1 = fmaxf(m1r, mx1);
        const float cr0 = __expf(m0r - mn0), cr1 = __expf(m1r - mn1);
        m0r = mn0; m1r = mn1;

        float rs0 = 0.f, rs1 = 0.f;
#pragma unroll
        for (int f = 0; f < 16; f++) {
            s[f][0] = __expf(s[f][0] - mn0);
            s[f][1] = __expf(s[f][1] - mn0);
            s[f][2] = __expf(s[f][2] - mn1);
            s[f][3] = __expf(s[f][3] - mn1);
            rs0 += s[f][0] + s[f][1];
            rs1 += s[f][2] + s[f][3];
        }
        rs0 += __shfl_xor_sync(0xffffffffu, rs0, 1);
        rs0 += __shfl_xor_sync(0xffffffffu, rs0, 2);
        rs1 += __shfl_xor_sync(0xffffffffu, rs1, 1);
        rs1 += __shfl_xor_sync(0xffffffffu, rs1, 2);
        l0 = l0 * cr0 + rs0;
        l1 = l1 * cr1 + rs1;
#pragma unroll
        for (int fn = 0; fn < 8; fn++) {
            o[fn][0] *= cr0; o[fn][1] *= cr0;
            o[fn][2] *= cr1; o[fn][3] *= cr1;
        }

#pragma unroll
        for (int ks = 0; ks < 8; ks++) {
            uint32_t pa[4];
            pa[0] = pack_h2(s[2*ks][0],   s[2*ks][1]);
            pa[1] = pack_h2(s[2*ks][2],   s[2*ks][3]);
            pa[2] = pack_h2(s[2*ks+1][0], s[2*ks+1][1]);
            pa[3] = pack_h2(s[2*ks+1][2], s[2*ks+1][3]);
            const int k0 = 16 * ks;
#pragma unroll
            for (int fp = 0; fp < 4; fp++) {
                uint32_t t[4];
                ldmx4t(t, &Vb[(k0 + vt_row) * FA_LD + fp * 16 + vt_col]);
                uint32_t b0[2] = {t[0], t[1]}, b1[2] = {t[2], t[3]};
                mma_f16(o[2*fp],   pa, b0, o[2*fp]);
                mma_f16(o[2*fp+1], pa, b1, o[2*fp+1]);
            }
        }
    }

    const float inv0 = 1.f / l0, inv1 = 1.f / l1;
    const int r0 = qt * 256 + w * 16 + gq;
    float* Ob0 = outb + ((size_t)(b * SEQ + r0)) * EMBED + h * HDIM;
    float* Ob1 = Ob0 + 8 * (size_t)EMBED;
#pragma unroll
    for (int fn = 0; fn < 8; fn++) {
        const int c = fn * 8 + 2 * tq;
        float2 t0; t0.x = o[fn][0] * inv0; t0.y = o[fn][1] * inv0;
        float2 t1; t1.x = o[fn][2] * inv1; t1.y = o[fn][3] * inv1;
        *(float2*)(Ob0 + c) = t0;
        *(float2*)(Ob1 + c) = t1;
    }
}

// ---------------- host launch ----------------
extern "C" void kernel_launch(void* const* d_in, const int* in_sizes, int n_in,
                              void* d_out, int out_size)
{
    (void)in_sizes; (void)n_in; (void)out_size;
    const float* query = (const float*)d_in[0];
    const float* key   = (const float*)d_in[1];
    const float* value = (const float*)d_in[2];
    const float* Wq    = (const float*)d_in[3];
    const float* Wk    = (const float*)d_in[4];
    const float* Wv    = (const float*)d_in[5];
    const float* Wo    = (const float*)d_in[6];
    float* out = (float*)d_out;

    float *Mcat, *q, *at;
    __half *Wo2h, *Wo2l, *Wvh, *Wvl, *Woh, *Wol, *kh, *kl, *vh;
    cudaGetSymbolAddress((void**)&Mcat, g_Mcat);
    cudaGetSymbolAddress((void**)&q,    g_q);
    cudaGetSymbolAddress((void**)&at,   g_at);
    cudaGetSymbolAddress((void**)&Wo2h, g_Wo2h);
    cudaGetSymbolAddress((void**)&Wo2l, g_Wo2l);
    cudaGetSymbolAddress((void**)&Wvh,  g_Wvh);
    cudaGetSymbolAddress((void**)&Wvl,  g_Wvl);
    cudaGetSymbolAddress((void**)&Woh,  g_Woh);
    cudaGetSymbolAddress((void**)&Wol,  g_Wol);
    cudaGetSymbolAddress((void**)&kh,   g_kh);
    cudaGetSymbolAddress((void**)&kl,   g_kl);
    cudaGetSymbolAddress((void**)&vh,   g_vh);

    split_planes<<<EE/256, 256>>>(Wv, Wvh, Wvl);
    split_planes<<<EE/256, 256>>>(Wo, Woh, Wol);

    // 1: Mcat[0]=Wk^T Wk ; Mcat[1]=Wq^T Wq   (A hi-only, B split: 2 MMAs)
    {
        auto kfn = gemm_f16s<128,128,64,32,32,true,false,false,false,false,0>;
        int sm = (128*64 + 128*64)*4 + (1*128 + 2*128)*72*2;   // 120832
        cudaFuncSetAttribute(kfn, cudaFuncAttributeMaxDynamicSharedMemorySize, sm);
        dim3 grid(8, 8, 2);
        kfn<<<grid, 512, sm>>>(
            Wk, Wq, nullptr,  Wk, Wq, nullptr,  nullptr, nullptr, nullptr,
            nullptr, nullptr, nullptr,
            Mcat, Mcat + EE, nullptr,
            nullptr, nullptr, nullptr, 0,
            EMBED, EMBED, EMBED, EMBED, EMBED, EMBED, 1.f, 0.f);
    }
    // 2: Wo2[z] = W[z] - W[z]@Mcat[z]  -> fp16 planes  (full split)
    {
        auto kfn = gemm_f16s<128,128,64,32,32,false,false,true,true,false,1>;
        int sm = (128*64 + 128*64)*4 + (2*128 + 2*128)*72*2;   // 139264
        cudaFuncSetAttribute(kfn, cudaFuncAttributeMaxDynamicSharedMemorySize, sm);
        dim3 grid(8, 8, 2);
        kfn<<<grid, 512, sm>>>(
            Wq, Wk, nullptr,  Mcat, Mcat + EE, nullptr,  nullptr, nullptr, nullptr,
            Wq, Wk, nullptr,
            nullptr, nullptr, nullptr,
            Wo2h, Wo2l, nullptr, (long long)EE,
            EMBED, EMBED, EMBED, EMBED, EMBED, EMBED, -1.f, 1.f);
    }
    // 3: projections: z0 q fp32, z1 k planes, z2 v hi plane
    {
        auto kfn = gemm_f16s<128,128,64,32,32,false,true,false,false,true,2>;
        int sm = 128*64*4 + 1*128*72*2 + 4*128*72*2;           // 124928
        cudaFuncSetAttribute(kfn, cudaFuncAttributeMaxDynamicSharedMemorySize, sm);
        dim3 grid(8, 32, 3);
        kfn<<<grid, 512, sm>>>(
            query, key, value,
            Wo2h, Wo2h + EE, Wvh,  Wo2l, Wo2l + EE, Wvl,
            nullptr, nullptr, nullptr,
            q, nullptr, nullptr,
            kh, kl, vh, 0,
            ROWSM, EMBED, EMBED, EMBED, EMBED, EMBED, 1.f, 0.f);
    }
    // 4: flash attention (512 threads, BQ=256)
    {
        cudaFuncSetAttribute(flash_attn, cudaFuncAttributeMaxDynamicSharedMemorySize, FA_SMEM);
        dim3 grid(BATCH * HEADS, SEQ / 256);
        flash_attn<<<grid, 512, FA_SMEM>>>(q, kh, kl, vh, at);
    }
    // 5: out = at @ Wo^T  (A hi-only, B pre-split)
    {
        auto kfn = gemm_f16s<128,128,64,32,32,false,true,false,false,true,0>;
        int sm = 128*64*4 + 1*128*72*2 + 4*128*72*2;           // 124928
        cudaFuncSetAttribute(kfn, cudaFuncAttributeMaxDynamicSharedMemorySize, sm);
        dim3 grid(8, 32, 1);
        kfn<<<grid, 512, sm>>>(
            at, nullptr, nullptr,
            Woh, nullptr, nullptr,  Wol, nullptr, nullptr,
            nullptr, nullptr, nullptr,
            out, nullptr, nullptr,
            nullptr, nullptr, nullptr, 0,
            ROWSM, EMBED, EMBED, EMBED, EMBED, EMBED, 1.f, 0.f);
    }
}

// round 15
// speedup vs baseline: 1.5421x; 1.1025x over previous
#include <cuda_runtime.h>
#include <cuda_fp16.h>
#include <cstdint>

#define EMBED 1024
#define HEADS 16
#define HDIM  64
#define BATCH 2
#define SEQ   2048
#define ROWSM (BATCH*SEQ)   // 4096
#define EE    (EMBED*EMBED)
#define RME   (ROWSM*EMBED)

// ---------------- scratch (__device__ globals; no allocation allowed) ----------------
__device__ float  g_Mcat[2*EE];    // [Wk^T Wk, Wq^T Wq]
__device__ float  g_q   [RME];     // q projected (fp32)
__device__ float  g_at  [RME];     // attention output
__device__ __half g_Wo2h[2*EE], g_Wo2l[2*EE];  // [Wqo, Wko] planes
__device__ __half g_Wvh [EE],   g_Wvl [EE];    // Wv planes
__device__ __half g_Woh [EE],   g_Wol [EE];    // Wo planes
__device__ __half g_kh  [RME];                 // k hi plane [b*S+s][E]
__device__ __half g_vh  [RME];                 // v hi plane [b*S+s][E]

// ---------------- helpers ----------------
__device__ __forceinline__ void split_f16(float f, __half& hi, __half& lo) {
    hi = __float2half_rn(f);
    lo = __float2half_rn(f - __half2float(hi));
}
__device__ __forceinline__ void split2(float a, float b, uint32_t& hi, uint32_t& lo) {
    __half2 h = __floats2half2_rn(a, b);
    float2 hf = __half22float2(h);
    __half2 l = __floats2half2_rn(a - hf.x, b - hf.y);
    hi = *reinterpret_cast<uint32_t*>(&h);
    lo = *reinterpret_cast<uint32_t*>(&l);
}
__device__ __forceinline__ uint32_t pack_h2(float a, float b) {
    __half2 h = __floats2half2_rn(a, b);
    return *reinterpret_cast<uint32_t*>(&h);
}
__device__ __forceinline__ void mma_f16(float (&d)[4], const uint32_t (&a)[4],
                                        const uint32_t (&b)[2], const float (&c)[4]) {
    asm volatile(
        "mma.sync.aligned.m16n8k16.row.col.f32.f16.f16.f32 "
        "{%0,%1,%2,%3},{%4,%5,%6,%7},{%8,%9},{%10,%11,%12,%13};\n"
        : "=f"(d[0]), "=f"(d[1]), "=f"(d[2]), "=f"(d[3])
        : "r"(a[0]), "r"(a[1]), "r"(a[2]), "r"(a[3]),
          "r"(b[0]), "r"(b[1]),
          "f"(c[0]), "f"(c[1]), "f"(c[2]), "f"(c[3]));
}
__device__ __forceinline__ uint32_t sptr(const void* p) {
    return (uint32_t)__cvta_generic_to_shared(p);
}
__device__ __forceinline__ void ldmx4(uint32_t* r, const __half* p) {
    asm volatile("ldmatrix.sync.aligned.m8n8.x4.shared.b16 {%0,%1,%2,%3}, [%4];"
        : "=r"(r[0]), "=r"(r[1]), "=r"(r[2]), "=r"(r[3]) : "r"(sptr(p)));
}
__device__ __forceinline__ void ldmx4t(uint32_t* r, const __half* p) {
    asm volatile("ldmatrix.sync.aligned.m8n8.x4.trans.shared.b16 {%0,%1,%2,%3}, [%4];"
        : "=r"(r[0]), "=r"(r[1]), "=r"(r[2]), "=r"(r[3]) : "r"(sptr(p)));
}
__device__ __forceinline__ void cp16(void* s, const void* g) {
    asm volatile("cp.async.cg.shared.global [%0], [%1], 16;" :: "r"(sptr(s)), "l"(g));
}
__device__ __forceinline__ void cp_commit() { asm volatile("cp.async.commit_group;"); }
template<int N> __device__ __forceinline__ void cp_wait() {
    asm volatile("cp.async.wait_group %0;" :: "n"(N));
}

// ---------------- weight pre-split kernel ----------------
__global__ void __launch_bounds__(256) split_planes(const float* __restrict__ w,
                                                    __half* __restrict__ hi,
                                                    __half* __restrict__ lo) {
    int i = blockIdx.x * 256 + threadIdx.x;
    __half h, l; split_f16(w[i], h, l);
    hi[i] = h; lo[i] = l;
}

// ---------------- generic batched split-fp16 GEMM (R12 winning config) ----------------
// z selects pointer set. C = alpha*opA(A)*opB(B) [+ beta*Cin]
// BPRE: B pre-split planes [n][k], cp'd direct, double-buffered. Else fp32 staged.
// EPI: 0 = fp32 C; 1 = planes Hh/Hl (+z*sH); 2 = qkv (z0: fp32 C0; z1: hi->Hh; z2: hi->Ht)
template<int BM,int BN,int BK,int WM,int WN,bool TA,bool TB,bool HASC,bool SPLITA,bool BPRE,int EPI>
__global__ void __launch_bounds__((BM/WM)*(BN/WN)*32)
gemm_f16s(const float* A0, const float* A1, const float* A2,
          const void* Bv0, const void* Bv1, const void* Bv2,
          const __half* Bl0, const __half* Bl1, const __half* Bl2,
          const float* Ci0, const float* Ci1, const float* Ci2,
          float* C0, float* C1, float* C2,
          __half* Hh, __half* Hl, __half* Ht, long long sH,
          int M, int N, int K, int lda, int ldb, int ldc,
          float alpha, float beta)
{
    constexpr int WARPS_N = BN / WN;
    constexpr int WARPS_M = BM / WM;
    constexpr int NTH = WARPS_M * WARPS_N * 32;
    constexpr int MFRAG = WM / 16, NFRAG = WN / 8, KSTEPS = BK / 16;
    constexpr int LDK = BK + 8;
    constexpr int EA = BM * BK / NTH, EB = BN * BK / NTH;
    constexpr int CA = BM * BK / 4 / NTH, CB = BN * BK / 4 / NTH;
    constexpr int CBH = (BN * (BK / 8)) / NTH;
    constexpr int APL = SPLITA ? 2 : 1;

    extern __shared__ char smraw[];
    float*  Ast = (float*)smraw;
    float*  Bst = nullptr;
    __half* As;
    __half* Bs;
    if constexpr (BPRE) {
        As = (__half*)(Ast + BM * BK);
        Bs = As + APL * BM * LDK;          // [2 buf][2 plane][BN*LDK]
    } else {
        Bst = Ast + BM * BK;
        As = (__half*)(Bst + BN * BK);
        Bs = As + APL * BM * LDK;          // [2 plane][BN*LDK]
    }

    const int z = blockIdx.z;
    const float* A = (z == 0) ? A0 : ((z == 1) ? A1 : A2);
    const void*  Bv = (z == 0) ? Bv0 : ((z == 1) ? Bv1 : Bv2);
    const __half* Bl = (z == 0) ? Bl0 : ((z == 1) ? Bl1 : Bl2);
    const float* Cin = (z == 0) ? Ci0 : ((z == 1) ? Ci1 : Ci2);
    float*       C = (z == 0) ? C0 : ((z == 1) ? C1 : C2);

    const int mbase = blockIdx.y * BM;
    const int nbase = blockIdx.x * BN;
    const int tid  = threadIdx.x;
    const int warp = tid >> 5, lane = tid & 31;
    const int wm = warp / WARPS_N, wn = warp % WARPS_N;
    const int gq = lane >> 2, tq = lane & 3;

    float acc[MFRAG][NFRAG][4];
#pragma unroll
    for (int i = 0; i < MFRAG; i++)
#pragma unroll
        for (int j = 0; j < NFRAG; j++)
#pragma unroll
            for (int r = 0; r < 4; r++) acc[i][j][r] = 0.f;

    auto cpA = [&](int kb) {
#pragma unroll
        for (int i = 0; i < CA; i++) {
            int e = i * NTH + tid;
            if (TA) { int k = e / (BM/4), mc = e % (BM/4);
                cp16(Ast + k * BM + 4 * mc, A + (size_t)(kb + k) * lda + mbase + 4 * mc); }
            else    { int m = e / (BK/4), kc = e % (BK/4);
                cp16(Ast + m * BK + 4 * kc, A + (size_t)(mbase + m) * lda + kb + 4 * kc); }
        }
    };
    auto cpB = [&](int kb, int buf) {
        if constexpr (BPRE) {
            const __half* Bh = (const __half*)Bv;
#pragma unroll
            for (int i = 0; i < CBH; i++) {
                int e = i * NTH + tid;
                int n = e / (BK/8), k8 = e % (BK/8);
                cp16(Bs + (buf*2 + 0) * BN * LDK + n * LDK + k8 * 8,
                     Bh + (size_t)(nbase + n) * ldb + kb + k8 * 8);
                cp16(Bs + (buf*2 + 1) * BN * LDK + n * LDK + k8 * 8,
                     Bl + (size_t)(nbase + n) * ldb + kb + k8 * 8);
            }
        } else {
            const float* Bf = (const float*)Bv;
#pragma unroll
            for (int i = 0; i < CB; i++) {
                int e = i * NTH + tid;
                if (TB) { int n = e / (BK/4), kc = e % (BK/4);
                    cp16(Bst + n * BK + 4 * kc, Bf + (size_t)(nbase + n) * ldb + kb + 4 * kc); }
                else    { int k = e / (BN/4), nc = e % (BN/4);
                    cp16(Bst + k * BN + 4 * nc, Bf + (size_t)(kb + k) * ldb + nbase + 4 * nc); }
            }
        }
    };
    auto convert = [&]() {
#pragma unroll
        for (int i = 0; i < EA; i++) {
            int e = i * NTH + tid; int m, k;
            if (TA) { k = e / BM; m = e % BM; } else { m = e / BK; k = e % BK; }
            float f = Ast[e];
            if (SPLITA) {
                __half h, l; split_f16(f, h, l);
                As[m * LDK + k] = h;
                As[BM * LDK + m * LDK + k] = l;
            } else {
                As[m * LDK + k] = __float2half_rn(f);
            }
        }
        if constexpr (!BPRE) {
#pragma unroll
            for (int i = 0; i < EB; i++) {
                int e = i * NTH + tid; int n, k;
                if (TB) { n = e / BK; k = e % BK; } else { k = e / BN; n = e % BN; }
                float f = Bst[e];
                __half h, l; split_f16(f, h, l);
                Bs[n * LDK + k] = h;
                Bs[BN * LDK + n * LDK + k] = l;
            }
        }
    };

    cpA(0); cpB(0, 0); cp_commit();
    cp_wait<0>(); __syncthreads();
    convert(); __syncthreads();
    if (BK < K) { cpA(BK); cpB(BK, 1); cp_commit(); }

    const int a_row = (lane & 15);
    const int a_kof = (lane >> 4) << 3;
    const int b_row = (lane & 7) + (((lane >> 4) & 1) << 3);
    const int b_kof = ((lane >> 3) & 1) << 3;

    for (int kb = 0; kb < K; kb += BK) {
        const int ibuf = BPRE ? ((kb / BK) & 1) : 0;
        const __half* Bsh = Bs + (BPRE ? (ibuf*2 + 0) * BN * LDK : 0);
        const __half* Bsl = Bs + (BPRE ? (ibuf*2 + 1) * BN * LDK : BN * LDK);
#pragma unroll
        for (int ks = 0; ks < KSTEPS; ks++) {
            const int k0 = ks * 16;
            uint32_t ah[MFRAG][4], al[MFRAG][4];
            uint32_t bh[NFRAG][2], bl[NFRAG][2];
#pragma unroll
            for (int fm = 0; fm < MFRAG; fm++) {
                const int mr = wm * WM + fm * 16 + a_row;
                ldmx4(ah[fm], &As[mr * LDK + k0 + a_kof]);
                if (SPLITA)
                    ldmx4(al[fm], &As[BM * LDK + mr * LDK + k0 + a_kof]);
            }
#pragma unroll
            for (int fp = 0; fp < NFRAG / 2; fp++) {
                const int nr = wn * WN + fp * 16 + b_row;
                uint32_t t[4];
                ldmx4(t, &Bsh[nr * LDK + k0 + b_kof]);
                bh[2*fp][0] = t[0]; bh[2*fp][1] = t[1];
                bh[2*fp+1][0] = t[2]; bh[2*fp+1][1] = t[3];
                ldmx4(t, &Bsl[nr * LDK + k0 + b_kof]);
                bl[2*fp][0] = t[0]; bl[2*fp][1] = t[1];
                bl[2*fp+1][0] = t[2]; bl[2*fp+1][1] = t[3];
            }
            if (SPLITA) {
#pragma unroll
                for (int fm = 0; fm < MFRAG; fm++)
#pragma unroll
                    for (int fn = 0; fn < NFRAG; fn++)
                        mma_f16(acc[fm][fn], al[fm], bh[fn], acc[fm][fn]);
            }
#pragma unroll
            for (int fm = 0; fm < MFRAG; fm++)
#pragma unroll
                for (int fn = 0; fn < NFRAG; fn++)
                    mma_f16(acc[fm][fn], ah[fm], bl[fn], acc[fm][fn]);
#pragma unroll
            for (int fm = 0; fm < MFRAG; fm++)
#pragma unroll
                for (int fn = 0; fn < NFRAG; fn++)
                    mma_f16(acc[fm][fn], ah[fm], bh[fn], acc[fm][fn]);
        }
        if (kb + BK < K) {
            cp_wait<0>(); __syncthreads();
            convert(); __syncthreads();
            if (kb + 2 * BK < K) { cpA(kb + 2*BK); cpB(kb + 2*BK, ibuf); cp_commit(); }
        }
    }

#pragma unroll
    for (int fm = 0; fm < MFRAG; fm++) {
        const int m0 = mbase + wm * WM + fm * 16 + gq;
#pragma unroll
        for (int fn = 0; fn < NFRAG; fn++) {
            const int n0 = nbase + wn * WN + fn * 8 + tq * 2;
            float v0 = alpha * acc[fm][fn][0], v1 = alpha * acc[fm][fn][1];
            float v2 = alpha * acc[fm][fn][2], v3 = alpha * acc[fm][fn][3];
            if (HASC) {
                const float* ci0 = Cin + (size_t)m0 * ldc + n0;
                const float* ci1 = Cin + (size_t)(m0 + 8) * ldc + n0;
                v0 += beta * ci0[0]; v1 += beta * ci0[1];
                v2 += beta * ci1[0]; v3 += beta * ci1[1];
            }
            if (EPI == 1) {
                __half* hh = Hh + z * sH;
                __half* hl = Hl + z * sH;
                uint32_t h01, l01, h23, l23;
                split2(v0, v1, h01, l01);
                split2(v2, v3, h23, l23);
                *(uint32_t*)&hh[(size_t)m0 * ldc + n0] = h01;
                *(uint32_t*)&hl[(size_t)m0 * ldc + n0] = l01;
                *(uint32_t*)&hh[(size_t)(m0 + 8) * ldc + n0] = h23;
                *(uint32_t*)&hl[(size_t)(m0 + 8) * ldc + n0] = l23;
            } else if (EPI == 2 && z == 1) {
                *(uint32_t*)&Hh[(size_t)m0 * ldc + n0] = pack_h2(v0, v1);
                *(uint32_t*)&Hh[(size_t)(m0 + 8) * ldc + n0] = pack_h2(v2, v3);
            } else if (EPI == 2 && z == 2) {
                *(uint32_t*)&Ht[(size_t)m0 * ldc + n0] = pack_h2(v0, v1);
                *(uint32_t*)&Ht[(size_t)(m0 + 8) * ldc + n0] = pack_h2(v2, v3);
            } else {
                float* c0 = C + (size_t)m0 * ldc + n0;
                float* c1 = C + (size_t)(m0 + 8) * ldc + n0;
                c0[0] = v0; c0[1] = v1;
                c1[0] = v2; c1[1] = v3;
            }
        }
    }
}

// ---------------- fused flash attention: 512 threads, BQ=256, single-plane K ----------------
#define FA_LD  72
#define FA_PL  (128*FA_LD)
#define FA_NT  (SEQ/128)
#define FA_SMEM (6*FA_PL*2)   // 3 bufs x 2 planes (K, V) x 128x72 halves

__global__ void __launch_bounds__(512)
flash_attn(const float* __restrict__ qf,
           const __half* __restrict__ khi,
           const __half* __restrict__ vhi, float* __restrict__ outb)
{
    extern __shared__ __half sm[];

    const int hh = blockIdx.x;
    const int b = hh >> 4, h = hh & 15;
    const int qt = blockIdx.y;            // 0..7 (256 q rows per block)

    const int tid = threadIdx.x;
    const int w = tid >> 5, lane = tid & 31;   // 16 warps
    const int gq = lane >> 2, tq = lane & 3;
    const int b_row = (lane & 7) + (((lane >> 4) & 1) << 3);
    const int b_kof = ((lane >> 3) & 1) << 3;
    const int vt_row = ((lane >> 3) & 1) * 8 + (lane & 7);
    const int vt_col = ((lane >> 4) & 1) * 8;

    const __half* Kh = khi + ((size_t)b * SEQ) * EMBED + h * HDIM;
    const __half* Vh = vhi + ((size_t)b * SEQ) * EMBED + h * HDIM;

    auto cpKV = [&](int j) {
        __half* dst = sm + (j % 3) * 2 * FA_PL;
        const __half* sh = Kh + (size_t)(j * 128) * EMBED;
        const __half* sv = Vh + (size_t)(j * 128) * EMBED;
#pragma unroll
        for (int i = 0; i < 2; i++) {
            int c = i * 512 + tid;
            int row = c >> 3, c8 = c & 7;
            cp16(dst +          row * FA_LD + c8 * 8, sh + (size_t)row * EMBED + c8 * 8);
            cp16(dst + FA_PL +  row * FA_LD + c8 * 8, sv + (size_t)row * EMBED + c8 * 8);
        }
        cp_commit();
    };

    // ---- Q fragments: hi-only (pre-scaled) ----
    uint32_t qh[4][4];
    {
        const float* Qb = qf + ((size_t)b * SEQ) * EMBED + h * HDIM;
        const int r0 = qt * 256 + w * 16 + gq;
        const float* Qr0 = Qb + (size_t)r0 * EMBED;
        const float* Qr1 = Qr0 + 8 * (size_t)EMBED;
#pragma unroll
        for (int ks = 0; ks < 4; ks++) {
            const int c = 16 * ks + 2 * tq;
            float2 x0 = *(const float2*)(Qr0 + c);
            float2 x1 = *(const float2*)(Qr1 + c);
            float2 x2 = *(const float2*)(Qr0 + c + 8);
            float2 x3 = *(const float2*)(Qr1 + c + 8);
            qh[ks][0] = pack_h2(x0.x * 0.125f, x0.y * 0.125f);
            qh[ks][1] = pack_h2(x1.x * 0.125f, x1.y * 0.125f);
            qh[ks][2] = pack_h2(x2.x * 0.125f, x2.y * 0.125f);
            qh[ks][3] = pack_h2(x3.x * 0.125f, x3.y * 0.125f);
        }
    }

    float o[8][4];
#pragma unroll
    for (int i = 0; i < 8; i++)
#pragma unroll
        for (int r = 0; r < 4; r++) o[i][r] = 0.f;
    float m0r = -1e30f, m1r = -1e30f, l0 = 0.f, l1 = 0.f;

    cpKV(0);
    cpKV(1);

    for (int j = 0; j < FA_NT; j++) {
        if (j + 1 < FA_NT) cp_wait<1>(); else cp_wait<0>();
        __syncthreads();
        if (j + 2 < FA_NT) cpKV(j + 2);

        const __half* Kb = sm + (j % 3) * 2 * FA_PL;
        const __half* Vb = Kb + FA_PL;

        // ---- S = Q_hi K_hi^T : single plane, 4 independent MMAs per step ----
        float s[16][4];
#pragma unroll
        for (int f = 0; f < 16; f++)
#pragma unroll
            for (int r = 0; r < 4; r++) s[f][r] = 0.f;
#pragma unroll
        for (int ks = 0; ks < 4; ks++) {
            const int k0 = 16 * ks;
#pragma unroll
            for (int fp = 0; fp < 4; fp++) {
                const int nr0 = (2*fp)     * 16 + b_row;
                const int nr1 = (2*fp + 1) * 16 + b_row;
                uint32_t th0[4], th1[4];
                ldmx4(th0, &Kb[nr0 * FA_LD + k0 + b_kof]);
                ldmx4(th1, &Kb[nr1 * FA_LD + k0 + b_kof]);
                uint32_t bh00[2] = {th0[0], th0[1]}, bh01[2] = {th0[2], th0[3]};
                uint32_t bh10[2] = {th1[0], th1[1]}, bh11[2] = {th1[2], th1[3]};
                mma_f16(s[4*fp],   qh[ks], bh00, s[4*fp]);
                mma_f16(s[4*fp+1], qh[ks], bh01, s[4*fp+1]);
                mma_f16(s[4*fp+2], qh[ks], bh10, s[4*fp+2]);
                mma_f16(s[4*fp+3], qh[ks], bh11, s[4*fp+3]);
            }
        }

        float mx0 = -1e30f, mx1 = -1e30f;
#pragma unroll
        for (int f = 0; f < 16; f++) {
            mx0 = fmaxf(mx0, fmaxf(s[f][0], s[f][1]));
            mx1 = fmaxf(mx1, fmaxf(s[f][2], s[f][3]));
        }
        mx0 = fmaxf(mx0, __shfl_xor_sync(0xffffffffu, mx0, 1));
        mx0 = fmaxf(mx0, __shfl_xor_sync(0xffffffffu, mx0, 2));
        mx1 = fmaxf(mx1, __shfl_xor_sync(0xffffffffu, mx1, 1));
        mx1 = fmaxf(mx1, __shfl_xor_sync(0xffffffffu, mx1, 2));
        const float mn0 = fmaxf(m0r, mx0), mn1 = fmaxf(m1r, mx1);
        const float cr0 = __expf(m0r - mn0), cr1 = __expf(m1r - mn1);
        m0r = mn0; m1r = mn1;

        float rs0 = 0.f, rs1 = 0.f;
#pragma unroll
        for (int f = 0; f < 16; f++) {
            s[f][0] = __expf(s[f][0] - mn0);
            s[f][1] = __expf(s[f][1] - mn0);
            s[f][2] = __expf(s[f][2] - mn1);
            s[f][3] = __expf(s[f][3] - mn1);
            rs0 += s[f][0] + s[f][1];
            rs1 += s[f][2] + s[f][3];
        }
        rs0 += __shfl_xor_sync(0xffffffffu, rs0, 1);
        rs0 += __shfl_xor_sync(0xffffffffu, rs0, 2);
        rs1 += __shfl_xor_sync(0xffffffffu, rs1, 1);
        rs1 += __shfl_xor_sync(0xffffffffu, rs1, 2);
        l0 = l0 * cr0 + rs0;
        l1 = l1 * cr1 + rs1;
#pragma unroll
        for (int fn = 0; fn < 8; fn++) {
            o[fn][0] *= cr0; o[fn][1] *= cr0;
            o[fn][2] *= cr1; o[fn][3] *= cr1;
        }

#pragma unroll
        for (int ks = 0; ks < 8; ks++) {
            uint32_t pa[4];
            pa[0] = pack_h2(s[2*ks][0],   s[2*ks][1]);
            pa[1] = pack_h2(s[2*ks][2],   s[2*ks][3]);
            pa[2] = pack_h2(s[2*ks+1][0], s[2*ks+1][1]);
            pa[3] = pack_h2(s[2*ks+1][2], s[2*ks+1][3]);
            const int k0 = 16 * ks;
#pragma unroll
            for (int fp = 0; fp < 4; fp++) {
                uint32_t t[4];
                ldmx4t(t, &Vb[(k0 + vt_row) * FA_LD + fp * 16 + vt_col]);
                uint32_t b0[2] = {t[0], t[1]}, b1[2] = {t[2], t[3]};
                mma_f16(o[2*fp],   pa, b0, o[2*fp]);
                mma_f16(o[2*fp+1], pa, b1, o[2*fp+1]);
            }
        }
    }

    const float inv0 = 1.f / l0, inv1 = 1.f / l1;
    const int r0 = qt * 256 + w * 16 + gq;
    float* Ob0 = outb + ((size_t)(b * SEQ + r0)) * EMBED + h * HDIM;
    float* Ob1 = Ob0 + 8 * (size_t)EMBED;
#pragma unroll
    for (int fn = 0; fn < 8; fn++) {
        const int c = fn * 8 + 2 * tq;
        float2 t0; t0.x = o[fn][0] * inv0; t0.y = o[fn][1] * inv0;
        float2 t1; t1.x = o[fn][2] * inv1; t1.y = o[fn][3] * inv1;
        *(float2*)(Ob0 + c) = t0;
        *(float2*)(Ob1 + c) = t1;
    }
}

// ---------------- host launch ----------------
extern "C" void kernel_launch(void* const* d_in, const int* in_sizes, int n_in,
                              void* d_out, int out_size)
{
    (void)in_sizes; (void)n_in; (void)out_size;
    const float* query = (const float*)d_in[0];
    const float* key   = (const float*)d_in[1];
    const float* value = (const float*)d_in[2];
    const float* Wq    = (const float*)d_in[3];
    const float* Wk    = (const float*)d_in[4];
    const float* Wv    = (const float*)d_in[5];
    const float* Wo    = (const float*)d_in[6];
    float* out = (float*)d_out;

    float *Mcat, *q, *at;
    __half *Wo2h, *Wo2l, *Wvh, *Wvl, *Woh, *Wol, *kh, *vh;
    cudaGetSymbolAddress((void**)&Mcat, g_Mcat);
    cudaGetSymbolAddress((void**)&q,    g_q);
    cudaGetSymbolAddress((void**)&at,   g_at);
    cudaGetSymbolAddress((void**)&Wo2h, g_Wo2h);
    cudaGetSymbolAddress((void**)&Wo2l, g_Wo2l);
    cudaGetSymbolAddress((void**)&Wvh,  g_Wvh);
    cudaGetSymbolAddress((void**)&Wvl,  g_Wvl);
    cudaGetSymbolAddress((void**)&Woh,  g_Woh);
    cudaGetSymbolAddress((void**)&Wol,  g_Wol);
    cudaGetSymbolAddress((void**)&kh,   g_kh);
    cudaGetSymbolAddress((void**)&vh,   g_vh);

    split_planes<<<EE/256, 256>>>(Wv, Wvh, Wvl);
    split_planes<<<EE/256, 256>>>(Wo, Woh, Wol);

    // 1: Mcat[0]=Wk^T Wk ; Mcat[1]=Wq^T Wq   (A hi-only, B split: 2 MMAs)
    {
        auto kfn = gemm_f16s<128,128,64,32,32,true,false,false,false,false,0>;
        int sm = (128*64 + 128*64)*4 + (1*128 + 2*128)*72*2;   // 120832
        cudaFuncSetAttribute(kfn, cudaFuncAttributeMaxDynamicSharedMemorySize, sm);
        dim3 grid(8, 8, 2);
        kfn<<<grid, 512, sm>>>(
            Wk, Wq, nullptr,  Wk, Wq, nullptr,  nullptr, nullptr, nullptr,
            nullptr, nullptr, nullptr,
            Mcat, Mcat + EE, nullptr,
            nullptr, nullptr, nullptr, 0,
            EMBED, EMBED, EMBED, EMBED, EMBED, EMBED, 1.f, 0.f);
    }
    // 2: Wo2[z] = W[z] - W[z]@Mcat[z]  -> fp16 planes  (full split)
    {
        auto kfn = gemm_f16s<128,128,64,32,32,false,false,true,true,false,1>;
        int sm = (128*64 + 128*64)*4 + (2*128 + 2*128)*72*2;   // 139264
        cudaFuncSetAttribute(kfn, cudaFuncAttributeMaxDynamicSharedMemorySize, sm);
        dim3 grid(8, 8, 2);
        kfn<<<grid, 512, sm>>>(
            Wq, Wk, nullptr,  Mcat, Mcat + EE, nullptr,  nullptr, nullptr, nullptr,
            Wq, Wk, nullptr,
            nullptr, nullptr, nullptr,
            Wo2h, Wo2l, nullptr, (long long)EE,
            EMBED, EMBED, EMBED, EMBED, EMBED, EMBED, -1.f, 1.f);
    }
    // 3: projections: z0 q fp32, z1 k hi plane, z2 v hi plane
    {
        auto kfn = gemm_f16s<128,128,64,32,32,false,true,false,false,true,2>;
        int sm = 128*64*4 + 1*128*72*2 + 4*128*72*2;           // 124928
        cudaFuncSetAttribute(kfn, cudaFuncAttributeMaxDynamicSharedMemorySize, sm);
        dim3 grid(8, 32, 3);
        kfn<<<grid, 512, sm>>>(
            query, key, value,
            Wo2h, Wo2h + EE, Wvh,  Wo2l, Wo2l + EE, Wvl,
            nullptr, nullptr, nullptr,
            q, nullptr, nullptr,
            kh, nullptr, vh, 0,
            ROWSM, EMBED, EMBED, EMBED, EMBED, EMBED, 1.f, 0.f);
    }
    // 4: flash attention (512 threads, BQ=256, single-plane K)
    {
        cudaFuncSetAttribute(flash_attn, cudaFuncAttributeMaxDynamicSharedMemorySize, FA_SMEM);
        dim3 grid(BATCH * HEADS, SEQ / 256);
        flash_attn<<<grid, 512, FA_SMEM>>>(q, kh, vh, at);
    }
    // 5: out = at @ Wo^T  (A hi-only, B pre-split)
    {
        auto kfn = gemm_f16s<128,128,64,32,32,false,true,false,false,true,0>;
        int sm = 128*64*4 + 1*128*72*2 + 4*128*72*2;           // 124928
        cudaFuncSetAttribute(kfn, cudaFuncAttributeMaxDynamicSharedMemorySize, sm);
        dim3 grid(8, 32, 1);
        kfn<<<grid, 512, sm>>>(
            at, nullptr, nullptr,
            Woh, nullptr, nullptr,  Wol, nullptr, nullptr,
            nullptr, nullptr, nullptr,
            out, nullptr, nullptr,
            nullptr, nullptr, nullptr, 0,
            ROWSM, EMBED, EMBED, EMBED, EMBED, EMBED, 1.f, 0.f);
    }
}

// round 16
// speedup vs baseline: 1.5577x; 1.0101x over previous
#include <cuda_runtime.h>
#include <cuda_fp16.h>
#include <cstdint>

#define EMBED 1024
#define HEADS 16
#define HDIM  64
#define BATCH 2
#define SEQ   2048
#define ROWSM (BATCH*SEQ)   // 4096
#define EE    (EMBED*EMBED)
#define RME   (ROWSM*EMBED)

// ---------------- scratch (__device__ globals; no allocation allowed) ----------------
__device__ float  g_Mcat[2*EE];    // [Wk^T Wk, Wq^T Wq]
__device__ float  g_q   [RME];     // q projected (fp32)
__device__ float  g_at  [RME];     // attention output
__device__ __half g_Wo2h[2*EE], g_Wo2l[2*EE];  // [Wqo, Wko] planes
__device__ __half g_Wvh [EE],   g_Wvl [EE];    // Wv planes
__device__ __half g_Woh [EE],   g_Wol [EE];    // Wo planes
__device__ __half g_kh  [RME];                 // k hi plane [b*S+s][E]
__device__ __half g_vh  [RME];                 // v hi plane [b*S+s][E]

// ---------------- helpers ----------------
__device__ __forceinline__ void split_f16(float f, __half& hi, __half& lo) {
    hi = __float2half_rn(f);
    lo = __float2half_rn(f - __half2float(hi));
}
__device__ __forceinline__ void split2(float a, float b, uint32_t& hi, uint32_t& lo) {
    __half2 h = __floats2half2_rn(a, b);
    float2 hf = __half22float2(h);
    __half2 l = __floats2half2_rn(a - hf.x, b - hf.y);
    hi = *reinterpret_cast<uint32_t*>(&h);
    lo = *reinterpret_cast<uint32_t*>(&l);
}
__device__ __forceinline__ uint32_t pack_h2(float a, float b) {
    __half2 h = __floats2half2_rn(a, b);
    return *reinterpret_cast<uint32_t*>(&h);
}
__device__ __forceinline__ void mma_f16(float (&d)[4], const uint32_t (&a)[4],
                                        const uint32_t (&b)[2], const float (&c)[4]) {
    asm volatile(
        "mma.sync.aligned.m16n8k16.row.col.f32.f16.f16.f32 "
        "{%0,%1,%2,%3},{%4,%5,%6,%7},{%8,%9},{%10,%11,%12,%13};\n"
        : "=f"(d[0]), "=f"(d[1]), "=f"(d[2]), "=f"(d[3])
        : "r"(a[0]), "r"(a[1]), "r"(a[2]), "r"(a[3]),
          "r"(b[0]), "r"(b[1]),
          "f"(c[0]), "f"(c[1]), "f"(c[2]), "f"(c[3]));
}
__device__ __forceinline__ uint32_t sptr(const void* p) {
    return (uint32_t)__cvta_generic_to_shared(p);
}
__device__ __forceinline__ void ldmx4(uint32_t* r, const __half* p) {
    asm volatile("ldmatrix.sync.aligned.m8n8.x4.shared.b16 {%0,%1,%2,%3}, [%4];"
        : "=r"(r[0]), "=r"(r[1]), "=r"(r[2]), "=r"(r[3]) : "r"(sptr(p)));
}
__device__ __forceinline__ void ldmx4t(uint32_t* r, const __half* p) {
    asm volatile("ldmatrix.sync.aligned.m8n8.x4.trans.shared.b16 {%0,%1,%2,%3}, [%4];"
        : "=r"(r[0]), "=r"(r[1]), "=r"(r[2]), "=r"(r[3]) : "r"(sptr(p)));
}
__device__ __forceinline__ void cp16(void* s, const void* g) {
    asm volatile("cp.async.cg.shared.global [%0], [%1], 16;" :: "r"(sptr(s)), "l"(g));
}
__device__ __forceinline__ void cp_commit() { asm volatile("cp.async.commit_group;"); }
template<int N> __device__ __forceinline__ void cp_wait() {
    asm volatile("cp.async.wait_group %0;" :: "n"(N));
}

// ---------------- weight pre-split kernel ----------------
__global__ void __launch_bounds__(256) split_planes(const float* __restrict__ w,
                                                    __half* __restrict__ hi,
                                                    __half* __restrict__ lo) {
    int i = blockIdx.x * 256 + threadIdx.x;
    __half h, l; split_f16(w[i], h, l);
    hi[i] = h; lo[i] = l;
}

// ---------------- generic batched split-fp16 GEMM ----------------
// z selects pointer set. C = alpha*opA(A)*opB(B) [+ beta*Cin]
// BPRE: B pre-split planes [n][k], cp'd direct, double-buffered. Else fp32 staged.
// EPI: 0 = fp32 C; 1 = planes Hh/Hl (+z*sH); 2 = qkv (z0: fp32 C0; z1: hi->Hh; z2: hi->Ht)
template<int BM,int BN,int BK,int WM,int WN,bool TA,bool TB,bool HASC,bool SPLITA,bool BPRE,int EPI>
__global__ void __launch_bounds__((BM/WM)*(BN/WN)*32)
gemm_f16s(const float* A0, const float* A1, const float* A2,
          const void* Bv0, const void* Bv1, const void* Bv2,
          const __half* Bl0, const __half* Bl1, const __half* Bl2,
          const float* Ci0, const float* Ci1, const float* Ci2,
          float* C0, float* C1, float* C2,
          __half* Hh, __half* Hl, __half* Ht, long long sH,
          int M, int N, int K, int lda, int ldb, int ldc,
          float alpha, float beta)
{
    constexpr int WARPS_N = BN / WN;
    constexpr int WARPS_M = BM / WM;
    constexpr int NTH = WARPS_M * WARPS_N * 32;
    constexpr int MFRAG = WM / 16, NFRAG = WN / 8, KSTEPS = BK / 16;
    constexpr int LDK = BK + 8;
    constexpr int EA = BM * BK / NTH, EB = BN * BK / NTH;
    constexpr int CA = BM * BK / 4 / NTH, CB = BN * BK / 4 / NTH;
    constexpr int CBH = (BN * (BK / 8)) / NTH;
    constexpr int APL = SPLITA ? 2 : 1;

    extern __shared__ char smraw[];
    float*  Ast = (float*)smraw;
    float*  Bst = nullptr;
    __half* As;
    __half* Bs;
    if constexpr (BPRE) {
        As = (__half*)(Ast + BM * BK);
        Bs = As + APL * BM * LDK;          // [2 buf][2 plane][BN*LDK]
    } else {
        Bst = Ast + BM * BK;
        As = (__half*)(Bst + BN * BK);
        Bs = As + APL * BM * LDK;          // [2 plane][BN*LDK]
    }

    const int z = blockIdx.z;
    const float* A = (z == 0) ? A0 : ((z == 1) ? A1 : A2);
    const void*  Bv = (z == 0) ? Bv0 : ((z == 1) ? Bv1 : Bv2);
    const __half* Bl = (z == 0) ? Bl0 : ((z == 1) ? Bl1 : Bl2);
    const float* Cin = (z == 0) ? Ci0 : ((z == 1) ? Ci1 : Ci2);
    float*       C = (z == 0) ? C0 : ((z == 1) ? C1 : C2);

    const int mbase = blockIdx.y * BM;
    const int nbase = blockIdx.x * BN;
    const int tid  = threadIdx.x;
    const int warp = tid >> 5, lane = tid & 31;
    const int wm = warp / WARPS_N, wn = warp % WARPS_N;
    const int gq = lane >> 2, tq = lane & 3;

    float acc[MFRAG][NFRAG][4];
#pragma unroll
    for (int i = 0; i < MFRAG; i++)
#pragma unroll
        for (int j = 0; j < NFRAG; j++)
#pragma unroll
            for (int r = 0; r < 4; r++) acc[i][j][r] = 0.f;

    auto cpA = [&](int kb) {
#pragma unroll
        for (int i = 0; i < CA; i++) {
            int e = i * NTH + tid;
            if (TA) { int k = e / (BM/4), mc = e % (BM/4);
                cp16(Ast + k * BM + 4 * mc, A + (size_t)(kb + k) * lda + mbase + 4 * mc); }
            else    { int m = e / (BK/4), kc = e % (BK/4);
                cp16(Ast + m * BK + 4 * kc, A + (size_t)(mbase + m) * lda + kb + 4 * kc); }
        }
    };
    auto cpB = [&](int kb, int buf) {
        if constexpr (BPRE) {
            const __half* Bh = (const __half*)Bv;
#pragma unroll
            for (int i = 0; i < CBH; i++) {
                int e = i * NTH + tid;
                int n = e / (BK/8), k8 = e % (BK/8);
                cp16(Bs + (buf*2 + 0) * BN * LDK + n * LDK + k8 * 8,
                     Bh + (size_t)(nbase + n) * ldb + kb + k8 * 8);
                cp16(Bs + (buf*2 + 1) * BN * LDK + n * LDK + k8 * 8,
                     Bl + (size_t)(nbase + n) * ldb + kb + k8 * 8);
            }
        } else {
            const float* Bf = (const float*)Bv;
#pragma unroll
            for (int i = 0; i < CB; i++) {
                int e = i * NTH + tid;
                if (TB) { int n = e / (BK/4), kc = e % (BK/4);
                    cp16(Bst + n * BK + 4 * kc, Bf + (size_t)(nbase + n) * ldb + kb + 4 * kc); }
                else    { int k = e / (BN/4), nc = e % (BN/4);
                    cp16(Bst + k * BN + 4 * nc, Bf + (size_t)(kb + k) * ldb + nbase + 4 * nc); }
            }
        }
    };
    auto convert = [&]() {
#pragma unroll
        for (int i = 0; i < EA; i++) {
            int e = i * NTH + tid; int m, k;
            if (TA) { k = e / BM; m = e % BM; } else { m = e / BK; k = e % BK; }
            float f = Ast[e];
            if (SPLITA) {
                __half h, l; split_f16(f, h, l);
                As[m * LDK + k] = h;
                As[BM * LDK + m * LDK + k] = l;
            } else {
                As[m * LDK + k] = __float2half_rn(f);
            }
        }
        if constexpr (!BPRE) {
#pragma unroll
            for (int i = 0; i < EB; i++) {
                int e = i * NTH + tid; int n, k;
                if (TB) { n = e / BK; k = e % BK; } else { k = e / BN; n = e % BN; }
                float f = Bst[e];
                __half h, l; split_f16(f, h, l);
                Bs[n * LDK + k] = h;
                Bs[BN * LDK + n * LDK + k] = l;
            }
        }
    };

    cpA(0); cpB(0, 0); cp_commit();
    cp_wait<0>(); __syncthreads();
    convert(); __syncthreads();
    if (BK < K) { cpA(BK); cpB(BK, 1); cp_commit(); }

    const int a_row = (lane & 15);
    const int a_kof = (lane >> 4) << 3;
    const int b_row = (lane & 7) + (((lane >> 4) & 1) << 3);
    const int b_kof = ((lane >> 3) & 1) << 3;

    for (int kb = 0; kb < K; kb += BK) {
        const int ibuf = BPRE ? ((kb / BK) & 1) : 0;
        const __half* Bsh = Bs + (BPRE ? (ibuf*2 + 0) * BN * LDK : 0);
        const __half* Bsl = Bs + (BPRE ? (ibuf*2 + 1) * BN * LDK : BN * LDK);
#pragma unroll
        for (int ks = 0; ks < KSTEPS; ks++) {
            const int k0 = ks * 16;
            uint32_t ah[MFRAG][4], al[MFRAG][4];
            uint32_t bh[NFRAG][2], bl[NFRAG][2];
#pragma unroll
            for (int fm = 0; fm < MFRAG; fm++) {
                const int mr = wm * WM + fm * 16 + a_row;
                ldmx4(ah[fm], &As[mr * LDK + k0 + a_kof]);
                if (SPLITA)
                    ldmx4(al[fm], &As[BM * LDK + mr * LDK + k0 + a_kof]);
            }
#pragma unroll
            for (int fp = 0; fp < NFRAG / 2; fp++) {
                const int nr = wn * WN + fp * 16 + b_row;
                uint32_t t[4];
                ldmx4(t, &Bsh[nr * LDK + k0 + b_kof]);
                bh[2*fp][0] = t[0]; bh[2*fp][1] = t[1];
                bh[2*fp+1][0] = t[2]; bh[2*fp+1][1] = t[3];
                ldmx4(t, &Bsl[nr * LDK + k0 + b_kof]);
                bl[2*fp][0] = t[0]; bl[2*fp][1] = t[1];
                bl[2*fp+1][0] = t[2]; bl[2*fp+1][1] = t[3];
            }
            if (SPLITA) {
#pragma unroll
                for (int fm = 0; fm < MFRAG; fm++)
#pragma unroll
                    for (int fn = 0; fn < NFRAG; fn++)
                        mma_f16(acc[fm][fn], al[fm], bh[fn], acc[fm][fn]);
            }
#pragma unroll
            for (int fm = 0; fm < MFRAG; fm++)
#pragma unroll
                for (int fn = 0; fn < NFRAG; fn++)
                    mma_f16(acc[fm][fn], ah[fm], bl[fn], acc[fm][fn]);
#pragma unroll
            for (int fm = 0; fm < MFRAG; fm++)
#pragma unroll
                for (int fn = 0; fn < NFRAG; fn++)
                    mma_f16(acc[fm][fn], ah[fm], bh[fn], acc[fm][fn]);
        }
        if (kb + BK < K) {
            cp_wait<0>(); __syncthreads();
            convert(); __syncthreads();
            if (kb + 2 * BK < K) { cpA(kb + 2*BK); cpB(kb + 2*BK, ibuf); cp_commit(); }
        }
    }

#pragma unroll
    for (int fm = 0; fm < MFRAG; fm++) {
        const int m0 = mbase + wm * WM + fm * 16 + gq;
#pragma unroll
        for (int fn = 0; fn < NFRAG; fn++) {
            const int n0 = nbase + wn * WN + fn * 8 + tq * 2;
            float v0 = alpha * acc[fm][fn][0], v1 = alpha * acc[fm][fn][1];
            float v2 = alpha * acc[fm][fn][2], v3 = alpha * acc[fm][fn][3];
            if (HASC) {
                const float* ci0 = Cin + (size_t)m0 * ldc + n0;
                const float* ci1 = Cin + (size_t)(m0 + 8) * ldc + n0;
                v0 += beta * ci0[0]; v1 += beta * ci0[1];
                v2 += beta * ci1[0]; v3 += beta * ci1[1];
            }
            if (EPI == 1) {
                __half* hh = Hh + z * sH;
                __half* hl = Hl + z * sH;
                uint32_t h01, l01, h23, l23;
                split2(v0, v1, h01, l01);
                split2(v2, v3, h23, l23);
                *(uint32_t*)&hh[(size_t)m0 * ldc + n0] = h01;
                *(uint32_t*)&hl[(size_t)m0 * ldc + n0] = l01;
                *(uint32_t*)&hh[(size_t)(m0 + 8) * ldc + n0] = h23;
                *(uint32_t*)&hl[(size_t)(m0 + 8) * ldc + n0] = l23;
            } else if (EPI == 2 && z == 1) {
                *(uint32_t*)&Hh[(size_t)m0 * ldc + n0] = pack_h2(v0, v1);
                *(uint32_t*)&Hh[(size_t)(m0 + 8) * ldc + n0] = pack_h2(v2, v3);
            } else if (EPI == 2 && z == 2) {
                *(uint32_t*)&Ht[(size_t)m0 * ldc + n0] = pack_h2(v0, v1);
                *(uint32_t*)&Ht[(size_t)(m0 + 8) * ldc + n0] = pack_h2(v2, v3);
            } else {
                float* c0 = C + (size_t)m0 * ldc + n0;
                float* c1 = C + (size_t)(m0 + 8) * ldc + n0;
                c0[0] = v0; c0[1] = v1;
                c1[0] = v2; c1[1] = v3;
            }
        }
    }
}

// ---------------- fused flash attention: 512 threads, BQ=256, single-plane K ----------------
#define FA_LD  72
#define FA_PL  (128*FA_LD)
#define FA_NT  (SEQ/128)
#define FA_SMEM (6*FA_PL*2)   // 3 bufs x 2 planes (K, V) x 128x72 halves

__global__ void __launch_bounds__(512)
flash_attn(const float* __restrict__ qf,
           const __half* __restrict__ khi,
           const __half* __restrict__ vhi, float* __restrict__ outb)
{
    extern __shared__ __half sm[];

    const int hh = blockIdx.x;
    const int b = hh >> 4, h = hh & 15;
    const int qt = blockIdx.y;            // 0..7 (256 q rows per block)

    const int tid = threadIdx.x;
    const int w = tid >> 5, lane = tid & 31;   // 16 warps
    const int gq = lane >> 2, tq = lane & 3;
    const int b_row = (lane & 7) + (((lane >> 4) & 1) << 3);
    const int b_kof = ((lane >> 3) & 1) << 3;
    const int vt_row = ((lane >> 3) & 1) * 8 + (lane & 7);
    const int vt_col = ((lane >> 4) & 1) * 8;

    const __half* Kh = khi + ((size_t)b * SEQ) * EMBED + h * HDIM;
    const __half* Vh = vhi + ((size_t)b * SEQ) * EMBED + h * HDIM;

    auto cpKV = [&](int j) {
        __half* dst = sm + (j % 3) * 2 * FA_PL;
        const __half* sh = Kh + (size_t)(j * 128) * EMBED;
        const __half* sv = Vh + (size_t)(j * 128) * EMBED;
#pragma unroll
        for (int i = 0; i < 2; i++) {
            int c = i * 512 + tid;
            int row = c >> 3, c8 = c & 7;
            cp16(dst +          row * FA_LD + c8 * 8, sh + (size_t)row * EMBED + c8 * 8);
            cp16(dst + FA_PL +  row * FA_LD + c8 * 8, sv + (size_t)row * EMBED + c8 * 8);
        }
        cp_commit();
    };

    // ---- Q fragments: hi-only (pre-scaled) ----
    uint32_t qh[4][4];
    {
        const float* Qb = qf + ((size_t)b * SEQ) * EMBED + h * HDIM;
        const int r0 = qt * 256 + w * 16 + gq;
        const float* Qr0 = Qb + (size_t)r0 * EMBED;
        const float* Qr1 = Qr0 + 8 * (size_t)EMBED;
#pragma unroll
        for (int ks = 0; ks < 4; ks++) {
            const int c = 16 * ks + 2 * tq;
            float2 x0 = *(const float2*)(Qr0 + c);
            float2 x1 = *(const float2*)(Qr1 + c);
            float2 x2 = *(const float2*)(Qr0 + c + 8);
            float2 x3 = *(const float2*)(Qr1 + c + 8);
            qh[ks][0] = pack_h2(x0.x * 0.125f, x0.y * 0.125f);
            qh[ks][1] = pack_h2(x1.x * 0.125f, x1.y * 0.125f);
            qh[ks][2] = pack_h2(x2.x * 0.125f, x2.y * 0.125f);
            qh[ks][3] = pack_h2(x3.x * 0.125f, x3.y * 0.125f);
        }
    }

    float o[8][4];
#pragma unroll
    for (int i = 0; i < 8; i++)
#pragma unroll
        for (int r = 0; r < 4; r++) o[i][r] = 0.f;
    float m0r = -1e30f, m1r = -1e30f, l0 = 0.f, l1 = 0.f;

    cpKV(0);
    cpKV(1);

    for (int j = 0; j < FA_NT; j++) {
        if (j + 1 < FA_NT) cp_wait<1>(); else cp_wait<0>();
        __syncthreads();
        if (j + 2 < FA_NT) cpKV(j + 2);

        const __half* Kb = sm + (j % 3) * 2 * FA_PL;
        const __half* Vb = Kb + FA_PL;

        // ---- S = Q_hi K_hi^T : single plane, 4 independent MMAs per step ----
        float s[16][4];
#pragma unroll
        for (int f = 0; f < 16; f++)
#pragma unroll
            for (int r = 0; r < 4; r++) s[f][r] = 0.f;
#pragma unroll
        for (int ks = 0; ks < 4; ks++) {
            const int k0 = 16 * ks;
#pragma unroll
            for (int fp = 0; fp < 4; fp++) {
                const int nr0 = (2*fp)     * 16 + b_row;
                const int nr1 = (2*fp + 1) * 16 + b_row;
                uint32_t th0[4], th1[4];
                ldmx4(th0, &Kb[nr0 * FA_LD + k0 + b_kof]);
                ldmx4(th1, &Kb[nr1 * FA_LD + k0 + b_kof]);
                uint32_t bh00[2] = {th0[0], th0[1]}, bh01[2] = {th0[2], th0[3]};
                uint32_t bh10[2] = {th1[0], th1[1]}, bh11[2] = {th1[2], th1[3]};
                mma_f16(s[4*fp],   qh[ks], bh00, s[4*fp]);
                mma_f16(s[4*fp+1], qh[ks], bh01, s[4*fp+1]);
                mma_f16(s[4*fp+2], qh[ks], bh10, s[4*fp+2]);
                mma_f16(s[4*fp+3], qh[ks], bh11, s[4*fp+3]);
            }
        }

        float mx0 = -1e30f, mx1 = -1e30f;
#pragma unroll
        for (int f = 0; f < 16; f++) {
            mx0 = fmaxf(mx0, fmaxf(s[f][0], s[f][1]));
            mx1 = fmaxf(mx1, fmaxf(s[f][2], s[f][3]));
        }
        mx0 = fmaxf(mx0, __shfl_xor_sync(0xffffffffu, mx0, 1));
        mx0 = fmaxf(mx0, __shfl_xor_sync(0xffffffffu, mx0, 2));
        mx1 = fmaxf(mx1, __shfl_xor_sync(0xffffffffu, mx1, 1));
        mx1 = fmaxf(mx1, __shfl_xor_sync(0xffffffffu, mx1, 2));
        const float mn0 = fmaxf(m0r, mx0), mn1 = fmaxf(m1r, mx1);
        const float cr0 = __expf(m0r - mn0), cr1 = __expf(m1r - mn1);
        m0r = mn0; m1r = mn1;

        float rs0 = 0.f, rs1 = 0.f;
#pragma unroll
        for (int f = 0; f < 16; f++) {
            s[f][0] = __expf(s[f][0] - mn0);
            s[f][1] = __expf(s[f][1] - mn0);
            s[f][2] = __expf(s[f][2] - mn1);
            s[f][3] = __expf(s[f][3] - mn1);
            rs0 += s[f][0] + s[f][1];
            rs1 += s[f][2] + s[f][3];
        }
        rs0 += __shfl_xor_sync(0xffffffffu, rs0, 1);
        rs0 += __shfl_xor_sync(0xffffffffu, rs0, 2);
        rs1 += __shfl_xor_sync(0xffffffffu, rs1, 1);
        rs1 += __shfl_xor_sync(0xffffffffu, rs1, 2);
        l0 = l0 * cr0 + rs0;
        l1 = l1 * cr1 + rs1;
#pragma unroll
        for (int fn = 0; fn < 8; fn++) {
            o[fn][0] *= cr0; o[fn][1] *= cr0;
            o[fn][2] *= cr1; o[fn][3] *= cr1;
        }

#pragma unroll
        for (int ks = 0; ks < 8; ks++) {
            uint32_t pa[4];
            pa[0] = pack_h2(s[2*ks][0],   s[2*ks][1]);
            pa[1] = pack_h2(s[2*ks][2],   s[2*ks][3]);
            pa[2] = pack_h2(s[2*ks+1][0], s[2*ks+1][1]);
            pa[3] = pack_h2(s[2*ks+1][2], s[2*ks+1][3]);
            const int k0 = 16 * ks;
#pragma unroll
            for (int fp = 0; fp < 4; fp++) {
                uint32_t t[4];
                ldmx4t(t, &Vb[(k0 + vt_row) * FA_LD + fp * 16 + vt_col]);
                uint32_t b0[2] = {t[0], t[1]}, b1[2] = {t[2], t[3]};
                mma_f16(o[2*fp],   pa, b0, o[2*fp]);
                mma_f16(o[2*fp+1], pa, b1, o[2*fp+1]);
            }
        }
    }

    const float inv0 = 1.f / l0, inv1 = 1.f / l1;
    const int r0 = qt * 256 + w * 16 + gq;
    float* Ob0 = outb + ((size_t)(b * SEQ + r0)) * EMBED + h * HDIM;
    float* Ob1 = Ob0 + 8 * (size_t)EMBED;
#pragma unroll
    for (int fn = 0; fn < 8; fn++) {
        const int c = fn * 8 + 2 * tq;
        float2 t0; t0.x = o[fn][0] * inv0; t0.y = o[fn][1] * inv0;
        float2 t1; t1.x = o[fn][2] * inv1; t1.y = o[fn][3] * inv1;
        *(float2*)(Ob0 + c) = t0;
        *(float2*)(Ob1 + c) = t1;
    }
}

// ---------------- host launch ----------------
extern "C" void kernel_launch(void* const* d_in, const int* in_sizes, int n_in,
                              void* d_out, int out_size)
{
    (void)in_sizes; (void)n_in; (void)out_size;
    const float* query = (const float*)d_in[0];
    const float* key   = (const float*)d_in[1];
    const float* value = (const float*)d_in[2];
    const float* Wq    = (const float*)d_in[3];
    const float* Wk    = (const float*)d_in[4];
    const float* Wv    = (const float*)d_in[5];
    const float* Wo    = (const float*)d_in[6];
    float* out = (float*)d_out;

    float *Mcat, *q, *at;
    __half *Wo2h, *Wo2l, *Wvh, *Wvl, *Woh, *Wol, *kh, *vh;
    cudaGetSymbolAddress((void**)&Mcat, g_Mcat);
    cudaGetSymbolAddress((void**)&q,    g_q);
    cudaGetSymbolAddress((void**)&at,   g_at);
    cudaGetSymbolAddress((void**)&Wo2h, g_Wo2h);
    cudaGetSymbolAddress((void**)&Wo2l, g_Wo2l);
    cudaGetSymbolAddress((void**)&Wvh,  g_Wvh);
    cudaGetSymbolAddress((void**)&Wvl,  g_Wvl);
    cudaGetSymbolAddress((void**)&Woh,  g_Woh);
    cudaGetSymbolAddress((void**)&Wol,  g_Wol);
    cudaGetSymbolAddress((void**)&kh,   g_kh);
    cudaGetSymbolAddress((void**)&vh,   g_vh);

    split_planes<<<EE/256, 256>>>(Wv, Wvh, Wvl);
    split_planes<<<EE/256, 256>>>(Wo, Woh, Wol);

    // 1: Mcat[0]=Wk^T Wk ; Mcat[1]=Wq^T Wq   (A hi-only, B split: 2 MMAs)
    {
        auto kfn = gemm_f16s<128,128,64,32,32,true,false,false,false,false,0>;
        int sm = (128*64 + 128*64)*4 + (1*128 + 2*128)*72*2;   // 120832
        cudaFuncSetAttribute(kfn, cudaFuncAttributeMaxDynamicSharedMemorySize, sm);
        dim3 grid(8, 8, 2);
        kfn<<<grid, 512, sm>>>(
            Wk, Wq, nullptr,  Wk, Wq, nullptr,  nullptr, nullptr, nullptr,
            nullptr, nullptr, nullptr,
            Mcat, Mcat + EE, nullptr,
            nullptr, nullptr, nullptr, 0,
            EMBED, EMBED, EMBED, EMBED, EMBED, EMBED, 1.f, 0.f);
    }
    // 2: Wo2[z] = W[z] - W[z]@Mcat[z]  -> fp16 planes  (full split)
    {
        auto kfn = gemm_f16s<128,128,64,32,32,false,false,true,true,false,1>;
        int sm = (128*64 + 128*64)*4 + (2*128 + 2*128)*72*2;   // 139264
        cudaFuncSetAttribute(kfn, cudaFuncAttributeMaxDynamicSharedMemorySize, sm);
        dim3 grid(8, 8, 2);
        kfn<<<grid, 512, sm>>>(
            Wq, Wk, nullptr,  Mcat, Mcat + EE, nullptr,  nullptr, nullptr, nullptr,
            Wq, Wk, nullptr,
            nullptr, nullptr, nullptr,
            Wo2h, Wo2l, nullptr, (long long)EE,
            EMBED, EMBED, EMBED, EMBED, EMBED, EMBED, -1.f, 1.f);
    }
    // 3: projections: BM=256, WM=64 (128 B/MMA); z0 q fp32, z1 k hi, z2 v hi
    {
        auto kfn = gemm_f16s<256,128,64,64,32,false,true,false,false,true,2>;
        int sm = 256*64*4 + 1*256*72*2 + 4*128*72*2;           // 176128
        cudaFuncSetAttribute(kfn, cudaFuncAttributeMaxDynamicSharedMemorySize, sm);
        dim3 grid(8, 16, 3);
        kfn<<<grid, 512, sm>>>(
            query, key, value,
            Wo2h, Wo2h + EE, Wvh,  Wo2l, Wo2l + EE, Wvl,
            nullptr, nullptr, nullptr,
            q, nullptr, nullptr,
            kh, nullptr, vh, 0,
            ROWSM, EMBED, EMBED, EMBED, EMBED, EMBED, 1.f, 0.f);
    }
    // 4: flash attention (512 threads, BQ=256, single-plane K)
    {
        cudaFuncSetAttribute(flash_attn, cudaFuncAttributeMaxDynamicSharedMemorySize, FA_SMEM);
        dim3 grid(BATCH * HEADS, SEQ / 256);
        flash_attn<<<grid, 512, FA_SMEM>>>(q, kh, vh, at);
    }
    // 5: out = at @ Wo^T  (BM=256, WM=64; A hi-only, B pre-split)
    {
        auto kfn = gemm_f16s<256,128,64,64,32,false,true,false,false,true,0>;
        int sm = 256*64*4 + 1*256*72*2 + 4*128*72*2;           // 176128
        cudaFuncSetAttribute(kfn, cudaFuncAttributeMaxDynamicSharedMemorySize, sm);
        dim3 grid(8, 16, 1);
        kfn<<<grid, 512, sm>>>(
            at, nullptr, nullptr,
            Woh, nullptr, nullptr,  Wol, nullptr, nullptr,
            nullptr, nullptr, nullptr,
            out, nullptr, nullptr,
            nullptr, nullptr, nullptr, 0,
            ROWSM, EMBED, EMBED, EMBED, EMBED, EMBED, 1.f, 0.f);
    }
}